// round 10
// baseline (speedup 1.0000x reference)
#include <cuda_runtime.h>
#include <cuda_bf16.h>
#include <cstdint>
#include <math.h>

#define BATCH 2
#define NTOK  8000
#define NP1   8001
#define PADN  191
#define NPAD  8192
#define DM    512
#define DIN   1024
#define NH    8
#define DH    64
#define NLM   256
#define LPER  32
#define BHN   16
#define CONVK 33
#define TD    1536
#define BK    32
#define NSPLIT 8
#define MM    ((long long)NLM * NLM)

typedef __nv_bfloat16 bf16;

// ---------------- fp32 scratch ----------------
__device__ float g_h   [(long long)BATCH*NPAD*DM];
__device__ float g_a2  [(long long)BHN*NLM*NLM];
__device__ float g_outh[(long long)BHN*NPAD*DH];
__device__ float g_po  [(long long)NSPLIT*BHN*NLM*DH];
__device__ float g_pm  [(long long)NSPLIT*BHN*NLM];
__device__ float g_ps  [(long long)NSPLIT*BHN*NLM];
__device__ int   g_maxrow;
__device__ int   g_maxcol;

// ---------------- dual-bf16 scratch (hi plane + lo plane) ----------------
__device__ __align__(16) bf16 g_featsd[2LL*BATCH*NTOK*DIN];
__device__ __align__(16) bf16 g_w1d   [2LL*DIN*DM];
__device__ __align__(16) bf16 g_qkvwd [2LL*2*DM*TD];
__device__ __align__(16) bf16 g_outwd [2LL*2*DM*DM];
__device__ __align__(16) bf16 g_xlnd  [2LL*BATCH*NPAD*DM];
__device__ __align__(16) bf16 g_qkvd  [2LL*BATCH*NPAD*TD];
__device__ __align__(16) bf16 g_qld   [2LL*BHN*NLM*DH];
__device__ __align__(16) bf16 g_kld   [2LL*BHN*NLM*DH];
__device__ __align__(16) bf16 g_a2d   [2LL*BHN*NLM*NLM];
__device__ __align__(16) bf16 g_zpd   [2LL*32*NLM*NLM];
__device__ __align__(16) bf16 g_t1d   [2LL*32*NLM*NLM];
__device__ __align__(16) bf16 g_t2d   [2LL*16*NLM*NLM];
__device__ __align__(16) bf16 g_t3d   [2LL*16*NLM*NLM];
__device__ __align__(16) bf16 g_a3vd  [2LL*BHN*NLM*DH];
__device__ __align__(16) bf16 g_wd    [2LL*BHN*NLM*DH];
__device__ __align__(16) bf16 g_catd  [2LL*BATCH*NPAD*DM];

// ---------------- helpers ----------------
__device__ __forceinline__ void storeDual2(bf16* d, long long plane, long long idx,
                                           float x, float y) {
    __nv_bfloat162 h = __floats2bfloat162_rn(x, y);
    *reinterpret_cast<__nv_bfloat162*>(d + idx) = h;
    __nv_bfloat162 l = __floats2bfloat162_rn(x - __bfloat162float(h.x),
                                             y - __bfloat162float(h.y));
    *reinterpret_cast<__nv_bfloat162*>(d + plane + idx) = l;
}
__device__ __forceinline__ void storeDual1(bf16* d, long long plane, long long idx, float x) {
    bf16 h = __float2bfloat16(x);
    d[idx] = h;
    d[plane + idx] = __float2bfloat16(x - __bfloat162float(h));
}
__device__ __forceinline__ float loadDual(const bf16* d, long long plane, long long idx) {
    return __bfloat162float(d[idx]) + __bfloat162float(d[plane + idx]);
}
__device__ __forceinline__ void cpa16(uint32_t dst, const void* src, bool pred) {
    int sz = pred ? 16 : 0;
    asm volatile("cp.async.cg.shared.global [%0], [%1], 16, %2;\n"
                 :: "r"(dst), "l"(src), "r"(sz));
}
__device__ __forceinline__ void cpa_commit() {
    asm volatile("cp.async.commit_group;\n");
}

__device__ __forceinline__ float blockReduceSum(float v, float* sh) {
    #pragma unroll
    for (int o = 16; o; o >>= 1) v += __shfl_xor_sync(0xffffffffu, v, o);
    int w = threadIdx.x >> 5;
    if ((threadIdx.x & 31) == 0) sh[w] = v;
    __syncthreads();
    if (threadIdx.x < 8) {
        v = sh[threadIdx.x];
        #pragma unroll
        for (int o = 4; o; o >>= 1) v += __shfl_xor_sync(0xffu, v, o);
        if (threadIdx.x == 0) sh[0] = v;
    }
    __syncthreads();
    float r = sh[0];
    __syncthreads();
    return r;
}
__device__ __forceinline__ float blockReduceMax(float v, float* sh) {
    #pragma unroll
    for (int o = 16; o; o >>= 1) v = fmaxf(v, __shfl_xor_sync(0xffffffffu, v, o));
    int w = threadIdx.x >> 5;
    if ((threadIdx.x & 31) == 0) sh[w] = v;
    __syncthreads();
    if (threadIdx.x < 8) {
        v = sh[threadIdx.x];
        #pragma unroll
        for (int o = 4; o; o >>= 1) v = fmaxf(v, __shfl_xor_sync(0xffu, v, o));
        if (threadIdx.x == 0) sh[0] = v;
    }
    __syncthreads();
    float r = sh[0];
    __syncthreads();
    return r;
}

__device__ __forceinline__ void mma16816(float* c, const unsigned* a, const unsigned* b) {
    asm volatile(
        "mma.sync.aligned.m16n8k16.row.col.f32.bf16.bf16.f32 "
        "{%0,%1,%2,%3},{%4,%5,%6,%7},{%8,%9},{%0,%1,%2,%3};\n"
        : "+f"(c[0]), "+f"(c[1]), "+f"(c[2]), "+f"(c[3])
        : "r"(a[0]), "r"(a[1]), "r"(a[2]), "r"(a[3]), "r"(b[0]), "r"(b[1]));
}
__device__ __forceinline__ void ldsm4(unsigned& r0, unsigned& r1, unsigned& r2, unsigned& r3,
                                      uint32_t addr) {
    asm volatile("ldmatrix.sync.aligned.m8n8.x4.shared.b16 {%0,%1,%2,%3}, [%4];\n"
                 : "=r"(r0), "=r"(r1), "=r"(r2), "=r"(r3) : "r"(addr));
}
__device__ __forceinline__ void ldsm4t(unsigned& r0, unsigned& r1, unsigned& r2, unsigned& r3,
                                       uint32_t addr) {
    asm volatile("ldmatrix.sync.aligned.m8n8.x4.trans.shared.b16 {%0,%1,%2,%3}, [%4];\n"
                 : "=r"(r0), "=r"(r1), "=r"(r2), "=r"(r3) : "r"(addr));
}
__device__ __forceinline__ void split2(float x, float y, unsigned& hi, unsigned& lo) {
    __nv_bfloat162 h = __floats2bfloat162_rn(x, y);
    __nv_bfloat162 l = __floats2bfloat162_rn(x - __bfloat162float(h.x),
                                             y - __bfloat162float(h.y));
    hi = *reinterpret_cast<unsigned*>(&h);
    lo = *reinterpret_cast<unsigned*>(&l);
}

// ---------------- dual-bf16 tensor-core GEMM (cp.async pipelined, generic tile) ----------------
// DYN != 0 -> tiles live in dynamic shared memory (for big tiles)
template<int BMT, int BN, int WROWS, int WCOLS, int DYN>
__global__ void __launch_bounds__(256, 1) gemm_tc(
    const bf16* __restrict__ A, const bf16* __restrict__ B,
    long long aPlane, long long bPlane,
    float* __restrict__ C, bf16* __restrict__ D, long long dPlane,
    bf16* __restrict__ D2, long long d2Plane,
    int Mn, int Kn, int lda, int ldb, int ldc,
    long long aOuter, long long aInner, int aCnt,
    long long bOuter, long long bInner, int bCnt,
    long long cStride, float alpha, const float* __restrict__ bias,
    int relu, int accum, int transB, int splitK, long long partStride,
    float diagVal, float diag2)
{
    constexpr int WM = BMT / WROWS;
    constexpr int WN = BN / WCOLS;
    constexpr int MT = WM / 16;
    constexpr int NT = WN / 8;
    constexpr int NTP = WN / 16;
    constexpr int KST = BN + 8;
    constexpr int ASTG = 2 * BMT * 40;
    constexpr int BSTG = 2 * BN * 40;

    int bz = blockIdx.z;
    int batch = bz / splitK;
    int split = bz - batch * splitK;
    const bf16* Ab = A + (long long)(batch / aCnt) * aOuter + (long long)(batch % aCnt) * aInner;
    const bf16* Bb = B + (long long)(batch / bCnt) * bOuter + (long long)(batch % bCnt) * bInner;
    long long cOff = (long long)batch * cStride + (long long)split * partStride;
    int kPer = Kn / splitK;
    int kStart = split * kPer;

    extern __shared__ __align__(16) bf16 dsm[];
    __shared__ __align__(16) bf16 ssm[DYN ? 2 : 2 * (ASTG + BSTG)];
    bf16* base = DYN ? dsm : ssm;
    bf16* sA = base;
    bf16* sB = base + 2 * ASTG;
    uint32_t saBase = (uint32_t)__cvta_generic_to_shared(sA);
    uint32_t sbBase = (uint32_t)__cvta_generic_to_shared(sB);

    int tid = threadIdx.x;
    int lane = tid & 31;
    int wid = tid >> 5;
    int lt = lane & 7;
    int lg = lane >> 3;
    int warpM = (wid / WCOLS) * WM;
    int warpN = (wid % WCOLS) * WN;
    int rowBase = blockIdx.y * BMT;
    int colBase = blockIdx.x * BN;

    float acc[MT][NT][4];
    #pragma unroll
    for (int i = 0; i < MT; i++)
        #pragma unroll
        for (int j = 0; j < NT; j++)
            #pragma unroll
            for (int e = 0; e < 4; e++) acc[i][j][e] = 0.f;

    auto issue = [&](int k0, int stg) {
        uint32_t sa = saBase + stg * ASTG * 2;
        uint32_t sb = sbBase + stg * BSTG * 2;
        #pragma unroll
        for (int c = 0; c < 2 * BMT * 4 / 256; c++) {
            int id = tid + c * 256;
            int p = id / (BMT * 4);
            int rem = id - p * (BMT * 4);
            int row = rem >> 2, seg = rem & 3;
            int gr = rowBase + row;
            bool ok = gr < Mn;
            const bf16* src = Ab + p * aPlane +
                              (long long)(ok ? gr : 0) * lda + kStart + k0 + seg * 8;
            cpa16(sa + (((p * BMT + row) * 40 + seg * 8) << 1), src, ok);
        }
        if (transB) {
            #pragma unroll
            for (int c = 0; c < 2 * BN * 4 / 256; c++) {
                int id = tid + c * 256;
                int p = id / (BN * 4);
                int rem = id - p * (BN * 4);
                int row = rem >> 2, seg = rem & 3;
                const bf16* src = Bb + p * bPlane +
                                  (long long)(colBase + row) * ldb + kStart + k0 + seg * 8;
                cpa16(sb + (((p * BN + row) * 40 + seg * 8) << 1), src, true);
            }
        } else {
            #pragma unroll
            for (int c = 0; c < 2 * 32 * (BN / 8) / 256; c++) {
                int id = tid + c * 256;
                int p = id / (32 * (BN / 8));
                int rem = id - p * (32 * (BN / 8));
                int k = rem / (BN / 8), seg = rem % (BN / 8);
                const bf16* src = Bb + p * bPlane +
                                  (long long)(kStart + k0 + k) * ldb + colBase + seg * 8;
                cpa16(sb + (((p * 32 + k) * KST + seg * 8) << 1), src, true);
            }
        }
        cpa_commit();
    };

    int nIter = kPer / BK;
    issue(0, 0);

    for (int it = 0; it < nIter; it++) {
        int cur = it & 1;
        asm volatile("cp.async.wait_group 0;\n");
        __syncthreads();
        if (it + 1 < nIter) issue((it + 1) * BK, cur ^ 1);

        uint32_t saS = saBase + cur * ASTG * 2;
        uint32_t sbS = sbBase + cur * BSTG * 2;

        #pragma unroll
        for (int ks = 0; ks < 2; ks++) {
            int k8 = ks * 16;
            unsigned bh[NTP][4], bl[NTP][4];
            #pragma unroll
            for (int ntp = 0; ntp < NTP; ntp++) {
                if (transB) {
                    int n = warpN + ntp * 16 + lt + ((lg >> 1) << 3);
                    int kk = k8 + ((lg & 1) << 3);
                    ldsm4(bh[ntp][0], bh[ntp][1], bh[ntp][2], bh[ntp][3],
                          sbS + (((0 * BN + n) * 40 + kk) << 1));
                    ldsm4(bl[ntp][0], bl[ntp][1], bl[ntp][2], bl[ntp][3],
                          sbS + (((1 * BN + n) * 40 + kk) << 1));
                } else {
                    int k = k8 + lt + ((lg & 1) << 3);
                    int n = warpN + ntp * 16 + ((lg >> 1) << 3);
                    ldsm4t(bh[ntp][0], bh[ntp][1], bh[ntp][2], bh[ntp][3],
                           sbS + (((0 * 32 + k) * KST + n) << 1));
                    ldsm4t(bl[ntp][0], bl[ntp][1], bl[ntp][2], bl[ntp][3],
                           sbS + (((1 * 32 + k) * KST + n) << 1));
                }
            }
            #pragma unroll
            for (int mt = 0; mt < MT; mt++) {
                unsigned ah[4], al[4];
                int m = warpM + mt * 16 + lt + ((lg & 1) << 3);
                int kk = k8 + ((lg >> 1) << 3);
                ldsm4(ah[0], ah[1], ah[2], ah[3],
                      saS + (((0 * BMT + m) * 40 + kk) << 1));
                ldsm4(al[0], al[1], al[2], al[3],
                      saS + (((1 * BMT + m) * 40 + kk) << 1));
                #pragma unroll
                for (int nt = 0; nt < NT; nt++) {
                    const unsigned* ph = &bh[nt >> 1][(nt & 1) * 2];
                    const unsigned* pl = &bl[nt >> 1][(nt & 1) * 2];
                    mma16816(acc[mt][nt], ah, ph);
                    mma16816(acc[mt][nt], ah, pl);
                    mma16816(acc[mt][nt], al, ph);
                }
            }
        }
        __syncthreads();
    }

    int q = lane & 3, g = lane >> 2;
    float* Cb = C ? C + cOff : nullptr;
    bf16* Db = D ? D + cOff : nullptr;
    bf16* D2b = D2 ? D2 + cOff : nullptr;
    #pragma unroll
    for (int mt = 0; mt < MT; mt++) {
        #pragma unroll
        for (int nt = 0; nt < NT; nt++) {
            int r0 = rowBase + warpM + mt * 16 + g;
            int c0 = colBase + warpN + nt * 8 + q * 2;
            #pragma unroll
            for (int half = 0; half < 2; half++) {
                int gr = r0 + half * 8;
                if (gr >= Mn) continue;
                float v0 = alpha * acc[mt][nt][half * 2 + 0];
                float v1 = alpha * acc[mt][nt][half * 2 + 1];
                if (gr == c0)     v0 += diagVal;
                if (gr == c0 + 1) v1 += diagVal;
                long long off = (long long)gr * ldc + c0;
                if (Cb) {
                    float w0 = v0, w1 = v1;
                    if (bias) { w0 += bias[c0]; w1 += bias[c0 + 1]; }
                    if (relu) { w0 = fmaxf(w0, 0.f); w1 = fmaxf(w1, 0.f); }
                    if (accum) { w0 += Cb[off]; w1 += Cb[off + 1]; }
                    *reinterpret_cast<float2*>(Cb + off) = make_float2(w0, w1);
                }
                if (Db) storeDual2(Db, dPlane, off, v0, v1);
                if (D2b) {
                    float u0 = ((gr == c0)     ? diag2 : 0.f) - v0;
                    float u1 = ((gr == c0 + 1) ? diag2 : 0.f) - v1;
                    storeDual2(D2b, d2Plane, off, u0, u1);
                }
            }
        }
    }
}

#define BIG_SMEM_BYTES ((2 * (2 * 256 * 40) + 2 * (2 * 128 * 40)) * 2)

// ---------------- fused flash attention ----------------
#define FA_SMEM_BYTES (55296 * 2)

template<int MODE>
__global__ void __launch_bounds__(256) flash_kernel(
    const bf16* __restrict__ Qa, long long qPlane, int qStride,
    long long qOuter, long long qInner, int qCnt,
    const bf16* __restrict__ Ka, long long kPlane, int kStride,
    long long kOuter, long long kInner, int kCnt,
    const bf16* __restrict__ Va, long long vPlane, int vStride,
    long long vOuter, long long vInner, int vCnt,
    int keysPerSplit,
    float* __restrict__ PO, float* __restrict__ PM, float* __restrict__ PS,
    const float* __restrict__ CONV, bf16* __restrict__ CATD, long long catPlane)
{
    extern __shared__ __align__(16) bf16 fsm[];
    uint32_t smBase = (uint32_t)__cvta_generic_to_shared(fsm);
    int tid = threadIdx.x, lane = tid & 31, wid = tid >> 5;
    int lt = lane & 7, lg = lane >> 3, g = lane >> 2, q = lane & 3;
    int bh = blockIdx.z, split = blockIdx.y;
    int rowBase = blockIdx.x * 128;
    const bf16* Q = Qa + (long long)(bh / qCnt) * qOuter + (long long)(bh % qCnt) * qInner;
    const bf16* K = Ka + (long long)(bh / kCnt) * kOuter + (long long)(bh % kCnt) * kInner
                       + (long long)split * keysPerSplit * kStride;
    const bf16* V = Va + (long long)(bh / vCnt) * vOuter + (long long)(bh % vCnt) * vInner
                       + (long long)split * keysPerSplit * vStride;

    #pragma unroll
    for (int j = 0; j < 8; j++) {
        int c = tid + j * 256;
        int p = c >> 10, rem = c & 1023;
        int row = rem >> 3, seg = rem & 7;
        cpa16(smBase + (((p * 128 + row) * 72 + seg * 8) << 1),
              Q + (long long)p * qPlane + (long long)(rowBase + row) * qStride + seg * 8, true);
    }
    auto issueKV = [&](int t, int stg) {
        int key0 = t * 64;
        #pragma unroll
        for (int j = 0; j < 2; j++) {
            int c = tid + j * 256;
            int p = c >> 8, rem = c & 255;
            int row = rem >> 2, seg = rem & 3;
            cpa16(smBase + ((18432 + stg * 9216 + (p * 64 + row) * 72 + seg * 16) << 1),
                  K + (long long)p * kPlane + (long long)(key0 + row) * kStride + seg * 16, true);
            cpa16(smBase + ((18432 + stg * 9216 + (p * 64 + row) * 72 + seg * 16 + 8) << 1),
                  K + (long long)p * kPlane + (long long)(key0 + row) * kStride + seg * 16 + 8, true);
            cpa16(smBase + ((36864 + stg * 9216 + (p * 64 + row) * 72 + seg * 16) << 1),
                  V + (long long)p * vPlane + (long long)(key0 + row) * vStride + seg * 16, true);
            cpa16(smBase + ((36864 + stg * 9216 + (p * 64 + row) * 72 + seg * 16 + 8) << 1),
                  V + (long long)p * vPlane + (long long)(key0 + row) * vStride + seg * 16 + 8, true);
        }
        cpa_commit();
    };
    issueKV(0, 0);

    int warpRow = wid * 16;
    unsigned qh[4][4], qlo[4][4];
    float o[8][4];
    #pragma unroll
    for (int i = 0; i < 8; i++)
        #pragma unroll
        for (int e = 0; e < 4; e++) o[i][e] = 0.f;
    float m0 = -1e30f, m1 = -1e30f, l0 = 0.f, l1 = 0.f;

    int nTiles = keysPerSplit / 64;
    for (int t = 0; t < nTiles; t++) {
        int stg = t & 1;
        bool more = (t + 1 < nTiles);
        if (more) {
            issueKV(t + 1, stg ^ 1);
            asm volatile("cp.async.wait_group 1;\n");
        } else {
            asm volatile("cp.async.wait_group 0;\n");
        }
        __syncthreads();
        if (t == 0) {
            #pragma unroll
            for (int kc = 0; kc < 4; kc++) {
                int row = warpRow + lt + ((lg & 1) << 3);
                int kk = kc * 16 + ((lg >> 1) << 3);
                ldsm4(qh[kc][0], qh[kc][1], qh[kc][2], qh[kc][3],
                      smBase + (((0 * 128 + row) * 72 + kk) << 1));
                ldsm4(qlo[kc][0], qlo[kc][1], qlo[kc][2], qlo[kc][3],
                      smBase + (((1 * 128 + row) * 72 + kk) << 1));
            }
        }
        uint32_t skS = smBase + ((18432 + stg * 9216) << 1);
        uint32_t svS = smBase + ((36864 + stg * 9216) << 1);

        float sc[8][4];
        #pragma unroll
        for (int i = 0; i < 8; i++)
            #pragma unroll
            for (int e = 0; e < 4; e++) sc[i][e] = 0.f;
        #pragma unroll
        for (int kc = 0; kc < 4; kc++) {
            unsigned kh[4][4], kl[4][4];
            #pragma unroll
            for (int ntp = 0; ntp < 4; ntp++) {
                int n = ntp * 16 + lt + ((lg >> 1) << 3);
                int kk = kc * 16 + ((lg & 1) << 3);
                ldsm4(kh[ntp][0], kh[ntp][1], kh[ntp][2], kh[ntp][3],
                      skS + (((0 * 64 + n) * 72 + kk) << 1));
                ldsm4(kl[ntp][0], kl[ntp][1], kl[ntp][2], kl[ntp][3],
                      skS + (((64 + n) * 72 + kk) << 1));
            }
            #pragma unroll
            for (int nt = 0; nt < 8; nt++) {
                const unsigned* bhf = &kh[nt >> 1][(nt & 1) * 2];
                const unsigned* blf = &kl[nt >> 1][(nt & 1) * 2];
                mma16816(sc[nt], qh[kc], bhf);
                mma16816(sc[nt], qh[kc], blf);
                mma16816(sc[nt], qlo[kc], bhf);
            }
        }
        float mt0 = -1e30f, mt1 = -1e30f;
        #pragma unroll
        for (int nt = 0; nt < 8; nt++) {
            #pragma unroll
            for (int e = 0; e < 4; e++) sc[nt][e] *= 0.125f;
            mt0 = fmaxf(mt0, fmaxf(sc[nt][0], sc[nt][1]));
            mt1 = fmaxf(mt1, fmaxf(sc[nt][2], sc[nt][3]));
        }
        mt0 = fmaxf(mt0, __shfl_xor_sync(0xffffffffu, mt0, 1));
        mt0 = fmaxf(mt0, __shfl_xor_sync(0xffffffffu, mt0, 2));
        mt1 = fmaxf(mt1, __shfl_xor_sync(0xffffffffu, mt1, 1));
        mt1 = fmaxf(mt1, __shfl_xor_sync(0xffffffffu, mt1, 2));
        float mn0 = fmaxf(m0, mt0), mn1 = fmaxf(m1, mt1);
        float f0 = __expf(m0 - mn0), f1 = __expf(m1 - mn1);
        m0 = mn0; m1 = mn1;
        float rs0 = 0.f, rs1 = 0.f;
        #pragma unroll
        for (int nt = 0; nt < 8; nt++) {
            sc[nt][0] = __expf(sc[nt][0] - mn0);
            sc[nt][1] = __expf(sc[nt][1] - mn0);
            sc[nt][2] = __expf(sc[nt][2] - mn1);
            sc[nt][3] = __expf(sc[nt][3] - mn1);
            rs0 += sc[nt][0] + sc[nt][1];
            rs1 += sc[nt][2] + sc[nt][3];
        }
        rs0 += __shfl_xor_sync(0xffffffffu, rs0, 1);
        rs0 += __shfl_xor_sync(0xffffffffu, rs0, 2);
        rs1 += __shfl_xor_sync(0xffffffffu, rs1, 1);
        rs1 += __shfl_xor_sync(0xffffffffu, rs1, 2);
        l0 = l0 * f0 + rs0;
        l1 = l1 * f1 + rs1;
        #pragma unroll
        for (int nt = 0; nt < 8; nt++) {
            o[nt][0] *= f0; o[nt][1] *= f0;
            o[nt][2] *= f1; o[nt][3] *= f1;
        }
        #pragma unroll
        for (int kc = 0; kc < 4; kc++) {
            unsigned ph[4], pl[4];
            split2(sc[2 * kc][0],     sc[2 * kc][1],     ph[0], pl[0]);
            split2(sc[2 * kc][2],     sc[2 * kc][3],     ph[1], pl[1]);
            split2(sc[2 * kc + 1][0], sc[2 * kc + 1][1], ph[2], pl[2]);
            split2(sc[2 * kc + 1][2], sc[2 * kc + 1][3], ph[3], pl[3]);
            unsigned vh[4][4], vl[4][4];
            #pragma unroll
            for (int ntp = 0; ntp < 4; ntp++) {
                int k = kc * 16 + lt + ((lg & 1) << 3);
                int n = ntp * 16 + ((lg >> 1) << 3);
                ldsm4t(vh[ntp][0], vh[ntp][1], vh[ntp][2], vh[ntp][3],
                       svS + (((0 * 64 + k) * 72 + n) << 1));
                ldsm4t(vl[ntp][0], vl[ntp][1], vl[ntp][2], vl[ntp][3],
                       svS + (((64 + k) * 72 + n) << 1));
            }
            #pragma unroll
            for (int nt = 0; nt < 8; nt++) {
                const unsigned* bhf = &vh[nt >> 1][(nt & 1) * 2];
                const unsigned* blf = &vl[nt >> 1][(nt & 1) * 2];
                mma16816(o[nt], ph, bhf);
                mma16816(o[nt], ph, blf);
                mma16816(o[nt], pl, bhf);
            }
        }
        __syncthreads();
    }

    int row0 = rowBase + warpRow + g;
    int row1 = row0 + 8;
    if (MODE == 1) {
        float i0 = 1.f / l0, i1 = 1.f / l1;
        int b = bh >> 3, hh = bh & 7;
        const float* Cv = CONV + (long long)bh * NPAD * 64;
        #pragma unroll
        for (int nt = 0; nt < 8; nt++) {
            int col = nt * 8 + q * 2;
            float2 c0 = *(const float2*)&Cv[(long long)row0 * 64 + col];
            float2 c1 = *(const float2*)&Cv[(long long)row1 * 64 + col];
            long long i0d = ((long long)b * NPAD + row0) * DM + hh * 64 + col;
            long long i1d = ((long long)b * NPAD + row1) * DM + hh * 64 + col;
            storeDual2(CATD, catPlane, i0d, o[nt][0] * i0 + c0.x, o[nt][1] * i0 + c0.y);
            storeDual2(CATD, catPlane, i1d, o[nt][2] * i1 + c1.x, o[nt][3] * i1 + c1.y);
        }
    } else {
        long long pb = ((long long)split * BHN + bh) * NLM;
        #pragma unroll
        for (int nt = 0; nt < 8; nt++) {
            int col = nt * 8 + q * 2;
            *(float2*)&PO[(pb + row0) * 64 + col] = make_float2(o[nt][0], o[nt][1]);
            *(float2*)&PO[(pb + row1) * 64 + col] = make_float2(o[nt][2], o[nt][3]);
        }
        if (q == 0) {
            PM[pb + row0] = m0; PM[pb + row1] = m1;
            PS[pb + row0] = l0; PS[pb + row1] = l1;
        }
    }
}

__global__ void fa_combine(const float* __restrict__ po, const float* __restrict__ pm,
                           const float* __restrict__ ps, bf16* __restrict__ outd,
                           long long plane) {
    long long idx = (long long)blockIdx.x * 256 + threadIdx.x;
    int d = (int)(idx & 63);
    long long rid = idx >> 6;
    const long long RS = (long long)BHN * NLM;
    float M = -1e30f;
    #pragma unroll
    for (int s = 0; s < NSPLIT; s++) M = fmaxf(M, pm[s * RS + rid]);
    float S = 0.f, val = 0.f;
    #pragma unroll
    for (int s = 0; s < NSPLIT; s++) {
        float e = __expf(pm[s * RS + rid] - M);
        S += ps[s * RS + rid] * e;
        val += po[(s * RS + rid) * 64 + d] * e;
    }
    storeDual1(outd, plane, rid * 64 + d, val / S);
}

// ---------------- misc kernels ----------------
__global__ void tobf16_kernel(const float* __restrict__ x, bf16* __restrict__ d,
                              long long n, long long plane) {
    long long i = (long long)blockIdx.x * 256 + threadIdx.x;
    if (i >= n) return;
    storeDual1(d, plane, i, x[i]);
}

__global__ void init_h_kernel(const float* __restrict__ cls, float* __restrict__ h) {
    int r = blockIdx.x, b = blockIdx.y;
    float* o = h + ((long long)b * NPAD + r) * DM;
    for (int i = threadIdx.x; i < DM; i += 256) o[i] = (r == PADN) ? cls[i] : 0.f;
}

__global__ void layernorm_kernel(const float* __restrict__ in, bf16* __restrict__ xd,
                                 long long plane,
                                 const float* __restrict__ gam, const float* __restrict__ bet) {
    __shared__ float sh[8];
    long long row = blockIdx.x;
    int r = (int)(row % NPAD);
    int tid = threadIdx.x;
    long long idx = row * DM + tid * 2;
    if (r < PADN) {
        storeDual2(xd, plane, idx, 0.f, 0.f);
        return;
    }
    const float2* x = (const float2*)(in + row * DM);
    float2 v = x[tid];
    float s = v.x + v.y;
    float s2 = v.x * v.x + v.y * v.y;
    s = blockReduceSum(s, sh);
    s2 = blockReduceSum(s2, sh);
    float mean = s / DM;
    float var = s2 / DM - mean * mean;
    float inv = rsqrtf(var + 1e-5f);
    float2 gv = ((const float2*)gam)[tid];
    float2 bv = ((const float2*)bet)[tid];
    storeDual2(xd, plane, idx,
               (v.x - mean) * inv * gv.x + bv.x,
               (v.y - mean) * inv * gv.y + bv.y);
}

__global__ void landmark_kernel(const bf16* __restrict__ qkvd, long long qkvPlane,
                                bf16* __restrict__ qld, bf16* __restrict__ kld,
                                long long plane) {
    int m = blockIdx.x, bh = blockIdx.y;
    int b = bh >> 3, h = bh & 7;
    int d = threadIdx.x;
    long long base = (long long)b * NPAD * TD + (long long)m * LPER * TD + h * 64 + d;
    float sq = 0.f, sk = 0.f;
    #pragma unroll 4
    for (int r = 0; r < LPER; r++) {
        long long i = base + (long long)r * TD;
        sq += loadDual(qkvd, qkvPlane, i);
        sk += loadDual(qkvd, qkvPlane, i + 512);
    }
    long long idx = ((long long)bh * NLM + m) * DH + d;
    storeDual1(qld, plane, idx, sq * (1.f / LPER));
    storeDual1(kld, plane, idx, sk * (1.f / LPER));
}

__global__ void softmax256(const float* __restrict__ in, float* __restrict__ out32,
                           bf16* __restrict__ dual, long long plane, long long nrows) {
    long long row = (long long)blockIdx.x * 8 + (threadIdx.x >> 5);
    if (row >= nrows) return;
    int lane = threadIdx.x & 31;
    const float4* pi = (const float4*)(in + row * 256);
    float4 v0 = pi[lane];
    float4 v1 = pi[lane + 32];
    float m = fmaxf(fmaxf(fmaxf(v0.x, v0.y), fmaxf(v0.z, v0.w)),
                    fmaxf(fmaxf(v1.x, v1.y), fmaxf(v1.z, v1.w)));
    #pragma unroll
    for (int o = 16; o; o >>= 1) m = fmaxf(m, __shfl_xor_sync(0xffffffffu, m, o));
    v0.x = __expf(v0.x - m); v0.y = __expf(v0.y - m);
    v0.z = __expf(v0.z - m); v0.w = __expf(v0.w - m);
    v1.x = __expf(v1.x - m); v1.y = __expf(v1.y - m);
    v1.z = __expf(v1.z - m); v1.w = __expf(v1.w - m);
    float s = v0.x + v0.y + v0.z + v0.w + v1.x + v1.y + v1.z + v1.w;
    #pragma unroll
    for (int o = 16; o; o >>= 1) s += __shfl_xor_sync(0xffffffffu, s, o);
    float inv = 1.f / s;
    v0.x *= inv; v0.y *= inv; v0.z *= inv; v0.w *= inv;
    v1.x *= inv; v1.y *= inv; v1.z *= inv; v1.w *= inv;
    if (out32) {
        ((float4*)(out32 + row * 256))[lane] = v0;
        ((float4*)(out32 + row * 256))[lane + 32] = v1;
    }
    long long b0 = row * 256 + lane * 4;
    storeDual2(dual, plane, b0, v0.x, v0.y);
    storeDual2(dual, plane, b0 + 2, v0.z, v0.w);
    storeDual2(dual, plane, b0 + 128, v1.x, v1.y);
    storeDual2(dual, plane, b0 + 130, v1.z, v1.w);
}

__global__ void reset_kernel() {
    if (threadIdx.x == 0) { g_maxrow = 0; g_maxcol = 0; }
}

__global__ void a2stats_kernel(const float* __restrict__ a2) {
    __shared__ float sh[8];
    int bh = blockIdx.x;
    const float* a = a2 + (long long)bh * MM;
    int j = threadIdx.x;
    float cs = 0.f, rs = 0.f;
    for (int i = 0; i < NLM; i++) cs += a[(long long)i * NLM + j];
    const float* row = a + (long long)j * NLM;
    for (int i = 0; i < NLM; i++) rs += row[i];
    float cmax = blockReduceMax(cs, sh);
    float rmax = blockReduceMax(rs, sh);
    if (threadIdx.x == 0) {
        atomicMax(&g_maxcol, __float_as_int(cmax));
        atomicMax(&g_maxrow, __float_as_int(rmax));
    }
}

__global__ void z0_kernel(const float* __restrict__ a2, bf16* __restrict__ zp, long long plane) {
    __shared__ float tile[32][33];
    int bh = blockIdx.z;
    const float* a = a2 + (long long)bh * MM;
    long long zbase = (long long)bh * MM;
    float inv = 1.f / (__int_as_float(g_maxrow) * __int_as_float(g_maxcol));
    int i0 = blockIdx.y * 32, j0 = blockIdx.x * 32;
    for (int r = threadIdx.y; r < 32; r += 8)
        tile[r][threadIdx.x] = a[(long long)(i0 + r) * NLM + j0 + threadIdx.x];
    __syncthreads();
    for (int r = threadIdx.y; r < 32; r += 8)
        storeDual1(zp, plane, zbase + (long long)(j0 + r) * NLM + i0 + threadIdx.x,
                   tile[threadIdx.x][r] * inv);
}

__global__ void conv_kernel(const bf16* __restrict__ qkvd, long long qkvPlane,
                            const float* __restrict__ w, float* __restrict__ outh) {
    int bh = blockIdx.y;
    int b = bh >> 3, h = bh & 7;
    int iBase = blockIdx.x * 64;
    __shared__ float sv[96][64];
    __shared__ float sw[CONVK];
    long long vbase = (long long)b * NPAD * TD + 1024 + h * 64;
    int tid = threadIdx.x;
    for (int idx = tid; idx < 96 * 64; idx += 256) {
        int r = idx >> 6, d = idx & 63;
        int gi = iBase - 16 + r;
        sv[r][d] = (gi >= 0 && gi < NPAD)
                   ? loadDual(qkvd, qkvPlane, vbase + (long long)gi * TD + d) : 0.f;
    }
    if (tid < CONVK) sw[tid] = w[h * CONVK + tid];
    __syncthreads();
    float* out = outh + (long long)bh * NPAD * DH + (long long)iBase * DH;
    for (int idx = tid; idx < 64 * 64; idx += 256) {
        int r = idx >> 6, d = idx & 63;
        float s = 0.f;
        #pragma unroll
        for (int t = 0; t < CONVK; t++) s += sw[t] * sv[r + t][d];
        out[r * 64 + d] = s;
    }
}

__global__ void final_kernel(const float* __restrict__ h, const float* __restrict__ gam,
                             const float* __restrict__ bet, const float* __restrict__ w2,
                             const float* __restrict__ b2, float* __restrict__ out) {
    __shared__ float sh[8];
    int b = blockIdx.x;
    const float* x = h + ((long long)b * NPAD + PADN) * DM;
    float s = 0.f, s2 = 0.f;
    for (int i = threadIdx.x; i < DM; i += 256) { float v = x[i]; s += v; s2 += v * v; }
    s = blockReduceSum(s, sh);
    s2 = blockReduceSum(s2, sh);
    float mean = s / DM;
    float var = s2 / DM - mean * mean;
    float inv = rsqrtf(var + 1e-5f);
    float p0 = 0.f, p1 = 0.f;
    for (int i = threadIdx.x; i < DM; i += 256) {
        float hn = (x[i] - mean) * inv * gam[i] + bet[i];
        p0 += hn * w2[2 * i];
        p1 += hn * w2[2 * i + 1];
    }
    p0 = blockReduceSum(p0, sh);
    p1 = blockReduceSum(p1, sh);
    if (threadIdx.x == 0) {
        float l0 = p0 + b2[0], l1 = p1 + b2[1];
        float mx = fmaxf(l0, l1);
        float e0 = expf(l0 - mx), e1 = expf(l1 - mx);
        float si = 1.f / (e0 + e1);
        out[b * 2 + 0] = l0;
        out[b * 2 + 1] = l1;
        out[4 + b * 2 + 0] = e0 * si;
        out[4 + b * 2 + 1] = e1 * si;
        out[8 + b] = (l1 > l0) ? 1.f : 0.f;
    }
}

// ---------------- host side ----------------
static void launch_gemm(int bm, int bn, const bf16* A, const bf16* B,
                        long long aPlane, long long bPlane,
                        float* C, bf16* D, long long dPlane, bf16* D2, long long d2Plane,
                        int M, int N, int K, int lda, int ldb, int ldc,
                        long long aO, long long aI, int aC,
                        long long bO, long long bI, int bC,
                        long long cS, int batches, float alpha,
                        const float* bias, int relu, int accum, int transB,
                        int splitK = 1, long long partStride = 0,
                        float diagVal = 0.f, float diag2 = 0.f) {
    dim3 grid(N / bn, (M + bm - 1) / bm, batches * splitK);
    if (bm == 256)
        gemm_tc<256, 128, 4, 2, 1><<<grid, 256, BIG_SMEM_BYTES>>>(
            A, B, aPlane, bPlane, C, D, dPlane, D2, d2Plane,
            M, K, lda, ldb, ldc, aO, aI, aC, bO, bI, bC,
            cS, alpha, bias, relu, accum, transB, splitK, partStride, diagVal, diag2);
    else if (bn == 128)
        gemm_tc<128, 128, 2, 4, 0><<<grid, 256>>>(
            A, B, aPlane, bPlane, C, D, dPlane, D2, d2Plane,
            M, K, lda, ldb, ldc, aO, aI, aC, bO, bI, bC,
            cS, alpha, bias, relu, accum, transB, splitK, partStride, diagVal, diag2);
    else
        gemm_tc<128, 64, 4, 2, 0><<<grid, 256>>>(
            A, B, aPlane, bPlane, C, D, dPlane, D2, d2Plane,
            M, K, lda, ldb, ldc, aO, aI, aC, bO, bI, bC,
            cS, alpha, bias, relu, accum, transB, splitK, partStride, diagVal, diag2);
}

#define SYMF(p, s) do { void* _t; cudaGetSymbolAddress(&_t, s); p = (float*)_t; } while (0)
#define SYMB(p, s) do { void* _t; cudaGetSymbolAddress(&_t, s); p = (bf16*)_t; } while (0)

extern "C" void kernel_launch(void* const* d_in, const int* in_sizes, int n_in,
                              void* d_out, int out_size) {
    const float* feats = (const float*)d_in[0];
    const float* fc1_w = (const float*)d_in[1];
    const float* fc1_b = (const float*)d_in[2];
    const float* cls   = (const float*)d_in[3];
    const float* lng[2]   = {(const float*)d_in[4],  (const float*)d_in[10]};
    const float* lnb[2]   = {(const float*)d_in[5],  (const float*)d_in[11]};
    const float* qkvw[2]  = {(const float*)d_in[6],  (const float*)d_in[12]};
    const float* outw[2]  = {(const float*)d_in[7],  (const float*)d_in[13]};
    const float* outb[2]  = {(const float*)d_in[8],  (const float*)d_in[14]};
    const float* convw[2] = {(const float*)d_in[9],  (const float*)d_in[15]};
    const float* nfg  = (const float*)d_in[16];
    const float* nfb  = (const float*)d_in[17];
    const float* fc2w = (const float*)d_in[18];
    const float* fc2b = (const float*)d_in[19];

    float *h, *a2, *outh, *po, *pm, *ps;
    SYMF(h, g_h); SYMF(a2, g_a2); SYMF(outh, g_outh);
    SYMF(po, g_po); SYMF(pm, g_pm); SYMF(ps, g_ps);
    bf16 *featsd, *w1d, *qkvwd, *outwd, *xlnd, *qkvd, *qld, *kld, *a2d;
    bf16 *zpd, *t1d, *t2d, *t3d, *a3vd, *wd, *catd;
    SYMB(featsd, g_featsd); SYMB(w1d, g_w1d); SYMB(qkvwd, g_qkvwd); SYMB(outwd, g_outwd);
    SYMB(xlnd, g_xlnd); SYMB(qkvd, g_qkvd); SYMB(qld, g_qld); SYMB(kld, g_kld);
    SYMB(a2d, g_a2d);
    SYMB(zpd, g_zpd); SYMB(t1d, g_t1d); SYMB(t2d, g_t2d); SYMB(t3d, g_t3d);
    SYMB(a3vd, g_a3vd); SYMB(wd, g_wd); SYMB(catd, g_catd);

    const long long featsPlane = (long long)BATCH * NTOK * DIN;
    const long long xlnPlane   = (long long)BATCH * NPAD * DM;
    const long long qkvPlane   = (long long)BATCH * NPAD * TD;
    const long long qlPlane    = (long long)BHN * NLM * DH;
    const long long a2Plane    = (long long)BHN * MM;
    const long long zpPlane    = 32LL * MM;
    const long long t16Plane   = 16LL * MM;
    const long long avPlane    = (long long)BHN * NLM * DH;
    const long long catPlane   = (long long)BATCH * NPAD * DM;

    cudaFuncSetAttribute(flash_kernel<0>, cudaFuncAttributeMaxDynamicSharedMemorySize, FA_SMEM_BYTES);
    cudaFuncSetAttribute(flash_kernel<1>, cudaFuncAttributeMaxDynamicSharedMemorySize, FA_SMEM_BYTES);
    cudaFuncSetAttribute((const void*)gemm_tc<256, 128, 4, 2, 1>,
                         cudaFuncAttributeMaxDynamicSharedMemorySize, BIG_SMEM_BYTES);

    tobf16_kernel<<<(unsigned)((featsPlane + 255) / 256), 256>>>(feats, featsd, featsPlane, featsPlane);
    tobf16_kernel<<<(DIN * DM + 255) / 256, 256>>>(fc1_w, w1d, DIN * DM, DIN * DM);
    for (int l = 0; l < 2; l++) {
        tobf16_kernel<<<(DM * TD + 255) / 256, 256>>>(qkvw[l], qkvwd + (long long)l * 2 * DM * TD,
                                                      DM * TD, DM * TD);
        tobf16_kernel<<<(DM * DM + 255) / 256, 256>>>(outw[l], outwd + (long long)l * 2 * DM * DM,
                                                      DM * DM, DM * DM);
    }

    init_h_kernel<<<dim3(PADN + 1, BATCH), 256>>>(cls, h);

    // fc1 + relu (BM=256)
    launch_gemm(256, 128, featsd, w1d, featsPlane, DIN * DM,
                h + (long long)(PADN + 1) * DM, nullptr, 0, nullptr, 0,
                NTOK, DM, DIN, DIN, DM, DM,
                (long long)NTOK * DIN, 0, 1, 0, 0, 1,
                (long long)NPAD * DM, BATCH, 1.f, fc1_b, 1, 0, 0);

    for (int l = 0; l < 2; l++) {
        layernorm_kernel<<<BATCH * NPAD, 256>>>(h, xlnd, xlnPlane, lng[l], lnb[l]);

        // qkv = xln @ qkvw  (BM=256, dual output only)
        launch_gemm(256, 128, xlnd, qkvwd + (long long)l * 2 * DM * TD, xlnPlane, DM * TD,
                    nullptr, qkvd, qkvPlane, nullptr, 0,
                    NPAD, TD, DM, DM, TD, TD,
                    (long long)NPAD * DM, 0, 1, 0, 0, 1,
                    (long long)NPAD * TD, BATCH, 1.f, nullptr, 0, 0, 0);

        landmark_kernel<<<dim3(NLM, BHN), 64>>>(qkvd, qkvPlane, qld, kld, qlPlane);

        // a2 = softmax(0.125 * q_l @ k_l^T)
        launch_gemm(128, 128, qld, kld, qlPlane, qlPlane,
                    a2, nullptr, 0, nullptr, 0,
                    NLM, NLM, DH, DH, DH, NLM,
                    (long long)NLM * DH, 0, 1, (long long)NLM * DH, 0, 1,
                    MM, BHN, 0.125f, nullptr, 0, 0, 1);
        softmax256<<<(BHN * NLM) / 8, 256>>>(a2, a2, a2d, a2Plane, (long long)BHN * NLM);

        // F1: a3v = softmax(0.125 q_l K^T) V
        flash_kernel<0><<<dim3(NLM / 128, NSPLIT, BHN), 256, FA_SMEM_BYTES>>>(
            qld, qlPlane, DH, 0, (long long)NLM * DH, BHN,
            qkvd + DM, qkvPlane, TD, (long long)NPAD * TD, 64, NH,
            qkvd + 2 * DM, qkvPlane, TD, (long long)NPAD * TD, 64, NH,
            NPAD / NSPLIT, po, pm, ps, nullptr, nullptr, 0);
        fa_combine<<<(unsigned)((long long)BHN * NLM * DH / 256), 256>>>(po, pm, ps, a3vd, avPlane);

        // pinv(a2): p-propagated Newton chain
        reset_kernel<<<1, 32>>>();
        a2stats_kernel<<<BHN, 256>>>(a2);
        z0_kernel<<<dim3(8, 8, BHN), dim3(32, 8)>>>(a2, zpd, zpPlane);
        launch_gemm(128, 64, a2d, zpd, a2Plane, zpPlane,
                    nullptr, zpd + 16 * MM, zpPlane, t1d + 16 * MM, zpPlane,
                    NLM, NLM, NLM, NLM, NLM, NLM,
                    MM, 0, 1, MM, 0, 1, MM, BHN, 1.f, nullptr, 0, 0, 0,
                    1, 0, 0.f, 7.f);
        for (int it = 0; it < 6; it++) {
            launch_gemm(128, 64, zpd + 16 * MM, t1d + 16 * MM, zpPlane, zpPlane,
                        nullptr, nullptr, 0, t2d, t16Plane,
                        NLM, NLM, NLM, NLM, NLM, NLM,
                        MM, 0, 1, MM, 0, 1, MM, BHN, 1.f, nullptr, 0, 0, 0,
                        1, 0, 0.f, 15.f);
            launch_gemm(128, 64, zpd + 16 * MM, t2d, zpPlane, t16Plane,
                        nullptr, nullptr, 0, t3d, t16Plane,
                        NLM, NLM, NLM, NLM, NLM, NLM,
                        MM, 0, 1, MM, 0, 1, MM, BHN, 1.f, nullptr, 0, 0, 0,
                        1, 0, 0.f, 13.f);
            launch_gemm(128, 64, zpd, t3d, zpPlane, t16Plane,
                        nullptr, zpd, zpPlane, t1d, zpPlane,
                        NLM, NLM, NLM, NLM, NLM, NLM,
                        0, MM, 32, 0, MM, 16, MM, 32, 0.25f, nullptr, 0, 0, 0,
                        1, 0, 0.f, 7.f);
        }

        // w = pinv(a2) @ a3v
        launch_gemm(128, 64, zpd, a3vd, zpPlane, avPlane,
                    nullptr, wd, avPlane, nullptr, 0,
                    NLM, DH, NLM, NLM, DH, DH,
                    MM, 0, 1, (long long)NLM * DH, 0, 1,
                    (long long)NLM * DH, BHN, 1.f, nullptr, 0, 0, 0);

        // conv writes outh (pure conv result)
        conv_kernel<<<dim3(NPAD / 64, BHN), 256>>>(qkvd, qkvPlane, convw[l], outh);

        // F2: catd = merge( softmax(0.125 Q k_l^T) @ w + conv )
        flash_kernel<1><<<dim3(NPAD / 128, 1, BHN), 256, FA_SMEM_BYTES>>>(
            qkvd, qkvPlane, TD, (long long)NPAD * TD, 64, NH,
            kld, qlPlane, DH, 0, (long long)NLM * DH, BHN,
            wd, avPlane, DH, 0, (long long)NLM * DH, BHN,
            NLM, nullptr, nullptr, nullptr, outh, catd, catPlane);

        // output projection, accumulate into residual stream (BM=256, fp32)
        launch_gemm(256, 128, catd + (long long)PADN * DM, outwd + (long long)l * 2 * DM * DM,
                    catPlane, DM * DM,
                    h + (long long)PADN * DM, nullptr, 0, nullptr, 0,
                    NP1, DM, DM, DM, DM, DM,
                    (long long)NPAD * DM, 0, 1, 0, 0, 1,
                    (long long)NPAD * DM, BATCH, 1.f, outb[l], 0, 1, 0);
    }

    final_kernel<<<BATCH, 256>>>(h, nfg, nfb, fc2w, fc2b, (float*)d_out);
}

// round 11
// speedup vs baseline: 1.0516x; 1.0516x over previous
#include <cuda_runtime.h>
#include <cuda_bf16.h>
#include <cstdint>
#include <math.h>

#define BATCH 2
#define NTOK  8000
#define NP1   8001
#define PADN  191
#define NPAD  8192
#define DM    512
#define DIN   1024
#define NH    8
#define DH    64
#define NLM   256
#define LPER  32
#define BHN   16
#define CONVK 33
#define TD    1536
#define BM    128
#define BK    32
#define NSPLIT 8
#define MM    ((long long)NLM * NLM)

typedef __nv_bfloat16 bf16;

// ---------------- fp32 scratch ----------------
__device__ float g_h   [(long long)BATCH*NPAD*DM];
__device__ float g_a2  [(long long)BHN*NLM*NLM];
__device__ float g_outh[(long long)BHN*NPAD*DH];
__device__ float g_po  [(long long)NSPLIT*BHN*NLM*DH];
__device__ float g_pm  [(long long)NSPLIT*BHN*NLM];
__device__ float g_ps  [(long long)NSPLIT*BHN*NLM];
__device__ int   g_maxrow;
__device__ int   g_maxcol;

// ---------------- dual-bf16 scratch (hi plane + lo plane) ----------------
__device__ __align__(16) bf16 g_featsd[2LL*BATCH*NTOK*DIN];
__device__ __align__(16) bf16 g_w1d   [2LL*DIN*DM];
__device__ __align__(16) bf16 g_qkvwd [2LL*2*DM*TD];
__device__ __align__(16) bf16 g_outwd [2LL*2*DM*DM];
__device__ __align__(16) bf16 g_xlnd  [2LL*BATCH*NPAD*DM];
__device__ __align__(16) bf16 g_qkvd  [2LL*BATCH*NPAD*TD];
__device__ __align__(16) bf16 g_qld   [2LL*BHN*NLM*DH];
__device__ __align__(16) bf16 g_kld   [2LL*BHN*NLM*DH];
__device__ __align__(16) bf16 g_a2d   [2LL*BHN*NLM*NLM];
__device__ __align__(16) bf16 g_zpd   [2LL*32*NLM*NLM];   // z0 in batches 0-15, p in 16-31
__device__ __align__(16) bf16 g_p2d   [2LL*16*NLM*NLM];
__device__ __align__(16) bf16 g_t1d   [2LL*16*NLM*NLM];
__device__ __align__(16) bf16 g_t2d   [2LL*16*NLM*NLM];
__device__ __align__(16) bf16 g_t3d   [2LL*6*16*NLM*NLM]; // six stored t3 factors
__device__ __align__(16) bf16 g_a3vd  [2LL*BHN*NLM*DH];
__device__ __align__(16) bf16 g_u1d   [2LL*BHN*NLM*DH];
__device__ __align__(16) bf16 g_u2d   [2LL*BHN*NLM*DH];
__device__ __align__(16) bf16 g_wd    [2LL*BHN*NLM*DH];
__device__ __align__(16) bf16 g_catd  [2LL*BATCH*NPAD*DM];

// ---------------- helpers ----------------
__device__ __forceinline__ void storeDual2(bf16* d, long long plane, long long idx,
                                           float x, float y) {
    __nv_bfloat162 h = __floats2bfloat162_rn(x, y);
    *reinterpret_cast<__nv_bfloat162*>(d + idx) = h;
    __nv_bfloat162 l = __floats2bfloat162_rn(x - __bfloat162float(h.x),
                                             y - __bfloat162float(h.y));
    *reinterpret_cast<__nv_bfloat162*>(d + plane + idx) = l;
}
__device__ __forceinline__ void storeDual1(bf16* d, long long plane, long long idx, float x) {
    bf16 h = __float2bfloat16(x);
    d[idx] = h;
    d[plane + idx] = __float2bfloat16(x - __bfloat162float(h));
}
__device__ __forceinline__ float loadDual(const bf16* d, long long plane, long long idx) {
    return __bfloat162float(d[idx]) + __bfloat162float(d[plane + idx]);
}
__device__ __forceinline__ void cpa16(uint32_t dst, const void* src, bool pred) {
    int sz = pred ? 16 : 0;
    asm volatile("cp.async.cg.shared.global [%0], [%1], 16, %2;\n"
                 :: "r"(dst), "l"(src), "r"(sz));
}
__device__ __forceinline__ void cpa_commit() {
    asm volatile("cp.async.commit_group;\n");
}

__device__ __forceinline__ float blockReduceSum(float v, float* sh) {
    #pragma unroll
    for (int o = 16; o; o >>= 1) v += __shfl_xor_sync(0xffffffffu, v, o);
    int w = threadIdx.x >> 5;
    if ((threadIdx.x & 31) == 0) sh[w] = v;
    __syncthreads();
    if (threadIdx.x < 8) {
        v = sh[threadIdx.x];
        #pragma unroll
        for (int o = 4; o; o >>= 1) v += __shfl_xor_sync(0xffu, v, o);
        if (threadIdx.x == 0) sh[0] = v;
    }
    __syncthreads();
    float r = sh[0];
    __syncthreads();
    return r;
}
__device__ __forceinline__ float blockReduceMax(float v, float* sh) {
    #pragma unroll
    for (int o = 16; o; o >>= 1) v = fmaxf(v, __shfl_xor_sync(0xffffffffu, v, o));
    int w = threadIdx.x >> 5;
    if ((threadIdx.x & 31) == 0) sh[w] = v;
    __syncthreads();
    if (threadIdx.x < 8) {
        v = sh[threadIdx.x];
        #pragma unroll
        for (int o = 4; o; o >>= 1) v = fmaxf(v, __shfl_xor_sync(0xffu, v, o));
        if (threadIdx.x == 0) sh[0] = v;
    }
    __syncthreads();
    float r = sh[0];
    __syncthreads();
    return r;
}

__device__ __forceinline__ void mma16816(float* c, const unsigned* a, const unsigned* b) {
    asm volatile(
        "mma.sync.aligned.m16n8k16.row.col.f32.bf16.bf16.f32 "
        "{%0,%1,%2,%3},{%4,%5,%6,%7},{%8,%9},{%0,%1,%2,%3};\n"
        : "+f"(c[0]), "+f"(c[1]), "+f"(c[2]), "+f"(c[3])
        : "r"(a[0]), "r"(a[1]), "r"(a[2]), "r"(a[3]), "r"(b[0]), "r"(b[1]));
}
__device__ __forceinline__ void ldsm4(unsigned& r0, unsigned& r1, unsigned& r2, unsigned& r3,
                                      uint32_t addr) {
    asm volatile("ldmatrix.sync.aligned.m8n8.x4.shared.b16 {%0,%1,%2,%3}, [%4];\n"
                 : "=r"(r0), "=r"(r1), "=r"(r2), "=r"(r3) : "r"(addr));
}
__device__ __forceinline__ void ldsm4t(unsigned& r0, unsigned& r1, unsigned& r2, unsigned& r3,
                                       uint32_t addr) {
    asm volatile("ldmatrix.sync.aligned.m8n8.x4.trans.shared.b16 {%0,%1,%2,%3}, [%4];\n"
                 : "=r"(r0), "=r"(r1), "=r"(r2), "=r"(r3) : "r"(addr));
}
__device__ __forceinline__ void split2(float x, float y, unsigned& hi, unsigned& lo) {
    __nv_bfloat162 h = __floats2bfloat162_rn(x, y);
    __nv_bfloat162 l = __floats2bfloat162_rn(x - __bfloat162float(h.x),
                                             y - __bfloat162float(h.y));
    hi = *reinterpret_cast<unsigned*>(&h);
    lo = *reinterpret_cast<unsigned*>(&l);
}

// ---------------- dual-bf16 tensor-core GEMM (cp.async pipelined) ----------------
template<int BN, int WROWS, int WCOLS>
__global__ void __launch_bounds__(256) gemm_tc(
    const bf16* __restrict__ A, const bf16* __restrict__ B,
    long long aPlane, long long bPlane,
    float* __restrict__ C, bf16* __restrict__ D, long long dPlane,
    bf16* __restrict__ D2, long long d2Plane,
    int Mn, int Kn, int lda, int ldb, int ldc,
    long long aOuter, long long aInner, int aCnt,
    long long bOuter, long long bInner, int bCnt,
    long long cStride, float alpha, const float* __restrict__ bias,
    int relu, int accum, int transB, int splitK, long long partStride,
    float diagVal, float diag2)
{
    constexpr int WM = BM / WROWS;
    constexpr int WN = BN / WCOLS;
    constexpr int MT = WM / 16;
    constexpr int NT = WN / 8;
    constexpr int NTP = WN / 16;
    constexpr int KST = BN + 8;
    constexpr int ASTG = 2 * BM * 40;
    constexpr int BSTG = 2 * BN * 40;

    int bz = blockIdx.z;
    int batch = bz / splitK;
    int split = bz - batch * splitK;
    const bf16* Ab = A + (long long)(batch / aCnt) * aOuter + (long long)(batch % aCnt) * aInner;
    const bf16* Bb = B + (long long)(batch / bCnt) * bOuter + (long long)(batch % bCnt) * bInner;
    long long cOff = (long long)batch * cStride + (long long)split * partStride;
    int kPer = Kn / splitK;
    int kStart = split * kPer;

    __shared__ __align__(16) bf16 sA[2 * ASTG];
    __shared__ __align__(16) bf16 sB[2 * BSTG];
    uint32_t saBase = (uint32_t)__cvta_generic_to_shared(sA);
    uint32_t sbBase = (uint32_t)__cvta_generic_to_shared(sB);

    int tid = threadIdx.x;
    int lane = tid & 31;
    int wid = tid >> 5;
    int lt = lane & 7;
    int lg = lane >> 3;
    int warpM = (wid / WCOLS) * WM;
    int warpN = (wid % WCOLS) * WN;
    int rowBase = blockIdx.y * BM;
    int colBase = blockIdx.x * BN;

    float acc[MT][NT][4];
    #pragma unroll
    for (int i = 0; i < MT; i++)
        #pragma unroll
        for (int j = 0; j < NT; j++)
            #pragma unroll
            for (int e = 0; e < 4; e++) acc[i][j][e] = 0.f;

    auto issue = [&](int k0, int stg) {
        uint32_t sa = saBase + stg * ASTG * 2;
        uint32_t sb = sbBase + stg * BSTG * 2;
        #pragma unroll
        for (int p = 0; p < 2; p++)
            #pragma unroll
            for (int j = 0; j < 2; j++) {
                int id = tid + j * 256;
                int row = id >> 2, seg = id & 3;
                int gr = rowBase + row;
                bool ok = gr < Mn;
                const bf16* src = Ab + p * aPlane +
                                  (long long)(ok ? gr : 0) * lda + kStart + k0 + seg * 8;
                cpa16(sa + (((p * BM + row) * 40 + seg * 8) << 1), src, ok);
            }
        if (transB) {
            #pragma unroll
            for (int p = 0; p < 2; p++)
                #pragma unroll
                for (int j = 0; j < BN / 64; j++) {
                    int id = tid + j * 256;
                    int row = id >> 2, seg = id & 3;
                    const bf16* src = Bb + p * bPlane +
                                      (long long)(colBase + row) * ldb + kStart + k0 + seg * 8;
                    cpa16(sb + (((p * BN + row) * 40 + seg * 8) << 1), src, true);
                }
        } else {
            #pragma unroll
            for (int p = 0; p < 2; p++)
                #pragma unroll
                for (int j = 0; j < BN / 64; j++) {
                    int id = tid + j * 256;
                    int k = id / (BN / 8), seg = id % (BN / 8);
                    const bf16* src = Bb + p * bPlane +
                                      (long long)(kStart + k0 + k) * ldb + colBase + seg * 8;
                    cpa16(sb + (((p * 32 + k) * KST + seg * 8) << 1), src, true);
                }
        }
        cpa_commit();
    };

    int nIter = kPer / BK;
    issue(0, 0);

    for (int it = 0; it < nIter; it++) {
        int cur = it & 1;
        asm volatile("cp.async.wait_group 0;\n");
        __syncthreads();
        if (it + 1 < nIter) issue((it + 1) * BK, cur ^ 1);

        uint32_t saS = saBase + cur * ASTG * 2;
        uint32_t sbS = sbBase + cur * BSTG * 2;

        #pragma unroll
        for (int ks = 0; ks < 2; ks++) {
            int k8 = ks * 16;
            unsigned bh[NTP][4], bl[NTP][4];
            #pragma unroll
            for (int ntp = 0; ntp < NTP; ntp++) {
                if (transB) {
                    int n = warpN + ntp * 16 + lt + ((lg >> 1) << 3);
                    int kk = k8 + ((lg & 1) << 3);
                    ldsm4(bh[ntp][0], bh[ntp][1], bh[ntp][2], bh[ntp][3],
                          sbS + (((0 * BN + n) * 40 + kk) << 1));
                    ldsm4(bl[ntp][0], bl[ntp][1], bl[ntp][2], bl[ntp][3],
                          sbS + (((1 * BN + n) * 40 + kk) << 1));
                } else {
                    int k = k8 + lt + ((lg & 1) << 3);
                    int n = warpN + ntp * 16 + ((lg >> 1) << 3);
                    ldsm4t(bh[ntp][0], bh[ntp][1], bh[ntp][2], bh[ntp][3],
                           sbS + (((0 * 32 + k) * KST + n) << 1));
                    ldsm4t(bl[ntp][0], bl[ntp][1], bl[ntp][2], bl[ntp][3],
                           sbS + (((1 * 32 + k) * KST + n) << 1));
                }
            }
            #pragma unroll
            for (int mt = 0; mt < MT; mt++) {
                unsigned ah[4], al[4];
                int m = warpM + mt * 16 + lt + ((lg & 1) << 3);
                int kk = k8 + ((lg >> 1) << 3);
                ldsm4(ah[0], ah[1], ah[2], ah[3],
                      saS + (((0 * BM + m) * 40 + kk) << 1));
                ldsm4(al[0], al[1], al[2], al[3],
                      saS + (((1 * BM + m) * 40 + kk) << 1));
                #pragma unroll
                for (int nt = 0; nt < NT; nt++) {
                    const unsigned* ph = &bh[nt >> 1][(nt & 1) * 2];
                    const unsigned* pl = &bl[nt >> 1][(nt & 1) * 2];
                    mma16816(acc[mt][nt], ah, ph);
                    mma16816(acc[mt][nt], ah, pl);
                    mma16816(acc[mt][nt], al, ph);
                }
            }
        }
        __syncthreads();
    }

    int q = lane & 3, g = lane >> 2;
    float* Cb = C ? C + cOff : nullptr;
    bf16* Db = D ? D + cOff : nullptr;
    bf16* D2b = D2 ? D2 + cOff : nullptr;
    #pragma unroll
    for (int mt = 0; mt < MT; mt++) {
        #pragma unroll
        for (int nt = 0; nt < NT; nt++) {
            int r0 = rowBase + warpM + mt * 16 + g;
            int c0 = colBase + warpN + nt * 8 + q * 2;
            #pragma unroll
            for (int half = 0; half < 2; half++) {
                int gr = r0 + half * 8;
                if (gr >= Mn) continue;
                float v0 = alpha * acc[mt][nt][half * 2 + 0];
                float v1 = alpha * acc[mt][nt][half * 2 + 1];
                if (gr == c0)     v0 += diagVal;
                if (gr == c0 + 1) v1 += diagVal;
                long long off = (long long)gr * ldc + c0;
                if (Cb) {
                    float w0 = v0, w1 = v1;
                    if (bias) { w0 += bias[c0]; w1 += bias[c0 + 1]; }
                    if (relu) { w0 = fmaxf(w0, 0.f); w1 = fmaxf(w1, 0.f); }
                    if (accum) { w0 += Cb[off]; w1 += Cb[off + 1]; }
                    *reinterpret_cast<float2*>(Cb + off) = make_float2(w0, w1);
                }
                if (Db) storeDual2(Db, dPlane, off, v0, v1);
                if (D2b) {
                    float u0 = ((gr == c0)     ? diag2 : 0.f) - v0;
                    float u1 = ((gr == c0 + 1) ? diag2 : 0.f) - v1;
                    storeDual2(D2b, d2Plane, off, u0, u1);
                }
            }
        }
    }
}

// ---------------- fused flash attention ----------------
#define FA_SMEM_BYTES (55296 * 2)

template<int MODE>
__global__ void __launch_bounds__(256) flash_kernel(
    const bf16* __restrict__ Qa, long long qPlane, int qStride,
    long long qOuter, long long qInner, int qCnt,
    const bf16* __restrict__ Ka, long long kPlane, int kStride,
    long long kOuter, long long kInner, int kCnt,
    const bf16* __restrict__ Va, long long vPlane, int vStride,
    long long vOuter, long long vInner, int vCnt,
    int keysPerSplit,
    float* __restrict__ PO, float* __restrict__ PM, float* __restrict__ PS,
    const float* __restrict__ CONV, bf16* __restrict__ CATD, long long catPlane)
{
    extern __shared__ __align__(16) bf16 fsm[];
    uint32_t smBase = (uint32_t)__cvta_generic_to_shared(fsm);
    int tid = threadIdx.x, lane = tid & 31, wid = tid >> 5;
    int lt = lane & 7, lg = lane >> 3, g = lane >> 2, q = lane & 3;
    int bh = blockIdx.z, split = blockIdx.y;
    int rowBase = blockIdx.x * 128;
    const bf16* Q = Qa + (long long)(bh / qCnt) * qOuter + (long long)(bh % qCnt) * qInner;
    const bf16* K = Ka + (long long)(bh / kCnt) * kOuter + (long long)(bh % kCnt) * kInner
                       + (long long)split * keysPerSplit * kStride;
    const bf16* V = Va + (long long)(bh / vCnt) * vOuter + (long long)(bh % vCnt) * vInner
                       + (long long)split * keysPerSplit * vStride;

    #pragma unroll
    for (int j = 0; j < 8; j++) {
        int c = tid + j * 256;
        int p = c >> 10, rem = c & 1023;
        int row = rem >> 3, seg = rem & 7;
        cpa16(smBase + (((p * 128 + row) * 72 + seg * 8) << 1),
              Q + (long long)p * qPlane + (long long)(rowBase + row) * qStride + seg * 8, true);
    }
    auto issueKV = [&](int t, int stg) {
        int key0 = t * 64;
        #pragma unroll
        for (int j = 0; j < 2; j++) {
            int c = tid + j * 256;
            int p = c >> 8, rem = c & 255;
            int row = rem >> 2, seg = rem & 3;
            cpa16(smBase + ((18432 + stg * 9216 + (p * 64 + row) * 72 + seg * 16) << 1),
                  K + (long long)p * kPlane + (long long)(key0 + row) * kStride + seg * 16, true);
            cpa16(smBase + ((18432 + stg * 9216 + (p * 64 + row) * 72 + seg * 16 + 8) << 1),
                  K + (long long)p * kPlane + (long long)(key0 + row) * kStride + seg * 16 + 8, true);
            cpa16(smBase + ((36864 + stg * 9216 + (p * 64 + row) * 72 + seg * 16) << 1),
                  V + (long long)p * vPlane + (long long)(key0 + row) * vStride + seg * 16, true);
            cpa16(smBase + ((36864 + stg * 9216 + (p * 64 + row) * 72 + seg * 16 + 8) << 1),
                  V + (long long)p * vPlane + (long long)(key0 + row) * vStride + seg * 16 + 8, true);
        }
        cpa_commit();
    };
    issueKV(0, 0);

    int warpRow = wid * 16;
    unsigned qh[4][4], qlo[4][4];
    float o[8][4];
    #pragma unroll
    for (int i = 0; i < 8; i++)
        #pragma unroll
        for (int e = 0; e < 4; e++) o[i][e] = 0.f;
    float m0 = -1e30f, m1 = -1e30f, l0 = 0.f, l1 = 0.f;

    int nTiles = keysPerSplit / 64;
    for (int t = 0; t < nTiles; t++) {
        int stg = t & 1;
        bool more = (t + 1 < nTiles);
        if (more) {
            issueKV(t + 1, stg ^ 1);
            asm volatile("cp.async.wait_group 1;\n");
        } else {
            asm volatile("cp.async.wait_group 0;\n");
        }
        __syncthreads();
        if (t == 0) {
            #pragma unroll
            for (int kc = 0; kc < 4; kc++) {
                int row = warpRow + lt + ((lg & 1) << 3);
                int kk = kc * 16 + ((lg >> 1) << 3);
                ldsm4(qh[kc][0], qh[kc][1], qh[kc][2], qh[kc][3],
                      smBase + (((0 * 128 + row) * 72 + kk) << 1));
                ldsm4(qlo[kc][0], qlo[kc][1], qlo[kc][2], qlo[kc][3],
                      smBase + (((1 * 128 + row) * 72 + kk) << 1));
            }
        }
        uint32_t skS = smBase + ((18432 + stg * 9216) << 1);
        uint32_t svS = smBase + ((36864 + stg * 9216) << 1);

        float sc[8][4];
        #pragma unroll
        for (int i = 0; i < 8; i++)
            #pragma unroll
            for (int e = 0; e < 4; e++) sc[i][e] = 0.f;
        #pragma unroll
        for (int kc = 0; kc < 4; kc++) {
            unsigned kh[4][4], kl[4][4];
            #pragma unroll
            for (int ntp = 0; ntp < 4; ntp++) {
                int n = ntp * 16 + lt + ((lg >> 1) << 3);
                int kk = kc * 16 + ((lg & 1) << 3);
                ldsm4(kh[ntp][0], kh[ntp][1], kh[ntp][2], kh[ntp][3],
                      skS + (((0 * 64 + n) * 72 + kk) << 1));
                ldsm4(kl[ntp][0], kl[ntp][1], kl[ntp][2], kl[ntp][3],
                      skS + (((64 + n) * 72 + kk) << 1));
            }
            #pragma unroll
            for (int nt = 0; nt < 8; nt++) {
                const unsigned* bhf = &kh[nt >> 1][(nt & 1) * 2];
                const unsigned* blf = &kl[nt >> 1][(nt & 1) * 2];
                mma16816(sc[nt], qh[kc], bhf);
                mma16816(sc[nt], qh[kc], blf);
                mma16816(sc[nt], qlo[kc], bhf);
            }
        }
        float mt0 = -1e30f, mt1 = -1e30f;
        #pragma unroll
        for (int nt = 0; nt < 8; nt++) {
            #pragma unroll
            for (int e = 0; e < 4; e++) sc[nt][e] *= 0.125f;
            mt0 = fmaxf(mt0, fmaxf(sc[nt][0], sc[nt][1]));
            mt1 = fmaxf(mt1, fmaxf(sc[nt][2], sc[nt][3]));
        }
        mt0 = fmaxf(mt0, __shfl_xor_sync(0xffffffffu, mt0, 1));
        mt0 = fmaxf(mt0, __shfl_xor_sync(0xffffffffu, mt0, 2));
        mt1 = fmaxf(mt1, __shfl_xor_sync(0xffffffffu, mt1, 1));
        mt1 = fmaxf(mt1, __shfl_xor_sync(0xffffffffu, mt1, 2));
        float mn0 = fmaxf(m0, mt0), mn1 = fmaxf(m1, mt1);
        float f0 = __expf(m0 - mn0), f1 = __expf(m1 - mn1);
        m0 = mn0; m1 = mn1;
        float rs0 = 0.f, rs1 = 0.f;
        #pragma unroll
        for (int nt = 0; nt < 8; nt++) {
            sc[nt][0] = __expf(sc[nt][0] - mn0);
            sc[nt][1] = __expf(sc[nt][1] - mn0);
            sc[nt][2] = __expf(sc[nt][2] - mn1);
            sc[nt][3] = __expf(sc[nt][3] - mn1);
            rs0 += sc[nt][0] + sc[nt][1];
            rs1 += sc[nt][2] + sc[nt][3];
        }
        rs0 += __shfl_xor_sync(0xffffffffu, rs0, 1);
        rs0 += __shfl_xor_sync(0xffffffffu, rs0, 2);
        rs1 += __shfl_xor_sync(0xffffffffu, rs1, 1);
        rs1 += __shfl_xor_sync(0xffffffffu, rs1, 2);
        l0 = l0 * f0 + rs0;
        l1 = l1 * f1 + rs1;
        #pragma unroll
        for (int nt = 0; nt < 8; nt++) {
            o[nt][0] *= f0; o[nt][1] *= f0;
            o[nt][2] *= f1; o[nt][3] *= f1;
        }
        #pragma unroll
        for (int kc = 0; kc < 4; kc++) {
            unsigned ph[4], pl[4];
            split2(sc[2 * kc][0],     sc[2 * kc][1],     ph[0], pl[0]);
            split2(sc[2 * kc][2],     sc[2 * kc][3],     ph[1], pl[1]);
            split2(sc[2 * kc + 1][0], sc[2 * kc + 1][1], ph[2], pl[2]);
            split2(sc[2 * kc + 1][2], sc[2 * kc + 1][3], ph[3], pl[3]);
            unsigned vh[4][4], vl[4][4];
            #pragma unroll
            for (int ntp = 0; ntp < 4; ntp++) {
                int k = kc * 16 + lt + ((lg & 1) << 3);
                int n = ntp * 16 + ((lg >> 1) << 3);
                ldsm4t(vh[ntp][0], vh[ntp][1], vh[ntp][2], vh[ntp][3],
                       svS + (((0 * 64 + k) * 72 + n) << 1));
                ldsm4t(vl[ntp][0], vl[ntp][1], vl[ntp][2], vl[ntp][3],
                       svS + (((64 + k) * 72 + n) << 1));
            }
            #pragma unroll
            for (int nt = 0; nt < 8; nt++) {
                const unsigned* bhf = &vh[nt >> 1][(nt & 1) * 2];
                const unsigned* blf = &vl[nt >> 1][(nt & 1) * 2];
                mma16816(o[nt], ph, bhf);
                mma16816(o[nt], ph, blf);
                mma16816(o[nt], pl, bhf);
            }
        }
        __syncthreads();
    }

    int row0 = rowBase + warpRow + g;
    int row1 = row0 + 8;
    if (MODE == 1) {
        float i0 = 1.f / l0, i1 = 1.f / l1;
        int b = bh >> 3, hh = bh & 7;
        const float* Cv = CONV + (long long)bh * NPAD * 64;
        #pragma unroll
        for (int nt = 0; nt < 8; nt++) {
            int col = nt * 8 + q * 2;
            float2 c0 = *(const float2*)&Cv[(long long)row0 * 64 + col];
            float2 c1 = *(const float2*)&Cv[(long long)row1 * 64 + col];
            long long i0d = ((long long)b * NPAD + row0) * DM + hh * 64 + col;
            long long i1d = ((long long)b * NPAD + row1) * DM + hh * 64 + col;
            storeDual2(CATD, catPlane, i0d, o[nt][0] * i0 + c0.x, o[nt][1] * i0 + c0.y);
            storeDual2(CATD, catPlane, i1d, o[nt][2] * i1 + c1.x, o[nt][3] * i1 + c1.y);
        }
    } else {
        long long pb = ((long long)split * BHN + bh) * NLM;
        #pragma unroll
        for (int nt = 0; nt < 8; nt++) {
            int col = nt * 8 + q * 2;
            *(float2*)&PO[(pb + row0) * 64 + col] = make_float2(o[nt][0], o[nt][1]);
            *(float2*)&PO[(pb + row1) * 64 + col] = make_float2(o[nt][2], o[nt][3]);
        }
        if (q == 0) {
            PM[pb + row0] = m0; PM[pb + row1] = m1;
            PS[pb + row0] = l0; PS[pb + row1] = l1;
        }
    }
}

__global__ void fa_combine(const float* __restrict__ po, const float* __restrict__ pm,
                           const float* __restrict__ ps, bf16* __restrict__ outd,
                           long long plane) {
    long long idx = (long long)blockIdx.x * 256 + threadIdx.x;
    int d = (int)(idx & 63);
    long long rid = idx >> 6;
    const long long RS = (long long)BHN * NLM;
    float M = -1e30f;
    #pragma unroll
    for (int s = 0; s < NSPLIT; s++) M = fmaxf(M, pm[s * RS + rid]);
    float S = 0.f, val = 0.f;
    #pragma unroll
    for (int s = 0; s < NSPLIT; s++) {
        float e = __expf(pm[s * RS + rid] - M);
        S += ps[s * RS + rid] * e;
        val += po[(s * RS + rid) * 64 + d] * e;
    }
    storeDual1(outd, plane, rid * 64 + d, val / S);
}

// ---------------- misc kernels ----------------
__global__ void tobf16_kernel(const float* __restrict__ x, bf16* __restrict__ d,
                              long long n, long long plane) {
    long long i = (long long)blockIdx.x * 256 + threadIdx.x;
    if (i >= n) return;
    storeDual1(d, plane, i, x[i]);
}

__global__ void init_h_kernel(const float* __restrict__ cls, float* __restrict__ h) {
    int r = blockIdx.x, b = blockIdx.y;
    float* o = h + ((long long)b * NPAD + r) * DM;
    for (int i = threadIdx.x; i < DM; i += 256) o[i] = (r == PADN) ? cls[i] : 0.f;
}

__global__ void layernorm_kernel(const float* __restrict__ in, bf16* __restrict__ xd,
                                 long long plane,
                                 const float* __restrict__ gam, const float* __restrict__ bet) {
    __shared__ float sh[8];
    long long row = blockIdx.x;
    int r = (int)(row % NPAD);
    int tid = threadIdx.x;
    long long idx = row * DM + tid * 2;
    if (r < PADN) {
        storeDual2(xd, plane, idx, 0.f, 0.f);
        return;
    }
    const float2* x = (const float2*)(in + row * DM);
    float2 v = x[tid];
    float s = v.x + v.y;
    float s2 = v.x * v.x + v.y * v.y;
    s = blockReduceSum(s, sh);
    s2 = blockReduceSum(s2, sh);
    float mean = s / DM;
    float var = s2 / DM - mean * mean;
    float inv = rsqrtf(var + 1e-5f);
    float2 gv = ((const float2*)gam)[tid];
    float2 bv = ((const float2*)bet)[tid];
    storeDual2(xd, plane, idx,
               (v.x - mean) * inv * gv.x + bv.x,
               (v.y - mean) * inv * gv.y + bv.y);
}

__global__ void landmark_kernel(const bf16* __restrict__ qkvd, long long qkvPlane,
                                bf16* __restrict__ qld, bf16* __restrict__ kld,
                                long long plane) {
    int m = blockIdx.x, bh = blockIdx.y;
    int b = bh >> 3, h = bh & 7;
    int d = threadIdx.x;
    long long base = (long long)b * NPAD * TD + (long long)m * LPER * TD + h * 64 + d;
    float sq = 0.f, sk = 0.f;
    #pragma unroll 4
    for (int r = 0; r < LPER; r++) {
        long long i = base + (long long)r * TD;
        sq += loadDual(qkvd, qkvPlane, i);
        sk += loadDual(qkvd, qkvPlane, i + 512);
    }
    long long idx = ((long long)bh * NLM + m) * DH + d;
    storeDual1(qld, plane, idx, sq * (1.f / LPER));
    storeDual1(kld, plane, idx, sk * (1.f / LPER));
}

__global__ void softmax256(const float* __restrict__ in, float* __restrict__ out32,
                           bf16* __restrict__ dual, long long plane, long long nrows) {
    long long row = (long long)blockIdx.x * 8 + (threadIdx.x >> 5);
    if (row >= nrows) return;
    int lane = threadIdx.x & 31;
    const float4* pi = (const float4*)(in + row * 256);
    float4 v0 = pi[lane];
    float4 v1 = pi[lane + 32];
    float m = fmaxf(fmaxf(fmaxf(v0.x, v0.y), fmaxf(v0.z, v0.w)),
                    fmaxf(fmaxf(v1.x, v1.y), fmaxf(v1.z, v1.w)));
    #pragma unroll
    for (int o = 16; o; o >>= 1) m = fmaxf(m, __shfl_xor_sync(0xffffffffu, m, o));
    v0.x = __expf(v0.x - m); v0.y = __expf(v0.y - m);
    v0.z = __expf(v0.z - m); v0.w = __expf(v0.w - m);
    v1.x = __expf(v1.x - m); v1.y = __expf(v1.y - m);
    v1.z = __expf(v1.z - m); v1.w = __expf(v1.w - m);
    float s = v0.x + v0.y + v0.z + v0.w + v1.x + v1.y + v1.z + v1.w;
    #pragma unroll
    for (int o = 16; o; o >>= 1) s += __shfl_xor_sync(0xffffffffu, s, o);
    float inv = 1.f / s;
    v0.x *= inv; v0.y *= inv; v0.z *= inv; v0.w *= inv;
    v1.x *= inv; v1.y *= inv; v1.z *= inv; v1.w *= inv;
    if (out32) {
        ((float4*)(out32 + row * 256))[lane] = v0;
        ((float4*)(out32 + row * 256))[lane + 32] = v1;
    }
    long long b0 = row * 256 + lane * 4;
    storeDual2(dual, plane, b0, v0.x, v0.y);
    storeDual2(dual, plane, b0 + 2, v0.z, v0.w);
    storeDual2(dual, plane, b0 + 128, v1.x, v1.y);
    storeDual2(dual, plane, b0 + 130, v1.z, v1.w);
}

__global__ void reset_kernel() {
    if (threadIdx.x == 0) { g_maxrow = 0; g_maxcol = 0; }
}

__global__ void a2stats_kernel(const float* __restrict__ a2) {
    __shared__ float sh[8];
    int bh = blockIdx.x;
    const float* a = a2 + (long long)bh * MM;
    int j = threadIdx.x;
    float cs = 0.f, rs = 0.f;
    for (int i = 0; i < NLM; i++) cs += a[(long long)i * NLM + j];
    const float* row = a + (long long)j * NLM;
    for (int i = 0; i < NLM; i++) rs += row[i];
    float cmax = blockReduceMax(cs, sh);
    float rmax = blockReduceMax(rs, sh);
    if (threadIdx.x == 0) {
        atomicMax(&g_maxcol, __float_as_int(cmax));
        atomicMax(&g_maxrow, __float_as_int(rmax));
    }
}

__global__ void z0_kernel(const float* __restrict__ a2, bf16* __restrict__ zp, long long plane) {
    __shared__ float tile[32][33];
    int bh = blockIdx.z;
    const float* a = a2 + (long long)bh * MM;
    long long zbase = (long long)bh * MM;
    float inv = 1.f / (__int_as_float(g_maxrow) * __int_as_float(g_maxcol));
    int i0 = blockIdx.y * 32, j0 = blockIdx.x * 32;
    for (int r = threadIdx.y; r < 32; r += 8)
        tile[r][threadIdx.x] = a[(long long)(i0 + r) * NLM + j0 + threadIdx.x];
    __syncthreads();
    for (int r = threadIdx.y; r < 32; r += 8)
        storeDual1(zp, plane, zbase + (long long)(j0 + r) * NLM + i0 + threadIdx.x,
                   tile[threadIdx.x][r] * inv);
}

__global__ void conv_kernel(const bf16* __restrict__ qkvd, long long qkvPlane,
                            const float* __restrict__ w, float* __restrict__ outh) {
    int bh = blockIdx.y;
    int b = bh >> 3, h = bh & 7;
    int iBase = blockIdx.x * 64;
    __shared__ float sv[96][64];
    __shared__ float sw[CONVK];
    long long vbase = (long long)b * NPAD * TD + 1024 + h * 64;
    int tid = threadIdx.x;
    for (int idx = tid; idx < 96 * 64; idx += 256) {
        int r = idx >> 6, d = idx & 63;
        int gi = iBase - 16 + r;
        sv[r][d] = (gi >= 0 && gi < NPAD)
                   ? loadDual(qkvd, qkvPlane, vbase + (long long)gi * TD + d) : 0.f;
    }
    if (tid < CONVK) sw[tid] = w[h * CONVK + tid];
    __syncthreads();
    float* out = outh + (long long)bh * NPAD * DH + (long long)iBase * DH;
    for (int idx = tid; idx < 64 * 64; idx += 256) {
        int r = idx >> 6, d = idx & 63;
        float s = 0.f;
        #pragma unroll
        for (int t = 0; t < CONVK; t++) s += sw[t] * sv[r + t][d];
        out[r * 64 + d] = s;
    }
}

__global__ void final_kernel(const float* __restrict__ h, const float* __restrict__ gam,
                             const float* __restrict__ bet, const float* __restrict__ w2,
                             const float* __restrict__ b2, float* __restrict__ out) {
    __shared__ float sh[8];
    int b = blockIdx.x;
    const float* x = h + ((long long)b * NPAD + PADN) * DM;
    float s = 0.f, s2 = 0.f;
    for (int i = threadIdx.x; i < DM; i += 256) { float v = x[i]; s += v; s2 += v * v; }
    s = blockReduceSum(s, sh);
    s2 = blockReduceSum(s2, sh);
    float mean = s / DM;
    float var = s2 / DM - mean * mean;
    float inv = rsqrtf(var + 1e-5f);
    float p0 = 0.f, p1 = 0.f;
    for (int i = threadIdx.x; i < DM; i += 256) {
        float hn = (x[i] - mean) * inv * gam[i] + bet[i];
        p0 += hn * w2[2 * i];
        p1 += hn * w2[2 * i + 1];
    }
    p0 = blockReduceSum(p0, sh);
    p1 = blockReduceSum(p1, sh);
    if (threadIdx.x == 0) {
        float l0 = p0 + b2[0], l1 = p1 + b2[1];
        float mx = fmaxf(l0, l1);
        float e0 = expf(l0 - mx), e1 = expf(l1 - mx);
        float si = 1.f / (e0 + e1);
        out[b * 2 + 0] = l0;
        out[b * 2 + 1] = l1;
        out[4 + b * 2 + 0] = e0 * si;
        out[4 + b * 2 + 1] = e1 * si;
        out[8 + b] = (l1 > l0) ? 1.f : 0.f;
    }
}

// ---------------- host side ----------------
static void launch_gemm(int bn, const bf16* A, const bf16* B,
                        long long aPlane, long long bPlane,
                        float* C, bf16* D, long long dPlane, bf16* D2, long long d2Plane,
                        int M, int N, int K, int lda, int ldb, int ldc,
                        long long aO, long long aI, int aC,
                        long long bO, long long bI, int bC,
                        long long cS, int batches, float alpha,
                        const float* bias, int relu, int accum, int transB,
                        int splitK = 1, long long partStride = 0,
                        float diagVal = 0.f, float diag2 = 0.f) {
    dim3 grid(N / bn, (M + BM - 1) / BM, batches * splitK);
    if (bn == 128)
        gemm_tc<128, 2, 4><<<grid, 256>>>(A, B, aPlane, bPlane, C, D, dPlane, D2, d2Plane,
                                          M, K, lda, ldb, ldc, aO, aI, aC, bO, bI, bC,
                                          cS, alpha, bias, relu, accum, transB,
                                          splitK, partStride, diagVal, diag2);
    else
        gemm_tc<64, 4, 2><<<grid, 256>>>(A, B, aPlane, bPlane, C, D, dPlane, D2, d2Plane,
                                         M, K, lda, ldb, ldc, aO, aI, aC, bO, bI, bC,
                                         cS, alpha, bias, relu, accum, transB,
                                         splitK, partStride, diagVal, diag2);
}

#define SYMF(p, s) do { void* _t; cudaGetSymbolAddress(&_t, s); p = (float*)_t; } while (0)
#define SYMB(p, s) do { void* _t; cudaGetSymbolAddress(&_t, s); p = (bf16*)_t; } while (0)

extern "C" void kernel_launch(void* const* d_in, const int* in_sizes, int n_in,
                              void* d_out, int out_size) {
    const float* feats = (const float*)d_in[0];
    const float* fc1_w = (const float*)d_in[1];
    const float* fc1_b = (const float*)d_in[2];
    const float* cls   = (const float*)d_in[3];
    const float* lng[2]   = {(const float*)d_in[4],  (const float*)d_in[10]};
    const float* lnb[2]   = {(const float*)d_in[5],  (const float*)d_in[11]};
    const float* qkvw[2]  = {(const float*)d_in[6],  (const float*)d_in[12]};
    const float* outw[2]  = {(const float*)d_in[7],  (const float*)d_in[13]};
    const float* outb[2]  = {(const float*)d_in[8],  (const float*)d_in[14]};
    const float* convw[2] = {(const float*)d_in[9],  (const float*)d_in[15]};
    const float* nfg  = (const float*)d_in[16];
    const float* nfb  = (const float*)d_in[17];
    const float* fc2w = (const float*)d_in[18];
    const float* fc2b = (const float*)d_in[19];

    float *h, *a2, *outh, *po, *pm, *ps;
    SYMF(h, g_h); SYMF(a2, g_a2); SYMF(outh, g_outh);
    SYMF(po, g_po); SYMF(pm, g_pm); SYMF(ps, g_ps);
    bf16 *featsd, *w1d, *qkvwd, *outwd, *xlnd, *qkvd, *qld, *kld, *a2d;
    bf16 *zpd, *p2d, *t1d, *t2d, *t3d, *a3vd, *u1d, *u2d, *wd, *catd;
    SYMB(featsd, g_featsd); SYMB(w1d, g_w1d); SYMB(qkvwd, g_qkvwd); SYMB(outwd, g_outwd);
    SYMB(xlnd, g_xlnd); SYMB(qkvd, g_qkvd); SYMB(qld, g_qld); SYMB(kld, g_kld);
    SYMB(a2d, g_a2d);
    SYMB(zpd, g_zpd); SYMB(p2d, g_p2d); SYMB(t1d, g_t1d); SYMB(t2d, g_t2d); SYMB(t3d, g_t3d);
    SYMB(a3vd, g_a3vd); SYMB(u1d, g_u1d); SYMB(u2d, g_u2d); SYMB(wd, g_wd); SYMB(catd, g_catd);

    const long long featsPlane = (long long)BATCH * NTOK * DIN;
    const long long xlnPlane   = (long long)BATCH * NPAD * DM;
    const long long qkvPlane   = (long long)BATCH * NPAD * TD;
    const long long qlPlane    = (long long)BHN * NLM * DH;
    const long long a2Plane    = (long long)BHN * MM;
    const long long zpPlane    = 32LL * MM;
    const long long p16Plane   = 16LL * MM;
    const long long t3Plane    = 6LL * 16 * MM;
    const long long avPlane    = (long long)BHN * NLM * DH;
    const long long catPlane   = (long long)BATCH * NPAD * DM;

    cudaFuncSetAttribute(flash_kernel<0>, cudaFuncAttributeMaxDynamicSharedMemorySize, FA_SMEM_BYTES);
    cudaFuncSetAttribute(flash_kernel<1>, cudaFuncAttributeMaxDynamicSharedMemorySize, FA_SMEM_BYTES);

    tobf16_kernel<<<(unsigned)((featsPlane + 255) / 256), 256>>>(feats, featsd, featsPlane, featsPlane);
    tobf16_kernel<<<(DIN * DM + 255) / 256, 256>>>(fc1_w, w1d, DIN * DM, DIN * DM);
    for (int l = 0; l < 2; l++) {
        tobf16_kernel<<<(DM * TD + 255) / 256, 256>>>(qkvw[l], qkvwd + (long long)l * 2 * DM * TD,
                                                      DM * TD, DM * TD);
        tobf16_kernel<<<(DM * DM + 255) / 256, 256>>>(outw[l], outwd + (long long)l * 2 * DM * DM,
                                                      DM * DM, DM * DM);
    }

    init_h_kernel<<<dim3(PADN + 1, BATCH), 256>>>(cls, h);

    // fc1 + relu
    launch_gemm(128, featsd, w1d, featsPlane, DIN * DM,
                h + (long long)(PADN + 1) * DM, nullptr, 0, nullptr, 0,
                NTOK, DM, DIN, DIN, DM, DM,
                (long long)NTOK * DIN, 0, 1, 0, 0, 1,
                (long long)NPAD * DM, BATCH, 1.f, fc1_b, 1, 0, 0);

    for (int l = 0; l < 2; l++) {
        layernorm_kernel<<<BATCH * NPAD, 256>>>(h, xlnd, xlnPlane, lng[l], lnb[l]);

        // qkv = xln @ qkvw  (dual output only)
        launch_gemm(128, xlnd, qkvwd + (long long)l * 2 * DM * TD, xlnPlane, DM * TD,
                    nullptr, qkvd, qkvPlane, nullptr, 0,
                    NPAD, TD, DM, DM, TD, TD,
                    (long long)NPAD * DM, 0, 1, 0, 0, 1,
                    (long long)NPAD * TD, BATCH, 1.f, nullptr, 0, 0, 0);

        landmark_kernel<<<dim3(NLM, BHN), 64>>>(qkvd, qkvPlane, qld, kld, qlPlane);

        // a2 = softmax(0.125 * q_l @ k_l^T)
        launch_gemm(128, qld, kld, qlPlane, qlPlane,
                    a2, nullptr, 0, nullptr, 0,
                    NLM, NLM, DH, DH, DH, NLM,
                    (long long)NLM * DH, 0, 1, (long long)NLM * DH, 0, 1,
                    MM, BHN, 0.125f, nullptr, 0, 0, 1);
        softmax256<<<(BHN * NLM) / 8, 256>>>(a2, a2, a2d, a2Plane, (long long)BHN * NLM);

        // F1: a3v = softmax(0.125 q_l K^T) V
        flash_kernel<0><<<dim3(NLM / 128, NSPLIT, BHN), 256, FA_SMEM_BYTES>>>(
            qld, qlPlane, DH, 0, (long long)NLM * DH, BHN,
            qkvd + DM, qkvPlane, TD, (long long)NPAD * TD, 64, NH,
            qkvd + 2 * DM, qkvPlane, TD, (long long)NPAD * TD, 64, NH,
            NPAD / NSPLIT, po, pm, ps, nullptr, nullptr, 0);
        fa_combine<<<(unsigned)((long long)BHN * NLM * DH / 256), 256>>>(po, pm, ps, a3vd, avPlane);

        // ---- pinv(a2): p-only Newton chain storing t3 factors ----
        reset_kernel<<<1, 32>>>();
        a2stats_kernel<<<BHN, 256>>>(a2);
        z0_kernel<<<dim3(8, 8, BHN), dim3(32, 8)>>>(a2, zpd, zpPlane);
        // p0 = a2 @ z0 ; t1 = 7I - p0
        bf16* pA = zpd + 16 * MM;  long long pAplane = zpPlane;
        bf16* pB = p2d;            long long pBplane = p16Plane;
        launch_gemm(64, a2d, zpd, a2Plane, zpPlane,
                    nullptr, pA, pAplane, t1d, p16Plane,
                    NLM, NLM, NLM, NLM, NLM, NLM,
                    MM, 0, 1, MM, 0, 1, MM, BHN, 1.f, nullptr, 0, 0, 0,
                    1, 0, 0.f, 7.f);
        for (int it = 0; it < 6; it++) {
            // t2 = 15I - p@t1
            launch_gemm(64, pA, t1d, pAplane, p16Plane,
                        nullptr, nullptr, 0, t2d, p16Plane,
                        NLM, NLM, NLM, NLM, NLM, NLM,
                        MM, 0, 1, MM, 0, 1, MM, BHN, 1.f, nullptr, 0, 0, 0,
                        1, 0, 0.f, 15.f);
            // t3_it = 13I - p@t2
            launch_gemm(64, pA, t2d, pAplane, p16Plane,
                        nullptr, nullptr, 0, t3d + (long long)it * 16 * MM, t3Plane,
                        NLM, NLM, NLM, NLM, NLM, NLM,
                        MM, 0, 1, MM, 0, 1, MM, BHN, 1.f, nullptr, 0, 0, 0,
                        1, 0, 0.f, 13.f);
            if (it < 5) {
                // p' = 0.25 p @ t3_it ; t1 = 7I - p'
                launch_gemm(64, pA, t3d + (long long)it * 16 * MM, pAplane, t3Plane,
                            nullptr, pB, pBplane, t1d, p16Plane,
                            NLM, NLM, NLM, NLM, NLM, NLM,
                            MM, 0, 1, MM, 0, 1, MM, BHN, 0.25f, nullptr, 0, 0, 0,
                            1, 0, 0.f, 7.f);
                bf16* tp = pA; pA = pB; pB = tp;
                long long tpl = pAplane; pAplane = pBplane; pBplane = tpl;
            }
        }
        // u chain: u = t3_0 @ (t3_1 @ ... (t3_5 @ a3v))
        bf16* uc = a3vd;  long long ucPlane = avPlane;
        bf16* un = u1d;
        for (int it = 5; it >= 0; it--) {
            launch_gemm(64, t3d + (long long)it * 16 * MM, uc, t3Plane, ucPlane,
                        nullptr, un, avPlane, nullptr, 0,
                        NLM, DH, NLM, NLM, DH, DH,
                        MM, 0, 1, (long long)NLM * DH, 0, 1,
                        (long long)NLM * DH, BHN, 1.f, nullptr, 0, 0, 0);
            bf16* prev = uc;
            uc = un; ucPlane = avPlane;
            un = (prev == a3vd) ? u2d : prev;   // alternate u1d/u2d after first step
        }
        // w = 0.25^6 * z0 @ u
        launch_gemm(64, zpd, uc, zpPlane, avPlane,
                    nullptr, wd, avPlane, nullptr, 0,
                    NLM, DH, NLM, NLM, DH, DH,
                    MM, 0, 1, (long long)NLM * DH, 0, 1,
                    (long long)NLM * DH, BHN, 1.f / 4096.f, nullptr, 0, 0, 0);

        // conv writes outh (pure conv result)
        conv_kernel<<<dim3(NPAD / 64, BHN), 256>>>(qkvd, qkvPlane, convw[l], outh);

        // F2: catd = merge( softmax(0.125 Q k_l^T) @ w + conv )
        flash_kernel<1><<<dim3(NPAD / 128, 1, BHN), 256, FA_SMEM_BYTES>>>(
            qkvd, qkvPlane, TD, (long long)NPAD * TD, 64, NH,
            kld, qlPlane, DH, 0, (long long)NLM * DH, BHN,
            wd, avPlane, DH, 0, (long long)NLM * DH, BHN,
            NLM, nullptr, nullptr, nullptr, outh, catd, catPlane);

        // output projection, accumulate into residual stream (fp32)
        launch_gemm(128, catd + (long long)PADN * DM, outwd + (long long)l * 2 * DM * DM,
                    catPlane, DM * DM,
                    h + (long long)PADN * DM, nullptr, 0, nullptr, 0,
                    NP1, DM, DM, DM, DM, DM,
                    (long long)NPAD * DM, 0, 1, 0, 0, 1,
                    (long long)NPAD * DM, BATCH, 1.f, outb[l], 0, 1, 0);
    }

    final_kernel<<<BATCH, 256>>>(h, nfg, nfb, fc2w, fc2b, (float*)d_out);
}

// round 12
// speedup vs baseline: 1.3085x; 1.2443x over previous
#include <cuda_runtime.h>
#include <cuda_bf16.h>
#include <cstdint>
#include <math.h>

#define BATCH 2
#define NTOK  8000
#define NP1   8001
#define PADN  191
#define NPAD  8192
#define DM    512
#define DIN   1024
#define NH    8
#define DH    64
#define NLM   256
#define LPER  32
#define BHN   16
#define CONVK 33
#define TD    1536
#define BM    128
#define BK    32
#define NSPLIT 8
#define MM    ((long long)NLM * NLM)

typedef __nv_bfloat16 bf16;

// ---------------- fp32 scratch ----------------
__device__ float g_h   [(long long)BATCH*NPAD*DM];
__device__ float g_a2  [(long long)BHN*NLM*NLM];
__device__ float g_outh[(long long)BHN*NPAD*DH];
__device__ float g_po  [(long long)NSPLIT*BHN*NLM*DH];
__device__ float g_pm  [(long long)NSPLIT*BHN*NLM];
__device__ float g_ps  [(long long)NSPLIT*BHN*NLM];
__device__ int   g_maxrow;
__device__ int   g_maxcol;

// ---------------- dual-bf16 scratch (hi plane + lo plane) ----------------
__device__ __align__(16) bf16 g_featsd[2LL*BATCH*NTOK*DIN];
__device__ __align__(16) bf16 g_w1d   [2LL*DIN*DM];
__device__ __align__(16) bf16 g_qkvwd [2LL*2*DM*TD];
__device__ __align__(16) bf16 g_outwd [2LL*2*DM*DM];
__device__ __align__(16) bf16 g_xlnd  [2LL*BATCH*NPAD*DM];
__device__ __align__(16) bf16 g_qkvd  [2LL*BATCH*NPAD*TD];
__device__ __align__(16) bf16 g_qld   [2LL*BHN*NLM*DH];
__device__ __align__(16) bf16 g_kld   [2LL*BHN*NLM*DH];
__device__ __align__(16) bf16 g_a2d   [2LL*BHN*NLM*NLM];
__device__ __align__(16) bf16 g_zpd   [2LL*32*NLM*NLM];   // z0 in batches 0-15, p in 16-31
__device__ __align__(16) bf16 g_p2d   [2LL*16*NLM*NLM];
__device__ __align__(16) bf16 g_t1d   [2LL*16*NLM*NLM];
__device__ __align__(16) bf16 g_t2d   [2LL*16*NLM*NLM];
__device__ __align__(16) bf16 g_t3d   [2LL*6*16*NLM*NLM];
__device__ __align__(16) bf16 g_a3vd  [2LL*BHN*NLM*DH];
__device__ __align__(16) bf16 g_u1d   [2LL*BHN*NLM*DH];
__device__ __align__(16) bf16 g_u2d   [2LL*BHN*NLM*DH];
__device__ __align__(16) bf16 g_wd    [2LL*BHN*NLM*DH];
__device__ __align__(16) bf16 g_catd  [2LL*BATCH*NPAD*DM];

// ---------------- helpers ----------------
__device__ __forceinline__ void storeDual2(bf16* d, long long plane, long long idx,
                                           float x, float y) {
    __nv_bfloat162 h = __floats2bfloat162_rn(x, y);
    *reinterpret_cast<__nv_bfloat162*>(d + idx) = h;
    __nv_bfloat162 l = __floats2bfloat162_rn(x - __bfloat162float(h.x),
                                             y - __bfloat162float(h.y));
    *reinterpret_cast<__nv_bfloat162*>(d + plane + idx) = l;
}
__device__ __forceinline__ void storeDual1(bf16* d, long long plane, long long idx, float x) {
    bf16 h = __float2bfloat16(x);
    d[idx] = h;
    d[plane + idx] = __float2bfloat16(x - __bfloat162float(h));
}
__device__ __forceinline__ float loadDual(const bf16* d, long long plane, long long idx) {
    return __bfloat162float(d[idx]) + __bfloat162float(d[plane + idx]);
}
__device__ __forceinline__ void cpa16(uint32_t dst, const void* src, bool pred) {
    int sz = pred ? 16 : 0;
    asm volatile("cp.async.cg.shared.global [%0], [%1], 16, %2;\n"
                 :: "r"(dst), "l"(src), "r"(sz));
}
__device__ __forceinline__ void cpa_commit() {
    asm volatile("cp.async.commit_group;\n");
}

__device__ __forceinline__ float blockReduceSum(float v, float* sh) {
    #pragma unroll
    for (int o = 16; o; o >>= 1) v += __shfl_xor_sync(0xffffffffu, v, o);
    int w = threadIdx.x >> 5;
    if ((threadIdx.x & 31) == 0) sh[w] = v;
    __syncthreads();
    if (threadIdx.x < 8) {
        v = sh[threadIdx.x];
        #pragma unroll
        for (int o = 4; o; o >>= 1) v += __shfl_xor_sync(0xffu, v, o);
        if (threadIdx.x == 0) sh[0] = v;
    }
    __syncthreads();
    float r = sh[0];
    __syncthreads();
    return r;
}
__device__ __forceinline__ float blockReduceMax(float v, float* sh) {
    #pragma unroll
    for (int o = 16; o; o >>= 1) v = fmaxf(v, __shfl_xor_sync(0xffffffffu, v, o));
    int w = threadIdx.x >> 5;
    if ((threadIdx.x & 31) == 0) sh[w] = v;
    __syncthreads();
    if (threadIdx.x < 8) {
        v = sh[threadIdx.x];
        #pragma unroll
        for (int o = 4; o; o >>= 1) v = fmaxf(v, __shfl_xor_sync(0xffu, v, o));
        if (threadIdx.x == 0) sh[0] = v;
    }
    __syncthreads();
    float r = sh[0];
    __syncthreads();
    return r;
}

__device__ __forceinline__ void mma16816(float* c, const unsigned* a, const unsigned* b) {
    asm volatile(
        "mma.sync.aligned.m16n8k16.row.col.f32.bf16.bf16.f32 "
        "{%0,%1,%2,%3},{%4,%5,%6,%7},{%8,%9},{%0,%1,%2,%3};\n"
        : "+f"(c[0]), "+f"(c[1]), "+f"(c[2]), "+f"(c[3])
        : "r"(a[0]), "r"(a[1]), "r"(a[2]), "r"(a[3]), "r"(b[0]), "r"(b[1]));
}
__device__ __forceinline__ void ldsm4(unsigned& r0, unsigned& r1, unsigned& r2, unsigned& r3,
                                      uint32_t addr) {
    asm volatile("ldmatrix.sync.aligned.m8n8.x4.shared.b16 {%0,%1,%2,%3}, [%4];\n"
                 : "=r"(r0), "=r"(r1), "=r"(r2), "=r"(r3) : "r"(addr));
}
__device__ __forceinline__ void ldsm4t(unsigned& r0, unsigned& r1, unsigned& r2, unsigned& r3,
                                       uint32_t addr) {
    asm volatile("ldmatrix.sync.aligned.m8n8.x4.trans.shared.b16 {%0,%1,%2,%3}, [%4];\n"
                 : "=r"(r0), "=r"(r1), "=r"(r2), "=r"(r3) : "r"(addr));
}

// ---------------- A-hi x B-dual tensor-core GEMM (2 MMAs/tile, cp.async pipelined) ----------------
template<int BN, int WROWS, int WCOLS>
__global__ void __launch_bounds__(256) gemm_tc(
    const bf16* __restrict__ A, const bf16* __restrict__ B,
    long long aPlane, long long bPlane,
    float* __restrict__ C, bf16* __restrict__ D, long long dPlane,
    bf16* __restrict__ D2, long long d2Plane,
    int Mn, int Kn, int lda, int ldb, int ldc,
    long long aOuter, long long aInner, int aCnt,
    long long bOuter, long long bInner, int bCnt,
    long long cStride, float alpha, const float* __restrict__ bias,
    int relu, int accum, int transB, int splitK, long long partStride,
    float diagVal, float diag2)
{
    constexpr int WM = BM / WROWS;
    constexpr int WN = BN / WCOLS;
    constexpr int MT = WM / 16;
    constexpr int NT = WN / 8;
    constexpr int NTP = WN / 16;
    constexpr int KST = BN + 8;
    constexpr int ASTG = BM * 40;          // A: hi plane only
    constexpr int BSTG = 2 * BN * 40;

    int bz = blockIdx.z;
    int batch = bz / splitK;
    int split = bz - batch * splitK;
    const bf16* Ab = A + (long long)(batch / aCnt) * aOuter + (long long)(batch % aCnt) * aInner;
    const bf16* Bb = B + (long long)(batch / bCnt) * bOuter + (long long)(batch % bCnt) * bInner;
    long long cOff = (long long)batch * cStride + (long long)split * partStride;
    int kPer = Kn / splitK;
    int kStart = split * kPer;

    __shared__ __align__(16) bf16 sA[2 * ASTG];
    __shared__ __align__(16) bf16 sB[2 * BSTG];
    uint32_t saBase = (uint32_t)__cvta_generic_to_shared(sA);
    uint32_t sbBase = (uint32_t)__cvta_generic_to_shared(sB);

    int tid = threadIdx.x;
    int lane = tid & 31;
    int wid = tid >> 5;
    int lt = lane & 7;
    int lg = lane >> 3;
    int warpM = (wid / WCOLS) * WM;
    int warpN = (wid % WCOLS) * WN;
    int rowBase = blockIdx.y * BM;
    int colBase = blockIdx.x * BN;

    float acc[MT][NT][4];
    #pragma unroll
    for (int i = 0; i < MT; i++)
        #pragma unroll
        for (int j = 0; j < NT; j++)
            #pragma unroll
            for (int e = 0; e < 4; e++) acc[i][j][e] = 0.f;

    auto issue = [&](int k0, int stg) {
        uint32_t sa = saBase + stg * ASTG * 2;
        uint32_t sb = sbBase + stg * BSTG * 2;
        #pragma unroll
        for (int j = 0; j < 2; j++) {          // A hi only: 512 cpa / 256 thr
            int id = tid + j * 256;
            int row = id >> 2, seg = id & 3;
            int gr = rowBase + row;
            bool ok = gr < Mn;
            const bf16* src = Ab + (long long)(ok ? gr : 0) * lda + kStart + k0 + seg * 8;
            cpa16(sa + ((row * 40 + seg * 8) << 1), src, ok);
        }
        if (transB) {
            #pragma unroll
            for (int p = 0; p < 2; p++)
                #pragma unroll
                for (int j = 0; j < BN / 64; j++) {
                    int id = tid + j * 256;
                    int row = id >> 2, seg = id & 3;
                    const bf16* src = Bb + p * bPlane +
                                      (long long)(colBase + row) * ldb + kStart + k0 + seg * 8;
                    cpa16(sb + (((p * BN + row) * 40 + seg * 8) << 1), src, true);
                }
        } else {
            #pragma unroll
            for (int p = 0; p < 2; p++)
                #pragma unroll
                for (int j = 0; j < BN / 64; j++) {
                    int id = tid + j * 256;
                    int k = id / (BN / 8), seg = id % (BN / 8);
                    const bf16* src = Bb + p * bPlane +
                                      (long long)(kStart + k0 + k) * ldb + colBase + seg * 8;
                    cpa16(sb + (((p * 32 + k) * KST + seg * 8) << 1), src, true);
                }
        }
        cpa_commit();
    };

    int nIter = kPer / BK;
    issue(0, 0);

    for (int it = 0; it < nIter; it++) {
        int cur = it & 1;
        asm volatile("cp.async.wait_group 0;\n");
        __syncthreads();
        if (it + 1 < nIter) issue((it + 1) * BK, cur ^ 1);

        uint32_t saS = saBase + cur * ASTG * 2;
        uint32_t sbS = sbBase + cur * BSTG * 2;

        #pragma unroll
        for (int ks = 0; ks < 2; ks++) {
            int k8 = ks * 16;
            unsigned bh[NTP][4], bl[NTP][4];
            #pragma unroll
            for (int ntp = 0; ntp < NTP; ntp++) {
                if (transB) {
                    int n = warpN + ntp * 16 + lt + ((lg >> 1) << 3);
                    int kk = k8 + ((lg & 1) << 3);
                    ldsm4(bh[ntp][0], bh[ntp][1], bh[ntp][2], bh[ntp][3],
                          sbS + (((0 * BN + n) * 40 + kk) << 1));
                    ldsm4(bl[ntp][0], bl[ntp][1], bl[ntp][2], bl[ntp][3],
                          sbS + (((1 * BN + n) * 40 + kk) << 1));
                } else {
                    int k = k8 + lt + ((lg & 1) << 3);
                    int n = warpN + ntp * 16 + ((lg >> 1) << 3);
                    ldsm4t(bh[ntp][0], bh[ntp][1], bh[ntp][2], bh[ntp][3],
                           sbS + (((0 * 32 + k) * KST + n) << 1));
                    ldsm4t(bl[ntp][0], bl[ntp][1], bl[ntp][2], bl[ntp][3],
                           sbS + (((1 * 32 + k) * KST + n) << 1));
                }
            }
            #pragma unroll
            for (int mt = 0; mt < MT; mt++) {
                unsigned ah[4];
                int m = warpM + mt * 16 + lt + ((lg & 1) << 3);
                int kk = k8 + ((lg >> 1) << 3);
                ldsm4(ah[0], ah[1], ah[2], ah[3],
                      saS + ((m * 40 + kk) << 1));
                #pragma unroll
                for (int nt = 0; nt < NT; nt++) {
                    const unsigned* ph = &bh[nt >> 1][(nt & 1) * 2];
                    const unsigned* pl = &bl[nt >> 1][(nt & 1) * 2];
                    mma16816(acc[mt][nt], ah, ph);
                    mma16816(acc[mt][nt], ah, pl);
                }
            }
        }
        __syncthreads();
    }

    int q = lane & 3, g = lane >> 2;
    float* Cb = C ? C + cOff : nullptr;
    bf16* Db = D ? D + cOff : nullptr;
    bf16* D2b = D2 ? D2 + cOff : nullptr;
    #pragma unroll
    for (int mt = 0; mt < MT; mt++) {
        #pragma unroll
        for (int nt = 0; nt < NT; nt++) {
            int r0 = rowBase + warpM + mt * 16 + g;
            int c0 = colBase + warpN + nt * 8 + q * 2;
            #pragma unroll
            for (int half = 0; half < 2; half++) {
                int gr = r0 + half * 8;
                if (gr >= Mn) continue;
                float v0 = alpha * acc[mt][nt][half * 2 + 0];
                float v1 = alpha * acc[mt][nt][half * 2 + 1];
                if (gr == c0)     v0 += diagVal;
                if (gr == c0 + 1) v1 += diagVal;
                long long off = (long long)gr * ldc + c0;
                if (Cb) {
                    float w0 = v0, w1 = v1;
                    if (bias) { w0 += bias[c0]; w1 += bias[c0 + 1]; }
                    if (relu) { w0 = fmaxf(w0, 0.f); w1 = fmaxf(w1, 0.f); }
                    if (accum) { w0 += Cb[off]; w1 += Cb[off + 1]; }
                    *reinterpret_cast<float2*>(Cb + off) = make_float2(w0, w1);
                }
                if (Db) storeDual2(Db, dPlane, off, v0, v1);
                if (D2b) {
                    float u0 = ((gr == c0)     ? diag2 : 0.f) - v0;
                    float u1 = ((gr == c0 + 1) ? diag2 : 0.f) - v1;
                    storeDual2(D2b, d2Plane, off, u0, u1);
                }
            }
        }
    }
}

// ---------------- fused flash attention (Q-hi, K/V-dual, 2 MMAs/tile) ----------------
// smem elems: Q hi 128*72=9216 | K 2stg x 2pl x 64*72 | V same
#define FA_Q    0
#define FA_K    9216
#define FA_V    27648
#define FA_SMEM_BYTES (46080 * 2)

template<int MODE>
__global__ void __launch_bounds__(256) flash_kernel(
    const bf16* __restrict__ Qa, long long qPlane, int qStride,
    long long qOuter, long long qInner, int qCnt,
    const bf16* __restrict__ Ka, long long kPlane, int kStride,
    long long kOuter, long long kInner, int kCnt,
    const bf16* __restrict__ Va, long long vPlane, int vStride,
    long long vOuter, long long vInner, int vCnt,
    int keysPerSplit,
    float* __restrict__ PO, float* __restrict__ PM, float* __restrict__ PS,
    const float* __restrict__ CONV, bf16* __restrict__ CATD, long long catPlane)
{
    extern __shared__ __align__(16) bf16 fsm[];
    uint32_t smBase = (uint32_t)__cvta_generic_to_shared(fsm);
    int tid = threadIdx.x, lane = tid & 31, wid = tid >> 5;
    int lt = lane & 7, lg = lane >> 3, g = lane >> 2, q = lane & 3;
    int bh = blockIdx.z, split = blockIdx.y;
    int rowBase = blockIdx.x * 128;
    const bf16* Q = Qa + (long long)(bh / qCnt) * qOuter + (long long)(bh % qCnt) * qInner;
    const bf16* K = Ka + (long long)(bh / kCnt) * kOuter + (long long)(bh % kCnt) * kInner
                       + (long long)split * keysPerSplit * kStride;
    const bf16* V = Va + (long long)(bh / vCnt) * vOuter + (long long)(bh % vCnt) * vInner
                       + (long long)split * keysPerSplit * vStride;

    // stage Q hi plane only: 128 rows x 64 cols
    #pragma unroll
    for (int j = 0; j < 4; j++) {
        int c = tid + j * 256;
        int row = c >> 3, seg = c & 7;
        cpa16(smBase + ((row * 72 + seg * 8) << 1),
              Q + (long long)(rowBase + row) * qStride + seg * 8, true);
    }
    auto issueKV = [&](int t, int stg) {
        int key0 = t * 64;
        #pragma unroll
        for (int j = 0; j < 2; j++) {
            int c = tid + j * 256;
            int p = c >> 8, rem = c & 255;
            int row = rem >> 2, seg = rem & 3;
            cpa16(smBase + ((FA_K + stg * 9216 + (p * 64 + row) * 72 + seg * 16) << 1),
                  K + (long long)p * kPlane + (long long)(key0 + row) * kStride + seg * 16, true);
            cpa16(smBase + ((FA_K + stg * 9216 + (p * 64 + row) * 72 + seg * 16 + 8) << 1),
                  K + (long long)p * kPlane + (long long)(key0 + row) * kStride + seg * 16 + 8, true);
            cpa16(smBase + ((FA_V + stg * 9216 + (p * 64 + row) * 72 + seg * 16) << 1),
                  V + (long long)p * vPlane + (long long)(key0 + row) * vStride + seg * 16, true);
            cpa16(smBase + ((FA_V + stg * 9216 + (p * 64 + row) * 72 + seg * 16 + 8) << 1),
                  V + (long long)p * vPlane + (long long)(key0 + row) * vStride + seg * 16 + 8, true);
        }
        cpa_commit();
    };
    issueKV(0, 0);

    int warpRow = wid * 16;
    unsigned qh[4][4];
    float o[8][4];
    #pragma unroll
    for (int i = 0; i < 8; i++)
        #pragma unroll
        for (int e = 0; e < 4; e++) o[i][e] = 0.f;
    float m0 = -1e30f, m1 = -1e30f, l0 = 0.f, l1 = 0.f;

    int nTiles = keysPerSplit / 64;
    for (int t = 0; t < nTiles; t++) {
        int stg = t & 1;
        bool more = (t + 1 < nTiles);
        if (more) {
            issueKV(t + 1, stg ^ 1);
            asm volatile("cp.async.wait_group 1;\n");
        } else {
            asm volatile("cp.async.wait_group 0;\n");
        }
        __syncthreads();
        if (t == 0) {
            #pragma unroll
            for (int kc = 0; kc < 4; kc++) {
                int row = warpRow + lt + ((lg & 1) << 3);
                int kk = kc * 16 + ((lg >> 1) << 3);
                ldsm4(qh[kc][0], qh[kc][1], qh[kc][2], qh[kc][3],
                      smBase + ((row * 72 + kk) << 1));
            }
        }
        uint32_t skS = smBase + ((FA_K + stg * 9216) << 1);
        uint32_t svS = smBase + ((FA_V + stg * 9216) << 1);

        float sc[8][4];
        #pragma unroll
        for (int i = 0; i < 8; i++)
            #pragma unroll
            for (int e = 0; e < 4; e++) sc[i][e] = 0.f;
        #pragma unroll
        for (int kc = 0; kc < 4; kc++) {
            unsigned kh[4][4], kl[4][4];
            #pragma unroll
            for (int ntp = 0; ntp < 4; ntp++) {
                int n = ntp * 16 + lt + ((lg >> 1) << 3);
                int kk = kc * 16 + ((lg & 1) << 3);
                ldsm4(kh[ntp][0], kh[ntp][1], kh[ntp][2], kh[ntp][3],
                      skS + (((0 * 64 + n) * 72 + kk) << 1));
                ldsm4(kl[ntp][0], kl[ntp][1], kl[ntp][2], kl[ntp][3],
                      skS + (((64 + n) * 72 + kk) << 1));
            }
            #pragma unroll
            for (int nt = 0; nt < 8; nt++) {
                const unsigned* bhf = &kh[nt >> 1][(nt & 1) * 2];
                const unsigned* blf = &kl[nt >> 1][(nt & 1) * 2];
                mma16816(sc[nt], qh[kc], bhf);
                mma16816(sc[nt], qh[kc], blf);
            }
        }
        float mt0 = -1e30f, mt1 = -1e30f;
        #pragma unroll
        for (int nt = 0; nt < 8; nt++) {
            #pragma unroll
            for (int e = 0; e < 4; e++) sc[nt][e] *= 0.125f;
            mt0 = fmaxf(mt0, fmaxf(sc[nt][0], sc[nt][1]));
            mt1 = fmaxf(mt1, fmaxf(sc[nt][2], sc[nt][3]));
        }
        mt0 = fmaxf(mt0, __shfl_xor_sync(0xffffffffu, mt0, 1));
        mt0 = fmaxf(mt0, __shfl_xor_sync(0xffffffffu, mt0, 2));
        mt1 = fmaxf(mt1, __shfl_xor_sync(0xffffffffu, mt1, 1));
        mt1 = fmaxf(mt1, __shfl_xor_sync(0xffffffffu, mt1, 2));
        float mn0 = fmaxf(m0, mt0), mn1 = fmaxf(m1, mt1);
        float f0 = __expf(m0 - mn0), f1 = __expf(m1 - mn1);
        m0 = mn0; m1 = mn1;
        float rs0 = 0.f, rs1 = 0.f;
        #pragma unroll
        for (int nt = 0; nt < 8; nt++) {
            sc[nt][0] = __expf(sc[nt][0] - mn0);
            sc[nt][1] = __expf(sc[nt][1] - mn0);
            sc[nt][2] = __expf(sc[nt][2] - mn1);
            sc[nt][3] = __expf(sc[nt][3] - mn1);
            rs0 += sc[nt][0] + sc[nt][1];
            rs1 += sc[nt][2] + sc[nt][3];
        }
        rs0 += __shfl_xor_sync(0xffffffffu, rs0, 1);
        rs0 += __shfl_xor_sync(0xffffffffu, rs0, 2);
        rs1 += __shfl_xor_sync(0xffffffffu, rs1, 1);
        rs1 += __shfl_xor_sync(0xffffffffu, rs1, 2);
        l0 = l0 * f0 + rs0;
        l1 = l1 * f1 + rs1;
        #pragma unroll
        for (int nt = 0; nt < 8; nt++) {
            o[nt][0] *= f0; o[nt][1] *= f0;
            o[nt][2] *= f1; o[nt][3] *= f1;
        }
        #pragma unroll
        for (int kc = 0; kc < 4; kc++) {
            unsigned ph[4];
            __nv_bfloat162 t0 = __floats2bfloat162_rn(sc[2 * kc][0], sc[2 * kc][1]);
            __nv_bfloat162 t1 = __floats2bfloat162_rn(sc[2 * kc][2], sc[2 * kc][3]);
            __nv_bfloat162 t2 = __floats2bfloat162_rn(sc[2 * kc + 1][0], sc[2 * kc + 1][1]);
            __nv_bfloat162 t3 = __floats2bfloat162_rn(sc[2 * kc + 1][2], sc[2 * kc + 1][3]);
            ph[0] = *reinterpret_cast<unsigned*>(&t0);
            ph[1] = *reinterpret_cast<unsigned*>(&t1);
            ph[2] = *reinterpret_cast<unsigned*>(&t2);
            ph[3] = *reinterpret_cast<unsigned*>(&t3);
            unsigned vh[4][4], vl[4][4];
            #pragma unroll
            for (int ntp = 0; ntp < 4; ntp++) {
                int k = kc * 16 + lt + ((lg & 1) << 3);
                int n = ntp * 16 + ((lg >> 1) << 3);
                ldsm4t(vh[ntp][0], vh[ntp][1], vh[ntp][2], vh[ntp][3],
                       svS + (((0 * 64 + k) * 72 + n) << 1));
                ldsm4t(vl[ntp][0], vl[ntp][1], vl[ntp][2], vl[ntp][3],
                       svS + (((64 + k) * 72 + n) << 1));
            }
            #pragma unroll
            for (int nt = 0; nt < 8; nt++) {
                const unsigned* bhf = &vh[nt >> 1][(nt & 1) * 2];
                const unsigned* blf = &vl[nt >> 1][(nt & 1) * 2];
                mma16816(o[nt], ph, bhf);
                mma16816(o[nt], ph, blf);
            }
        }
        __syncthreads();
    }

    int row0 = rowBase + warpRow + g;
    int row1 = row0 + 8;
    if (MODE == 1) {
        float i0 = 1.f / l0, i1 = 1.f / l1;
        int b = bh >> 3, hh = bh & 7;
        const float* Cv = CONV + (long long)bh * NPAD * 64;
        #pragma unroll
        for (int nt = 0; nt < 8; nt++) {
            int col = nt * 8 + q * 2;
            float2 c0 = *(const float2*)&Cv[(long long)row0 * 64 + col];
            float2 c1 = *(const float2*)&Cv[(long long)row1 * 64 + col];
            long long i0d = ((long long)b * NPAD + row0) * DM + hh * 64 + col;
            long long i1d = ((long long)b * NPAD + row1) * DM + hh * 64 + col;
            storeDual2(CATD, catPlane, i0d, o[nt][0] * i0 + c0.x, o[nt][1] * i0 + c0.y);
            storeDual2(CATD, catPlane, i1d, o[nt][2] * i1 + c1.x, o[nt][3] * i1 + c1.y);
        }
    } else {
        long long pb = ((long long)split * BHN + bh) * NLM;
        #pragma unroll
        for (int nt = 0; nt < 8; nt++) {
            int col = nt * 8 + q * 2;
            *(float2*)&PO[(pb + row0) * 64 + col] = make_float2(o[nt][0], o[nt][1]);
            *(float2*)&PO[(pb + row1) * 64 + col] = make_float2(o[nt][2], o[nt][3]);
        }
        if (q == 0) {
            PM[pb + row0] = m0; PM[pb + row1] = m1;
            PS[pb + row0] = l0; PS[pb + row1] = l1;
        }
    }
}

__global__ void fa_combine(const float* __restrict__ po, const float* __restrict__ pm,
                           const float* __restrict__ ps, bf16* __restrict__ outd,
                           long long plane) {
    long long idx = (long long)blockIdx.x * 256 + threadIdx.x;
    int d = (int)(idx & 63);
    long long rid = idx >> 6;
    const long long RS = (long long)BHN * NLM;
    float M = -1e30f;
    #pragma unroll
    for (int s = 0; s < NSPLIT; s++) M = fmaxf(M, pm[s * RS + rid]);
    float S = 0.f, val = 0.f;
    #pragma unroll
    for (int s = 0; s < NSPLIT; s++) {
        float e = __expf(pm[s * RS + rid] - M);
        S += ps[s * RS + rid] * e;
        val += po[(s * RS + rid) * 64 + d] * e;
    }
    storeDual1(outd, plane, rid * 64 + d, val / S);
}

// ---------------- misc kernels ----------------
__global__ void tobf16_kernel(const float* __restrict__ x, bf16* __restrict__ d,
                              long long n, long long plane) {
    long long i = (long long)blockIdx.x * 256 + threadIdx.x;
    if (i >= n) return;
    storeDual1(d, plane, i, x[i]);
}

__global__ void init_h_kernel(const float* __restrict__ cls, float* __restrict__ h) {
    int r = blockIdx.x, b = blockIdx.y;
    float* o = h + ((long long)b * NPAD + r) * DM;
    for (int i = threadIdx.x; i < DM; i += 256) o[i] = (r == PADN) ? cls[i] : 0.f;
}

__global__ void layernorm_kernel(const float* __restrict__ in, bf16* __restrict__ xd,
                                 long long plane,
                                 const float* __restrict__ gam, const float* __restrict__ bet) {
    __shared__ float sh[8];
    long long row = blockIdx.x;
    int r = (int)(row % NPAD);
    int tid = threadIdx.x;
    long long idx = row * DM + tid * 2;
    if (r < PADN) {
        storeDual2(xd, plane, idx, 0.f, 0.f);
        return;
    }
    const float2* x = (const float2*)(in + row * DM);
    float2 v = x[tid];
    float s = v.x + v.y;
    float s2 = v.x * v.x + v.y * v.y;
    s = blockReduceSum(s, sh);
    s2 = blockReduceSum(s2, sh);
    float mean = s / DM;
    float var = s2 / DM - mean * mean;
    float inv = rsqrtf(var + 1e-5f);
    float2 gv = ((const float2*)gam)[tid];
    float2 bv = ((const float2*)bet)[tid];
    storeDual2(xd, plane, idx,
               (v.x - mean) * inv * gv.x + bv.x,
               (v.y - mean) * inv * gv.y + bv.y);
}

__global__ void landmark_kernel(const bf16* __restrict__ qkvd, long long qkvPlane,
                                bf16* __restrict__ qld, bf16* __restrict__ kld,
                                long long plane) {
    int m = blockIdx.x, bh = blockIdx.y;
    int b = bh >> 3, h = bh & 7;
    int d = threadIdx.x;
    long long base = (long long)b * NPAD * TD + (long long)m * LPER * TD + h * 64 + d;
    float sq = 0.f, sk = 0.f;
    #pragma unroll 4
    for (int r = 0; r < LPER; r++) {
        long long i = base + (long long)r * TD;
        sq += loadDual(qkvd, qkvPlane, i);
        sk += loadDual(qkvd, qkvPlane, i + 512);
    }
    long long idx = ((long long)bh * NLM + m) * DH + d;
    storeDual1(qld, plane, idx, sq * (1.f / LPER));
    storeDual1(kld, plane, idx, sk * (1.f / LPER));
}

__global__ void softmax256(const float* __restrict__ in, float* __restrict__ out32,
                           bf16* __restrict__ dual, long long plane, long long nrows) {
    long long row = (long long)blockIdx.x * 8 + (threadIdx.x >> 5);
    if (row >= nrows) return;
    int lane = threadIdx.x & 31;
    const float4* pi = (const float4*)(in + row * 256);
    float4 v0 = pi[lane];
    float4 v1 = pi[lane + 32];
    float m = fmaxf(fmaxf(fmaxf(v0.x, v0.y), fmaxf(v0.z, v0.w)),
                    fmaxf(fmaxf(v1.x, v1.y), fmaxf(v1.z, v1.w)));
    #pragma unroll
    for (int o = 16; o; o >>= 1) m = fmaxf(m, __shfl_xor_sync(0xffffffffu, m, o));
    v0.x = __expf(v0.x - m); v0.y = __expf(v0.y - m);
    v0.z = __expf(v0.z - m); v0.w = __expf(v0.w - m);
    v1.x = __expf(v1.x - m); v1.y = __expf(v1.y - m);
    v1.z = __expf(v1.z - m); v1.w = __expf(v1.w - m);
    float s = v0.x + v0.y + v0.z + v0.w + v1.x + v1.y + v1.z + v1.w;
    #pragma unroll
    for (int o = 16; o; o >>= 1) s += __shfl_xor_sync(0xffffffffu, s, o);
    float inv = 1.f / s;
    v0.x *= inv; v0.y *= inv; v0.z *= inv; v0.w *= inv;
    v1.x *= inv; v1.y *= inv; v1.z *= inv; v1.w *= inv;
    if (out32) {
        ((float4*)(out32 + row * 256))[lane] = v0;
        ((float4*)(out32 + row * 256))[lane + 32] = v1;
    }
    long long b0 = row * 256 + lane * 4;
    storeDual2(dual, plane, b0, v0.x, v0.y);
    storeDual2(dual, plane, b0 + 2, v0.z, v0.w);
    storeDual2(dual, plane, b0 + 128, v1.x, v1.y);
    storeDual2(dual, plane, b0 + 130, v1.z, v1.w);
}

__global__ void reset_kernel() {
    if (threadIdx.x == 0) { g_maxrow = 0; g_maxcol = 0; }
}

__global__ void a2stats_kernel(const float* __restrict__ a2) {
    __shared__ float sh[8];
    int bh = blockIdx.x;
    const float* a = a2 + (long long)bh * MM;
    int j = threadIdx.x;
    float cs = 0.f, rs = 0.f;
    for (int i = 0; i < NLM; i++) cs += a[(long long)i * NLM + j];
    const float* row = a + (long long)j * NLM;
    for (int i = 0; i < NLM; i++) rs += row[i];
    float cmax = blockReduceMax(cs, sh);
    float rmax = blockReduceMax(rs, sh);
    if (threadIdx.x == 0) {
        atomicMax(&g_maxcol, __float_as_int(cmax));
        atomicMax(&g_maxrow, __float_as_int(rmax));
    }
}

__global__ void z0_kernel(const float* __restrict__ a2, bf16* __restrict__ zp, long long plane) {
    __shared__ float tile[32][33];
    int bh = blockIdx.z;
    const float* a = a2 + (long long)bh * MM;
    long long zbase = (long long)bh * MM;
    float inv = 1.f / (__int_as_float(g_maxrow) * __int_as_float(g_maxcol));
    int i0 = blockIdx.y * 32, j0 = blockIdx.x * 32;
    for (int r = threadIdx.y; r < 32; r += 8)
        tile[r][threadIdx.x] = a[(long long)(i0 + r) * NLM + j0 + threadIdx.x];
    __syncthreads();
    for (int r = threadIdx.y; r < 32; r += 8)
        storeDual1(zp, plane, zbase + (long long)(j0 + r) * NLM + i0 + threadIdx.x,
                   tile[threadIdx.x][r] * inv);
}

__global__ void conv_kernel(const bf16* __restrict__ qkvd, long long qkvPlane,
                            const float* __restrict__ w, float* __restrict__ outh) {
    int bh = blockIdx.y;
    int b = bh >> 3, h = bh & 7;
    int iBase = blockIdx.x * 64;
    __shared__ float sv[96][64];
    __shared__ float sw[CONVK];
    long long vbase = (long long)b * NPAD * TD + 1024 + h * 64;
    int tid = threadIdx.x;
    for (int idx = tid; idx < 96 * 64; idx += 256) {
        int r = idx >> 6, d = idx & 63;
        int gi = iBase - 16 + r;
        sv[r][d] = (gi >= 0 && gi < NPAD)
                   ? loadDual(qkvd, qkvPlane, vbase + (long long)gi * TD + d) : 0.f;
    }
    if (tid < CONVK) sw[tid] = w[h * CONVK + tid];
    __syncthreads();
    float* out = outh + (long long)bh * NPAD * DH + (long long)iBase * DH;
    for (int idx = tid; idx < 64 * 64; idx += 256) {
        int r = idx >> 6, d = idx & 63;
        float s = 0.f;
        #pragma unroll
        for (int t = 0; t < CONVK; t++) s += sw[t] * sv[r + t][d];
        out[r * 64 + d] = s;
    }
}

__global__ void final_kernel(const float* __restrict__ h, const float* __restrict__ gam,
                             const float* __restrict__ bet, const float* __restrict__ w2,
                             const float* __restrict__ b2, float* __restrict__ out) {
    __shared__ float sh[8];
    int b = blockIdx.x;
    const float* x = h + ((long long)b * NPAD + PADN) * DM;
    float s = 0.f, s2 = 0.f;
    for (int i = threadIdx.x; i < DM; i += 256) { float v = x[i]; s += v; s2 += v * v; }
    s = blockReduceSum(s, sh);
    s2 = blockReduceSum(s2, sh);
    float mean = s / DM;
    float var = s2 / DM - mean * mean;
    float inv = rsqrtf(var + 1e-5f);
    float p0 = 0.f, p1 = 0.f;
    for (int i = threadIdx.x; i < DM; i += 256) {
        float hn = (x[i] - mean) * inv * gam[i] + bet[i];
        p0 += hn * w2[2 * i];
        p1 += hn * w2[2 * i + 1];
    }
    p0 = blockReduceSum(p0, sh);
    p1 = blockReduceSum(p1, sh);
    if (threadIdx.x == 0) {
        float l0 = p0 + b2[0], l1 = p1 + b2[1];
        float mx = fmaxf(l0, l1);
        float e0 = expf(l0 - mx), e1 = expf(l1 - mx);
        float si = 1.f / (e0 + e1);
        out[b * 2 + 0] = l0;
        out[b * 2 + 1] = l1;
        out[4 + b * 2 + 0] = e0 * si;
        out[4 + b * 2 + 1] = e1 * si;
        out[8 + b] = (l1 > l0) ? 1.f : 0.f;
    }
}

// ---------------- host side ----------------
static void launch_gemm(int bn, const bf16* A, const bf16* B,
                        long long aPlane, long long bPlane,
                        float* C, bf16* D, long long dPlane, bf16* D2, long long d2Plane,
                        int M, int N, int K, int lda, int ldb, int ldc,
                        long long aO, long long aI, int aC,
                        long long bO, long long bI, int bC,
                        long long cS, int batches, float alpha,
                        const float* bias, int relu, int accum, int transB,
                        int splitK = 1, long long partStride = 0,
                        float diagVal = 0.f, float diag2 = 0.f) {
    dim3 grid(N / bn, (M + BM - 1) / BM, batches * splitK);
    if (bn == 128)
        gemm_tc<128, 2, 4><<<grid, 256>>>(A, B, aPlane, bPlane, C, D, dPlane, D2, d2Plane,
                                          M, K, lda, ldb, ldc, aO, aI, aC, bO, bI, bC,
                                          cS, alpha, bias, relu, accum, transB,
                                          splitK, partStride, diagVal, diag2);
    else
        gemm_tc<64, 4, 2><<<grid, 256>>>(A, B, aPlane, bPlane, C, D, dPlane, D2, d2Plane,
                                         M, K, lda, ldb, ldc, aO, aI, aC, bO, bI, bC,
                                         cS, alpha, bias, relu, accum, transB,
                                         splitK, partStride, diagVal, diag2);
}

#define SYMF(p, s) do { void* _t; cudaGetSymbolAddress(&_t, s); p = (float*)_t; } while (0)
#define SYMB(p, s) do { void* _t; cudaGetSymbolAddress(&_t, s); p = (bf16*)_t; } while (0)

extern "C" void kernel_launch(void* const* d_in, const int* in_sizes, int n_in,
                              void* d_out, int out_size) {
    const float* feats = (const float*)d_in[0];
    const float* fc1_w = (const float*)d_in[1];
    const float* fc1_b = (const float*)d_in[2];
    const float* cls   = (const float*)d_in[3];
    const float* lng[2]   = {(const float*)d_in[4],  (const float*)d_in[10]};
    const float* lnb[2]   = {(const float*)d_in[5],  (const float*)d_in[11]};
    const float* qkvw[2]  = {(const float*)d_in[6],  (const float*)d_in[12]};
    const float* outw[2]  = {(const float*)d_in[7],  (const float*)d_in[13]};
    const float* outb[2]  = {(const float*)d_in[8],  (const float*)d_in[14]};
    const float* convw[2] = {(const float*)d_in[9],  (const float*)d_in[15]};
    const float* nfg  = (const float*)d_in[16];
    const float* nfb  = (const float*)d_in[17];
    const float* fc2w = (const float*)d_in[18];
    const float* fc2b = (const float*)d_in[19];

    float *h, *a2, *outh, *po, *pm, *ps;
    SYMF(h, g_h); SYMF(a2, g_a2); SYMF(outh, g_outh);
    SYMF(po, g_po); SYMF(pm, g_pm); SYMF(ps, g_ps);
    bf16 *featsd, *w1d, *qkvwd, *outwd, *xlnd, *qkvd, *qld, *kld, *a2d;
    bf16 *zpd, *p2d, *t1d, *t2d, *t3d, *a3vd, *u1d, *u2d, *wd, *catd;
    SYMB(featsd, g_featsd); SYMB(w1d, g_w1d); SYMB(qkvwd, g_qkvwd); SYMB(outwd, g_outwd);
    SYMB(xlnd, g_xlnd); SYMB(qkvd, g_qkvd); SYMB(qld, g_qld); SYMB(kld, g_kld);
    SYMB(a2d, g_a2d);
    SYMB(zpd, g_zpd); SYMB(p2d, g_p2d); SYMB(t1d, g_t1d); SYMB(t2d, g_t2d); SYMB(t3d, g_t3d);
    SYMB(a3vd, g_a3vd); SYMB(u1d, g_u1d); SYMB(u2d, g_u2d); SYMB(wd, g_wd); SYMB(catd, g_catd);

    const long long featsPlane = (long long)BATCH * NTOK * DIN;
    const long long xlnPlane   = (long long)BATCH * NPAD * DM;
    const long long qkvPlane   = (long long)BATCH * NPAD * TD;
    const long long qlPlane    = (long long)BHN * NLM * DH;
    const long long a2Plane    = (long long)BHN * MM;
    const long long zpPlane    = 32LL * MM;
    const long long p16Plane   = 16LL * MM;
    const long long t3Plane    = 6LL * 16 * MM;
    const long long avPlane    = (long long)BHN * NLM * DH;
    const long long catPlane   = (long long)BATCH * NPAD * DM;

    cudaFuncSetAttribute(flash_kernel<0>, cudaFuncAttributeMaxDynamicSharedMemorySize, FA_SMEM_BYTES);
    cudaFuncSetAttribute(flash_kernel<1>, cudaFuncAttributeMaxDynamicSharedMemorySize, FA_SMEM_BYTES);

    tobf16_kernel<<<(unsigned)((featsPlane + 255) / 256), 256>>>(feats, featsd, featsPlane, featsPlane);
    tobf16_kernel<<<(DIN * DM + 255) / 256, 256>>>(fc1_w, w1d, DIN * DM, DIN * DM);
    for (int l = 0; l < 2; l++) {
        tobf16_kernel<<<(DM * TD + 255) / 256, 256>>>(qkvw[l], qkvwd + (long long)l * 2 * DM * TD,
                                                      DM * TD, DM * TD);
        tobf16_kernel<<<(DM * DM + 255) / 256, 256>>>(outw[l], outwd + (long long)l * 2 * DM * DM,
                                                      DM * DM, DM * DM);
    }

    init_h_kernel<<<dim3(PADN + 1, BATCH), 256>>>(cls, h);

    // fc1 + relu
    launch_gemm(128, featsd, w1d, featsPlane, DIN * DM,
                h + (long long)(PADN + 1) * DM, nullptr, 0, nullptr, 0,
                NTOK, DM, DIN, DIN, DM, DM,
                (long long)NTOK * DIN, 0, 1, 0, 0, 1,
                (long long)NPAD * DM, BATCH, 1.f, fc1_b, 1, 0, 0);

    for (int l = 0; l < 2; l++) {
        layernorm_kernel<<<BATCH * NPAD, 256>>>(h, xlnd, xlnPlane, lng[l], lnb[l]);

        // qkv = xln @ qkvw  (dual output only)
        launch_gemm(128, xlnd, qkvwd + (long long)l * 2 * DM * TD, xlnPlane, DM * TD,
                    nullptr, qkvd, qkvPlane, nullptr, 0,
                    NPAD, TD, DM, DM, TD, TD,
                    (long long)NPAD * DM, 0, 1, 0, 0, 1,
                    (long long)NPAD * TD, BATCH, 1.f, nullptr, 0, 0, 0);

        landmark_kernel<<<dim3(NLM, BHN), 64>>>(qkvd, qkvPlane, qld, kld, qlPlane);

        // a2 = softmax(0.125 * q_l @ k_l^T)
        launch_gemm(128, qld, kld, qlPlane, qlPlane,
                    a2, nullptr, 0, nullptr, 0,
                    NLM, NLM, DH, DH, DH, NLM,
                    (long long)NLM * DH, 0, 1, (long long)NLM * DH, 0, 1,
                    MM, BHN, 0.125f, nullptr, 0, 0, 1);
        softmax256<<<(BHN * NLM) / 8, 256>>>(a2, a2, a2d, a2Plane, (long long)BHN * NLM);

        // F1: a3v = softmax(0.125 q_l K^T) V
        flash_kernel<0><<<dim3(NLM / 128, NSPLIT, BHN), 256, FA_SMEM_BYTES>>>(
            qld, qlPlane, DH, 0, (long long)NLM * DH, BHN,
            qkvd + DM, qkvPlane, TD, (long long)NPAD * TD, 64, NH,
            qkvd + 2 * DM, qkvPlane, TD, (long long)NPAD * TD, 64, NH,
            NPAD / NSPLIT, po, pm, ps, nullptr, nullptr, 0);
        fa_combine<<<(unsigned)((long long)BHN * NLM * DH / 256), 256>>>(po, pm, ps, a3vd, avPlane);

        // ---- pinv(a2): p-only Newton chain storing t3 factors ----
        reset_kernel<<<1, 32>>>();
        a2stats_kernel<<<BHN, 256>>>(a2);
        z0_kernel<<<dim3(8, 8, BHN), dim3(32, 8)>>>(a2, zpd, zpPlane);
        bf16* pA = zpd + 16 * MM;  long long pAplane = zpPlane;
        bf16* pB = p2d;            long long pBplane = p16Plane;
        launch_gemm(64, a2d, zpd, a2Plane, zpPlane,
                    nullptr, pA, pAplane, t1d, p16Plane,
                    NLM, NLM, NLM, NLM, NLM, NLM,
                    MM, 0, 1, MM, 0, 1, MM, BHN, 1.f, nullptr, 0, 0, 0,
                    1, 0, 0.f, 7.f);
        for (int it = 0; it < 6; it++) {
            launch_gemm(64, pA, t1d, pAplane, p16Plane,
                        nullptr, nullptr, 0, t2d, p16Plane,
                        NLM, NLM, NLM, NLM, NLM, NLM,
                        MM, 0, 1, MM, 0, 1, MM, BHN, 1.f, nullptr, 0, 0, 0,
                        1, 0, 0.f, 15.f);
            launch_gemm(64, pA, t2d, pAplane, p16Plane,
                        nullptr, nullptr, 0, t3d + (long long)it * 16 * MM, t3Plane,
                        NLM, NLM, NLM, NLM, NLM, NLM,
                        MM, 0, 1, MM, 0, 1, MM, BHN, 1.f, nullptr, 0, 0, 0,
                        1, 0, 0.f, 13.f);
            if (it < 5) {
                launch_gemm(64, pA, t3d + (long long)it * 16 * MM, pAplane, t3Plane,
                            nullptr, pB, pBplane, t1d, p16Plane,
                            NLM, NLM, NLM, NLM, NLM, NLM,
                            MM, 0, 1, MM, 0, 1, MM, BHN, 0.25f, nullptr, 0, 0, 0,
                            1, 0, 0.f, 7.f);
                bf16* tp = pA; pA = pB; pB = tp;
                long long tpl = pAplane; pAplane = pBplane; pBplane = tpl;
            }
        }
        // u chain: u = t3_0 @ (t3_1 @ ... (t3_5 @ a3v))
        bf16* uc = a3vd;  long long ucPlane = avPlane;
        bf16* un = u1d;
        for (int it = 5; it >= 0; it--) {
            launch_gemm(64, t3d + (long long)it * 16 * MM, uc, t3Plane, ucPlane,
                        nullptr, un, avPlane, nullptr, 0,
                        NLM, DH, NLM, NLM, DH, DH,
                        MM, 0, 1, (long long)NLM * DH, 0, 1,
                        (long long)NLM * DH, BHN, 1.f, nullptr, 0, 0, 0);
            bf16* prev = uc;
            uc = un; ucPlane = avPlane;
            un = (prev == a3vd) ? u2d : prev;
        }
        // w = 0.25^6 * z0 @ u
        launch_gemm(64, zpd, uc, zpPlane, avPlane,
                    nullptr, wd, avPlane, nullptr, 0,
                    NLM, DH, NLM, NLM, DH, DH,
                    MM, 0, 1, (long long)NLM * DH, 0, 1,
                    (long long)NLM * DH, BHN, 1.f / 4096.f, nullptr, 0, 0, 0);

        // conv writes outh (pure conv result)
        conv_kernel<<<dim3(NPAD / 64, BHN), 256>>>(qkvd, qkvPlane, convw[l], outh);

        // F2: catd = merge( softmax(0.125 Q k_l^T) @ w + conv )
        flash_kernel<1><<<dim3(NPAD / 128, 1, BHN), 256, FA_SMEM_BYTES>>>(
            qkvd, qkvPlane, TD, (long long)NPAD * TD, 64, NH,
            kld, qlPlane, DH, 0, (long long)NLM * DH, BHN,
            wd, avPlane, DH, 0, (long long)NLM * DH, BHN,
            NLM, nullptr, nullptr, nullptr, outh, catd, catPlane);

        // output projection, accumulate into residual stream (fp32)
        launch_gemm(128, catd + (long long)PADN * DM, outwd + (long long)l * 2 * DM * DM,
                    catPlane, DM * DM,
                    h + (long long)PADN * DM, nullptr, 0, nullptr, 0,
                    NP1, DM, DM, DM, DM, DM,
                    (long long)NPAD * DM, 0, 1, 0, 0, 1,
                    (long long)NPAD * DM, BATCH, 1.f, outb[l], 0, 1, 0);
    }

    final_kernel<<<BATCH, 256>>>(h, nfg, nfb, fc2w, fc2b, (float*)d_out);
}

// round 14
// speedup vs baseline: 1.4095x; 1.0772x over previous
#include <cuda_runtime.h>
#include <cuda_bf16.h>
#include <cstdint>
#include <math.h>

#define BATCH 2
#define NTOK  8000
#define NP1   8001
#define PADN  191
#define NPAD  8192
#define DM    512
#define DIN   1024
#define NH    8
#define DH    64
#define NLM   256
#define LPER  32
#define BHN   16
#define CONVK 33
#define TD    1536
#define BM    128
#define BK    32
#define NSPLIT 8
#define MM    ((long long)NLM * NLM)

typedef __nv_bfloat16 bf16;

// ---------------- fp32 scratch ----------------
__device__ float g_h   [(long long)BATCH*NPAD*DM];
__device__ float g_a2  [(long long)BHN*NLM*NLM];
__device__ float g_outh[(long long)BHN*NPAD*DH];
__device__ float g_po  [(long long)NSPLIT*BHN*NLM*DH];
__device__ float g_pm  [(long long)NSPLIT*BHN*NLM];
__device__ float g_ps  [(long long)NSPLIT*BHN*NLM];
__device__ int   g_maxrow;
__device__ int   g_maxcol;

// ---------------- dual-bf16 scratch (hi plane + lo plane) ----------------
__device__ __align__(16) bf16 g_featsd[1LL*BATCH*NTOK*DIN];        // hi only
__device__ __align__(16) bf16 g_w1d   [2LL*DIN*DM];
__device__ __align__(16) bf16 g_qkvwd [2LL*2*DM*TD];
__device__ __align__(16) bf16 g_outwd [2LL*2*DM*DM];
__device__ __align__(16) bf16 g_xlnd  [1LL*BATCH*NPAD*DM];         // hi only
__device__ __align__(16) bf16 g_qkvd  [2LL*BATCH*NPAD*TD];
__device__ __align__(16) bf16 g_qld   [1LL*BHN*NLM*DH];            // hi only
__device__ __align__(16) bf16 g_kld   [2LL*BHN*NLM*DH];
__device__ __align__(16) bf16 g_a2d   [2LL*BHN*NLM*NLM];
__device__ __align__(16) bf16 g_zpd   [2LL*32*NLM*NLM];   // z0 in batches 0-15, p in 16-31
__device__ __align__(16) bf16 g_p2d   [2LL*16*NLM*NLM];
__device__ __align__(16) bf16 g_t1d   [2LL*16*NLM*NLM];
__device__ __align__(16) bf16 g_t2d   [2LL*16*NLM*NLM];
__device__ __align__(16) bf16 g_t3d   [2LL*6*16*NLM*NLM];
__device__ __align__(16) bf16 g_a3vd  [2LL*BHN*NLM*DH];
__device__ __align__(16) bf16 g_u1d   [2LL*BHN*NLM*DH];
__device__ __align__(16) bf16 g_u2d   [2LL*BHN*NLM*DH];
__device__ __align__(16) bf16 g_wd    [2LL*BHN*NLM*DH];
__device__ __align__(16) bf16 g_catd  [1LL*BATCH*NPAD*DM];         // hi only

// ---------------- helpers ----------------
__device__ __forceinline__ void storeDual2(bf16* d, long long plane, long long idx,
                                           float x, float y) {
    __nv_bfloat162 h = __floats2bfloat162_rn(x, y);
    *reinterpret_cast<__nv_bfloat162*>(d + idx) = h;
    __nv_bfloat162 l = __floats2bfloat162_rn(x - __bfloat162float(h.x),
                                             y - __bfloat162float(h.y));
    *reinterpret_cast<__nv_bfloat162*>(d + plane + idx) = l;
}
__device__ __forceinline__ void storeHi2(bf16* d, long long idx, float x, float y) {
    __nv_bfloat162 h = __floats2bfloat162_rn(x, y);
    *reinterpret_cast<__nv_bfloat162*>(d + idx) = h;
}
__device__ __forceinline__ void storeDual1(bf16* d, long long plane, long long idx, float x) {
    bf16 h = __float2bfloat16(x);
    d[idx] = h;
    d[plane + idx] = __float2bfloat16(x - __bfloat162float(h));
}
__device__ __forceinline__ float loadDual(const bf16* d, long long plane, long long idx) {
    return __bfloat162float(d[idx]) + __bfloat162float(d[plane + idx]);
}
__device__ __forceinline__ void cpa16(uint32_t dst, const void* src, bool pred) {
    int sz = pred ? 16 : 0;
    asm volatile("cp.async.cg.shared.global [%0], [%1], 16, %2;\n"
                 :: "r"(dst), "l"(src), "r"(sz));
}
__device__ __forceinline__ void cpa_commit() {
    asm volatile("cp.async.commit_group;\n");
}

__device__ __forceinline__ float blockReduceSum(float v, float* sh) {
    #pragma unroll
    for (int o = 16; o; o >>= 1) v += __shfl_xor_sync(0xffffffffu, v, o);
    int w = threadIdx.x >> 5;
    if ((threadIdx.x & 31) == 0) sh[w] = v;
    __syncthreads();
    if (threadIdx.x < 8) {
        v = sh[threadIdx.x];
        #pragma unroll
        for (int o = 4; o; o >>= 1) v += __shfl_xor_sync(0xffu, v, o);
        if (threadIdx.x == 0) sh[0] = v;
    }
    __syncthreads();
    float r = sh[0];
    __syncthreads();
    return r;
}
__device__ __forceinline__ float blockReduceMax(float v, float* sh) {
    #pragma unroll
    for (int o = 16; o; o >>= 1) v = fmaxf(v, __shfl_xor_sync(0xffffffffu, v, o));
    int w = threadIdx.x >> 5;
    if ((threadIdx.x & 31) == 0) sh[w] = v;
    __syncthreads();
    if (threadIdx.x < 8) {
        v = sh[threadIdx.x];
        #pragma unroll
        for (int o = 4; o; o >>= 1) v = fmaxf(v, __shfl_xor_sync(0xffu, v, o));
        if (threadIdx.x == 0) sh[0] = v;
    }
    __syncthreads();
    float r = sh[0];
    __syncthreads();
    return r;
}

__device__ __forceinline__ void mma16816(float* c, const unsigned* a, const unsigned* b) {
    asm volatile(
        "mma.sync.aligned.m16n8k16.row.col.f32.bf16.bf16.f32 "
        "{%0,%1,%2,%3},{%4,%5,%6,%7},{%8,%9},{%0,%1,%2,%3};\n"
        : "+f"(c[0]), "+f"(c[1]), "+f"(c[2]), "+f"(c[3])
        : "r"(a[0]), "r"(a[1]), "r"(a[2]), "r"(a[3]), "r"(b[0]), "r"(b[1]));
}
__device__ __forceinline__ void ldsm4(unsigned& r0, unsigned& r1, unsigned& r2, unsigned& r3,
                                      uint32_t addr) {
    asm volatile("ldmatrix.sync.aligned.m8n8.x4.shared.b16 {%0,%1,%2,%3}, [%4];\n"
                 : "=r"(r0), "=r"(r1), "=r"(r2), "=r"(r3) : "r"(addr));
}
__device__ __forceinline__ void ldsm4t(unsigned& r0, unsigned& r1, unsigned& r2, unsigned& r3,
                                       uint32_t addr) {
    asm volatile("ldmatrix.sync.aligned.m8n8.x4.trans.shared.b16 {%0,%1,%2,%3}, [%4];\n"
                 : "=r"(r0), "=r"(r1), "=r"(r2), "=r"(r3) : "r"(addr));
}

// ---------------- A-hi x B-dual tensor-core GEMM (2 MMAs/tile, cp.async pipelined) ----------------
template<int BN, int WROWS, int WCOLS>
__global__ void __launch_bounds__(256) gemm_tc(
    const bf16* __restrict__ A, const bf16* __restrict__ B,
    long long aPlane, long long bPlane,
    float* __restrict__ C, bf16* __restrict__ D, long long dPlane,
    bf16* __restrict__ D2, long long d2Plane,
    int Mn, int Kn, int lda, int ldb, int ldc,
    long long aOuter, long long aInner, int aCnt,
    long long bOuter, long long bInner, int bCnt,
    long long cStride, float alpha, const float* __restrict__ bias,
    int relu, int accum, int transB, int splitK, long long partStride,
    float diagVal, float diag2)
{
    constexpr int WM = BM / WROWS;
    constexpr int WN = BN / WCOLS;
    constexpr int MT = WM / 16;
    constexpr int NT = WN / 8;
    constexpr int NTP = WN / 16;
    constexpr int KST = BN + 8;
    constexpr int ASTG = BM * 40;          // A: hi plane only
    constexpr int BSTG = 2 * BN * 40;

    int bz = blockIdx.z;
    int batch = bz / splitK;
    int split = bz - batch * splitK;
    const bf16* Ab = A + (long long)(batch / aCnt) * aOuter + (long long)(batch % aCnt) * aInner;
    const bf16* Bb = B + (long long)(batch / bCnt) * bOuter + (long long)(batch % bCnt) * bInner;
    long long cOff = (long long)batch * cStride + (long long)split * partStride;
    int kPer = Kn / splitK;
    int kStart = split * kPer;

    __shared__ __align__(16) bf16 sA[2 * ASTG];
    __shared__ __align__(16) bf16 sB[2 * BSTG];
    uint32_t saBase = (uint32_t)__cvta_generic_to_shared(sA);
    uint32_t sbBase = (uint32_t)__cvta_generic_to_shared(sB);

    int tid = threadIdx.x;
    int lane = tid & 31;
    int wid = tid >> 5;
    int lt = lane & 7;
    int lg = lane >> 3;
    int warpM = (wid / WCOLS) * WM;
    int warpN = (wid % WCOLS) * WN;
    int rowBase = blockIdx.y * BM;
    int colBase = blockIdx.x * BN;

    float acc[MT][NT][4];
    #pragma unroll
    for (int i = 0; i < MT; i++)
        #pragma unroll
        for (int j = 0; j < NT; j++)
            #pragma unroll
            for (int e = 0; e < 4; e++) acc[i][j][e] = 0.f;

    auto issue = [&](int k0, int stg) {
        uint32_t sa = saBase + stg * ASTG * 2;
        uint32_t sb = sbBase + stg * BSTG * 2;
        #pragma unroll
        for (int j = 0; j < 2; j++) {
            int id = tid + j * 256;
            int row = id >> 2, seg = id & 3;
            int gr = rowBase + row;
            bool ok = gr < Mn;
            const bf16* src = Ab + (long long)(ok ? gr : 0) * lda + kStart + k0 + seg * 8;
            cpa16(sa + ((row * 40 + seg * 8) << 1), src, ok);
        }
        if (transB) {
            #pragma unroll
            for (int p = 0; p < 2; p++)
                #pragma unroll
                for (int j = 0; j < BN / 64; j++) {
                    int id = tid + j * 256;
                    int row = id >> 2, seg = id & 3;
                    const bf16* src = Bb + p * bPlane +
                                      (long long)(colBase + row) * ldb + kStart + k0 + seg * 8;
                    cpa16(sb + (((p * BN + row) * 40 + seg * 8) << 1), src, true);
                }
        } else {
            #pragma unroll
            for (int p = 0; p < 2; p++)
                #pragma unroll
                for (int j = 0; j < BN / 64; j++) {
                    int id = tid + j * 256;
                    int k = id / (BN / 8), seg = id % (BN / 8);
                    const bf16* src = Bb + p * bPlane +
                                      (long long)(kStart + k0 + k) * ldb + colBase + seg * 8;
                    cpa16(sb + (((p * 32 + k) * KST + seg * 8) << 1), src, true);
                }
        }
        cpa_commit();
    };

    int nIter = kPer / BK;
    issue(0, 0);

    for (int it = 0; it < nIter; it++) {
        int cur = it & 1;
        asm volatile("cp.async.wait_group 0;\n");
        __syncthreads();
        if (it + 1 < nIter) issue((it + 1) * BK, cur ^ 1);

        uint32_t saS = saBase + cur * ASTG * 2;
        uint32_t sbS = sbBase + cur * BSTG * 2;

        #pragma unroll
        for (int ks = 0; ks < 2; ks++) {
            int k8 = ks * 16;
            unsigned bh[NTP][4], bl[NTP][4];
            #pragma unroll
            for (int ntp = 0; ntp < NTP; ntp++) {
                if (transB) {
                    int n = warpN + ntp * 16 + lt + ((lg >> 1) << 3);
                    int kk = k8 + ((lg & 1) << 3);
                    ldsm4(bh[ntp][0], bh[ntp][1], bh[ntp][2], bh[ntp][3],
                          sbS + (((0 * BN + n) * 40 + kk) << 1));
                    ldsm4(bl[ntp][0], bl[ntp][1], bl[ntp][2], bl[ntp][3],
                          sbS + (((1 * BN + n) * 40 + kk) << 1));
                } else {
                    int k = k8 + lt + ((lg & 1) << 3);
                    int n = warpN + ntp * 16 + ((lg >> 1) << 3);
                    ldsm4t(bh[ntp][0], bh[ntp][1], bh[ntp][2], bh[ntp][3],
                           sbS + (((0 * 32 + k) * KST + n) << 1));
                    ldsm4t(bl[ntp][0], bl[ntp][1], bl[ntp][2], bl[ntp][3],
                           sbS + (((1 * 32 + k) * KST + n) << 1));
                }
            }
            #pragma unroll
            for (int mt = 0; mt < MT; mt++) {
                unsigned ah[4];
                int m = warpM + mt * 16 + lt + ((lg & 1) << 3);
                int kk = k8 + ((lg >> 1) << 3);
                ldsm4(ah[0], ah[1], ah[2], ah[3],
                      saS + ((m * 40 + kk) << 1));
                #pragma unroll
                for (int nt = 0; nt < NT; nt++) {
                    const unsigned* ph = &bh[nt >> 1][(nt & 1) * 2];
                    const unsigned* pl = &bl[nt >> 1][(nt & 1) * 2];
                    mma16816(acc[mt][nt], ah, ph);
                    mma16816(acc[mt][nt], ah, pl);
                }
            }
        }
        __syncthreads();
    }

    int q = lane & 3, g = lane >> 2;
    float* Cb = C ? C + cOff : nullptr;
    bf16* Db = D ? D + cOff : nullptr;
    bf16* D2b = D2 ? D2 + cOff : nullptr;
    #pragma unroll
    for (int mt = 0; mt < MT; mt++) {
        #pragma unroll
        for (int nt = 0; nt < NT; nt++) {
            int r0 = rowBase + warpM + mt * 16 + g;
            int c0 = colBase + warpN + nt * 8 + q * 2;
            #pragma unroll
            for (int half = 0; half < 2; half++) {
                int gr = r0 + half * 8;
                if (gr >= Mn) continue;
                float v0 = alpha * acc[mt][nt][half * 2 + 0];
                float v1 = alpha * acc[mt][nt][half * 2 + 1];
                if (gr == c0)     v0 += diagVal;
                if (gr == c0 + 1) v1 += diagVal;
                long long off = (long long)gr * ldc + c0;
                if (Cb) {
                    float w0 = v0, w1 = v1;
                    if (bias) { w0 += bias[c0]; w1 += bias[c0 + 1]; }
                    if (relu) { w0 = fmaxf(w0, 0.f); w1 = fmaxf(w1, 0.f); }
                    if (accum) { w0 += Cb[off]; w1 += Cb[off + 1]; }
                    *reinterpret_cast<float2*>(Cb + off) = make_float2(w0, w1);
                }
                if (Db) storeDual2(Db, dPlane, off, v0, v1);
                if (D2b) {
                    float u0 = ((gr == c0)     ? diag2 : 0.f) - v0;
                    float u1 = ((gr == c0 + 1) ? diag2 : 0.f) - v1;
                    storeDual2(D2b, d2Plane, off, u0, u1);
                }
            }
        }
    }
}

// ---------------- fused flash attention (Q-hi, K/V-dual, 2 MMAs/tile) ----------------
#define FA_K    9216
#define FA_V    27648
#define FA_SMEM_BYTES (46080 * 2)

template<int MODE>
__global__ void __launch_bounds__(256) flash_kernel(
    const bf16* __restrict__ Qa, long long qPlane, int qStride,
    long long qOuter, long long qInner, int qCnt,
    const bf16* __restrict__ Ka, long long kPlane, int kStride,
    long long kOuter, long long kInner, int kCnt,
    const bf16* __restrict__ Va, long long vPlane, int vStride,
    long long vOuter, long long vInner, int vCnt,
    int keysPerSplit,
    float* __restrict__ PO, float* __restrict__ PM, float* __restrict__ PS,
    const float* __restrict__ CONV, bf16* __restrict__ CATD, long long catPlane)
{
    extern __shared__ __align__(16) bf16 fsm[];
    uint32_t smBase = (uint32_t)__cvta_generic_to_shared(fsm);
    int tid = threadIdx.x, lane = tid & 31, wid = tid >> 5;
    int lt = lane & 7, lg = lane >> 3, g = lane >> 2, q = lane & 3;
    int bh = blockIdx.z, split = blockIdx.y;
    int rowBase = blockIdx.x * 128;
    const bf16* Q = Qa + (long long)(bh / qCnt) * qOuter + (long long)(bh % qCnt) * qInner;
    const bf16* K = Ka + (long long)(bh / kCnt) * kOuter + (long long)(bh % kCnt) * kInner
                       + (long long)split * keysPerSplit * kStride;
    const bf16* V = Va + (long long)(bh / vCnt) * vOuter + (long long)(bh % vCnt) * vInner
                       + (long long)split * keysPerSplit * vStride;

    #pragma unroll
    for (int j = 0; j < 4; j++) {
        int c = tid + j * 256;
        int row = c >> 3, seg = c & 7;
        cpa16(smBase + ((row * 72 + seg * 8) << 1),
              Q + (long long)(rowBase + row) * qStride + seg * 8, true);
    }
    auto issueKV = [&](int t, int stg) {
        int key0 = t * 64;
        #pragma unroll
        for (int j = 0; j < 2; j++) {
            int c = tid + j * 256;
            int p = c >> 8, rem = c & 255;
            int row = rem >> 2, seg = rem & 3;
            cpa16(smBase + ((FA_K + stg * 9216 + (p * 64 + row) * 72 + seg * 16) << 1),
                  K + (long long)p * kPlane + (long long)(key0 + row) * kStride + seg * 16, true);
            cpa16(smBase + ((FA_K + stg * 9216 + (p * 64 + row) * 72 + seg * 16 + 8) << 1),
                  K + (long long)p * kPlane + (long long)(key0 + row) * kStride + seg * 16 + 8, true);
            cpa16(smBase + ((FA_V + stg * 9216 + (p * 64 + row) * 72 + seg * 16) << 1),
                  V + (long long)p * vPlane + (long long)(key0 + row) * vStride + seg * 16, true);
            cpa16(smBase + ((FA_V + stg * 9216 + (p * 64 + row) * 72 + seg * 16 + 8) << 1),
                  V + (long long)p * vPlane + (long long)(key0 + row) * vStride + seg * 16 + 8, true);
        }
        cpa_commit();
    };
    issueKV(0, 0);

    int warpRow = wid * 16;
    unsigned qh[4][4];
    float o[8][4];
    #pragma unroll
    for (int i = 0; i < 8; i++)
        #pragma unroll
        for (int e = 0; e < 4; e++) o[i][e] = 0.f;
    float m0 = -1e30f, m1 = -1e30f, l0 = 0.f, l1 = 0.f;

    int nTiles = keysPerSplit / 64;
    for (int t = 0; t < nTiles; t++) {
        int stg = t & 1;
        bool more = (t + 1 < nTiles);
        if (more) {
            issueKV(t + 1, stg ^ 1);
            asm volatile("cp.async.wait_group 1;\n");
        } else {
            asm volatile("cp.async.wait_group 0;\n");
        }
        __syncthreads();
        if (t == 0) {
            #pragma unroll
            for (int kc = 0; kc < 4; kc++) {
                int row = warpRow + lt + ((lg & 1) << 3);
                int kk = kc * 16 + ((lg >> 1) << 3);
                ldsm4(qh[kc][0], qh[kc][1], qh[kc][2], qh[kc][3],
                      smBase + ((row * 72 + kk) << 1));
            }
        }
        uint32_t skS = smBase + ((FA_K + stg * 9216) << 1);
        uint32_t svS = smBase + ((FA_V + stg * 9216) << 1);

        float sc[8][4];
        #pragma unroll
        for (int i = 0; i < 8; i++)
            #pragma unroll
            for (int e = 0; e < 4; e++) sc[i][e] = 0.f;
        #pragma unroll
        for (int kc = 0; kc < 4; kc++) {
            unsigned kh[4][4], kl[4][4];
            #pragma unroll
            for (int ntp = 0; ntp < 4; ntp++) {
                int n = ntp * 16 + lt + ((lg >> 1) << 3);
                int kk = kc * 16 + ((lg & 1) << 3);
                ldsm4(kh[ntp][0], kh[ntp][1], kh[ntp][2], kh[ntp][3],
                      skS + (((0 * 64 + n) * 72 + kk) << 1));
                ldsm4(kl[ntp][0], kl[ntp][1], kl[ntp][2], kl[ntp][3],
                      skS + (((64 + n) * 72 + kk) << 1));
            }
            #pragma unroll
            for (int nt = 0; nt < 8; nt++) {
                const unsigned* bhf = &kh[nt >> 1][(nt & 1) * 2];
                const unsigned* blf = &kl[nt >> 1][(nt & 1) * 2];
                mma16816(sc[nt], qh[kc], bhf);
                mma16816(sc[nt], qh[kc], blf);
            }
        }
        float mt0 = -1e30f, mt1 = -1e30f;
        #pragma unroll
        for (int nt = 0; nt < 8; nt++) {
            #pragma unroll
            for (int e = 0; e < 4; e++) sc[nt][e] *= 0.125f;
            mt0 = fmaxf(mt0, fmaxf(sc[nt][0], sc[nt][1]));
            mt1 = fmaxf(mt1, fmaxf(sc[nt][2], sc[nt][3]));
        }
        mt0 = fmaxf(mt0, __shfl_xor_sync(0xffffffffu, mt0, 1));
        mt0 = fmaxf(mt0, __shfl_xor_sync(0xffffffffu, mt0, 2));
        mt1 = fmaxf(mt1, __shfl_xor_sync(0xffffffffu, mt1, 1));
        mt1 = fmaxf(mt1, __shfl_xor_sync(0xffffffffu, mt1, 2));
        float mn0 = fmaxf(m0, mt0), mn1 = fmaxf(m1, mt1);
        float f0 = __expf(m0 - mn0), f1 = __expf(m1 - mn1);
        m0 = mn0; m1 = mn1;
        float rs0 = 0.f, rs1 = 0.f;
        #pragma unroll
        for (int nt = 0; nt < 8; nt++) {
            sc[nt][0] = __expf(sc[nt][0] - mn0);
            sc[nt][1] = __expf(sc[nt][1] - mn0);
            sc[nt][2] = __expf(sc[nt][2] - mn1);
            sc[nt][3] = __expf(sc[nt][3] - mn1);
            rs0 += sc[nt][0] + sc[nt][1];
            rs1 += sc[nt][2] + sc[nt][3];
        }
        rs0 += __shfl_xor_sync(0xffffffffu, rs0, 1);
        rs0 += __shfl_xor_sync(0xffffffffu, rs0, 2);
        rs1 += __shfl_xor_sync(0xffffffffu, rs1, 1);
        rs1 += __shfl_xor_sync(0xffffffffu, rs1, 2);
        l0 = l0 * f0 + rs0;
        l1 = l1 * f1 + rs1;
        #pragma unroll
        for (int nt = 0; nt < 8; nt++) {
            o[nt][0] *= f0; o[nt][1] *= f0;
            o[nt][2] *= f1; o[nt][3] *= f1;
        }
        #pragma unroll
        for (int kc = 0; kc < 4; kc++) {
            unsigned ph[4];
            __nv_bfloat162 t0 = __floats2bfloat162_rn(sc[2 * kc][0], sc[2 * kc][1]);
            __nv_bfloat162 t1 = __floats2bfloat162_rn(sc[2 * kc][2], sc[2 * kc][3]);
            __nv_bfloat162 t2 = __floats2bfloat162_rn(sc[2 * kc + 1][0], sc[2 * kc + 1][1]);
            __nv_bfloat162 t3 = __floats2bfloat162_rn(sc[2 * kc + 1][2], sc[2 * kc + 1][3]);
            ph[0] = *reinterpret_cast<unsigned*>(&t0);
            ph[1] = *reinterpret_cast<unsigned*>(&t1);
            ph[2] = *reinterpret_cast<unsigned*>(&t2);
            ph[3] = *reinterpret_cast<unsigned*>(&t3);
            unsigned vh[4][4], vl[4][4];
            #pragma unroll
            for (int ntp = 0; ntp < 4; ntp++) {
                int k = kc * 16 + lt + ((lg & 1) << 3);
                int n = ntp * 16 + ((lg >> 1) << 3);
                ldsm4t(vh[ntp][0], vh[ntp][1], vh[ntp][2], vh[ntp][3],
                       svS + (((0 * 64 + k) * 72 + n) << 1));
                ldsm4t(vl[ntp][0], vl[ntp][1], vl[ntp][2], vl[ntp][3],
                       svS + (((64 + k) * 72 + n) << 1));
            }
            #pragma unroll
            for (int nt = 0; nt < 8; nt++) {
                const unsigned* bhf = &vh[nt >> 1][(nt & 1) * 2];
                const unsigned* blf = &vl[nt >> 1][(nt & 1) * 2];
                mma16816(o[nt], ph, bhf);
                mma16816(o[nt], ph, blf);
            }
        }
        __syncthreads();
    }

    int row0 = rowBase + warpRow + g;
    int row1 = row0 + 8;
    if (MODE == 1) {
        float i0 = 1.f / l0, i1 = 1.f / l1;
        int b = bh >> 3, hh = bh & 7;
        const float* Cv = CONV + (long long)bh * NPAD * 64;
        #pragma unroll
        for (int nt = 0; nt < 8; nt++) {
            int col = nt * 8 + q * 2;
            float2 c0 = *(const float2*)&Cv[(long long)row0 * 64 + col];
            float2 c1 = *(const float2*)&Cv[(long long)row1 * 64 + col];
            long long i0d = ((long long)b * NPAD + row0) * DM + hh * 64 + col;
            long long i1d = ((long long)b * NPAD + row1) * DM + hh * 64 + col;
            storeHi2(CATD, i0d, o[nt][0] * i0 + c0.x, o[nt][1] * i0 + c0.y);
            storeHi2(CATD, i1d, o[nt][2] * i1 + c1.x, o[nt][3] * i1 + c1.y);
        }
    } else {
        long long pb = ((long long)split * BHN + bh) * NLM;
        #pragma unroll
        for (int nt = 0; nt < 8; nt++) {
            int col = nt * 8 + q * 2;
            *(float2*)&PO[(pb + row0) * 64 + col] = make_float2(o[nt][0], o[nt][1]);
            *(float2*)&PO[(pb + row1) * 64 + col] = make_float2(o[nt][2], o[nt][3]);
        }
        if (q == 0) {
            PM[pb + row0] = m0; PM[pb + row1] = m1;
            PS[pb + row0] = l0; PS[pb + row1] = l1;
        }
    }
}

__global__ void fa_combine(const float* __restrict__ po, const float* __restrict__ pm,
                           const float* __restrict__ ps, bf16* __restrict__ outd,
                           long long plane) {
    long long idx = (long long)blockIdx.x * 256 + threadIdx.x;
    int d = (int)(idx & 63);
    long long rid = idx >> 6;
    const long long RS = (long long)BHN * NLM;
    float M = -1e30f;
    #pragma unroll
    for (int s = 0; s < NSPLIT; s++) M = fmaxf(M, pm[s * RS + rid]);
    float S = 0.f, val = 0.f;
    #pragma unroll
    for (int s = 0; s < NSPLIT; s++) {
        float e = __expf(pm[s * RS + rid] - M);
        S += ps[s * RS + rid] * e;
        val += po[(s * RS + rid) * 64 + d] * e;
    }
    storeDual1(outd, plane, rid * 64 + d, val / S);
}

// ---------------- misc kernels ----------------
__global__ void tobf16_kernel(const float* __restrict__ x, bf16* __restrict__ d,
                              long long n, long long plane) {
    long long i = (long long)blockIdx.x * 256 + threadIdx.x;
    if (i >= n) return;
    storeDual1(d, plane, i, x[i]);
}
__global__ void tobf16hi_kernel(const float* __restrict__ x, bf16* __restrict__ d,
                                long long n) {
    long long i = (long long)blockIdx.x * 256 + threadIdx.x;
    if (i >= n) return;
    d[i] = __float2bfloat16(x[i]);
}

__global__ void init_h_kernel(const float* __restrict__ cls, float* __restrict__ h) {
    int r = blockIdx.x, b = blockIdx.y;
    float* o = h + ((long long)b * NPAD + r) * DM;
    for (int i = threadIdx.x; i < DM; i += 256) o[i] = (r == PADN) ? cls[i] : 0.f;
}

// layernorm: fp32 in -> hi-bf16 out (pad rows zeroed)
__global__ void layernorm_kernel(const float* __restrict__ in, bf16* __restrict__ xd,
                                 const float* __restrict__ gam, const float* __restrict__ bet) {
    __shared__ float sh[8];
    long long row = blockIdx.x;
    int r = (int)(row % NPAD);
    int tid = threadIdx.x;
    long long idx = row * DM + tid * 2;
    if (r < PADN) {
        storeHi2(xd, idx, 0.f, 0.f);
        return;
    }
    const float2* x = (const float2*)(in + row * DM);
    float2 v = x[tid];
    float s = v.x + v.y;
    float s2 = v.x * v.x + v.y * v.y;
    s = blockReduceSum(s, sh);
    s2 = blockReduceSum(s2, sh);
    float mean = s / DM;
    float var = s2 / DM - mean * mean;
    float inv = rsqrtf(var + 1e-5f);
    float2 gv = ((const float2*)gam)[tid];
    float2 bv = ((const float2*)bet)[tid];
    storeHi2(xd, idx,
             (v.x - mean) * inv * gv.x + bv.x,
             (v.y - mean) * inv * gv.y + bv.y);
}

__global__ void landmark_kernel(const bf16* __restrict__ qkvd, long long qkvPlane,
                                bf16* __restrict__ qld, bf16* __restrict__ kld,
                                long long kplane) {
    int m = blockIdx.x, bh = blockIdx.y;
    int b = bh >> 3, h = bh & 7;
    int d = threadIdx.x;
    long long base = (long long)b * NPAD * TD + (long long)m * LPER * TD + h * 64 + d;
    float sq = 0.f, sk = 0.f;
    #pragma unroll 4
    for (int r = 0; r < LPER; r++) {
        long long i = base + (long long)r * TD;
        sq += loadDual(qkvd, qkvPlane, i);
        sk += loadDual(qkvd, qkvPlane, i + 512);
    }
    long long idx = ((long long)bh * NLM + m) * DH + d;
    qld[idx] = __float2bfloat16(sq * (1.f / LPER));
    storeDual1(kld, kplane, idx, sk * (1.f / LPER));
}

__global__ void softmax256(const float* __restrict__ in, float* __restrict__ out32,
                           bf16* __restrict__ dual, long long plane, long long nrows) {
    long long row = (long long)blockIdx.x * 8 + (threadIdx.x >> 5);
    if (row >= nrows) return;
    int lane = threadIdx.x & 31;
    const float4* pi = (const float4*)(in + row * 256);
    float4 v0 = pi[lane];
    float4 v1 = pi[lane + 32];
    float m = fmaxf(fmaxf(fmaxf(v0.x, v0.y), fmaxf(v0.z, v0.w)),
                    fmaxf(fmaxf(v1.x, v1.y), fmaxf(v1.z, v1.w)));
    #pragma unroll
    for (int o = 16; o; o >>= 1) m = fmaxf(m, __shfl_xor_sync(0xffffffffu, m, o));
    v0.x = __expf(v0.x - m); v0.y = __expf(v0.y - m);
    v0.z = __expf(v0.z - m); v0.w = __expf(v0.w - m);
    v1.x = __expf(v1.x - m); v1.y = __expf(v1.y - m);
    v1.z = __expf(v1.z - m); v1.w = __expf(v1.w - m);
    float s = v0.x + v0.y + v0.z + v0.w + v1.x + v1.y + v1.z + v1.w;
    #pragma unroll
    for (int o = 16; o; o >>= 1) s += __shfl_xor_sync(0xffffffffu, s, o);
    float inv = 1.f / s;
    v0.x *= inv; v0.y *= inv; v0.z *= inv; v0.w *= inv;
    v1.x *= inv; v1.y *= inv; v1.z *= inv; v1.w *= inv;
    if (out32) {
        ((float4*)(out32 + row * 256))[lane] = v0;
        ((float4*)(out32 + row * 256))[lane + 32] = v1;
    }
    long long b0 = row * 256 + lane * 4;
    storeDual2(dual, plane, b0, v0.x, v0.y);
    storeDual2(dual, plane, b0 + 2, v0.z, v0.w);
    storeDual2(dual, plane, b0 + 128, v1.x, v1.y);
    storeDual2(dual, plane, b0 + 130, v1.z, v1.w);
}

__global__ void reset_kernel() {
    if (threadIdx.x == 0) { g_maxrow = 0; g_maxcol = 0; }
}

__global__ void a2stats_kernel(const float* __restrict__ a2) {
    __shared__ float sh[8];
    int bh = blockIdx.x;
    const float* a = a2 + (long long)bh * MM;
    int j = threadIdx.x;
    float cs = 0.f, rs = 0.f;
    for (int i = 0; i < NLM; i++) cs += a[(long long)i * NLM + j];
    const float* row = a + (long long)j * NLM;
    for (int i = 0; i < NLM; i++) rs += row[i];
    float cmax = blockReduceMax(cs, sh);
    float rmax = blockReduceMax(rs, sh);
    if (threadIdx.x == 0) {
        atomicMax(&g_maxcol, __float_as_int(cmax));
        atomicMax(&g_maxrow, __float_as_int(rmax));
    }
}

__global__ void z0_kernel(const float* __restrict__ a2, bf16* __restrict__ zp, long long plane) {
    __shared__ float tile[32][33];
    int bh = blockIdx.z;
    const float* a = a2 + (long long)bh * MM;
    long long zbase = (long long)bh * MM;
    float inv = 1.f / (__int_as_float(g_maxrow) * __int_as_float(g_maxcol));
    int i0 = blockIdx.y * 32, j0 = blockIdx.x * 32;
    for (int r = threadIdx.y; r < 32; r += 8)
        tile[r][threadIdx.x] = a[(long long)(i0 + r) * NLM + j0 + threadIdx.x];
    __syncthreads();
    for (int r = threadIdx.y; r < 32; r += 8)
        storeDual1(zp, plane, zbase + (long long)(j0 + r) * NLM + i0 + threadIdx.x,
                   tile[threadIdx.x][r] * inv);
}

__global__ void conv_kernel(const bf16* __restrict__ qkvd, long long qkvPlane,
                            const float* __restrict__ w, float* __restrict__ outh) {
    int bh = blockIdx.y;
    int b = bh >> 3, h = bh & 7;
    int iBase = blockIdx.x * 64;
    __shared__ float sv[96][64];
    __shared__ float sw[CONVK];
    long long vbase = (long long)b * NPAD * TD + 1024 + h * 64;
    int tid = threadIdx.x;
    for (int idx = tid; idx < 96 * 64; idx += 256) {
        int r = idx >> 6, d = idx & 63;
        int gi = iBase - 16 + r;
        sv[r][d] = (gi >= 0 && gi < NPAD)
                   ? loadDual(qkvd, qkvPlane, vbase + (long long)gi * TD + d) : 0.f;
    }
    if (tid < CONVK) sw[tid] = w[h * CONVK + tid];
    __syncthreads();
    float* out = outh + (long long)bh * NPAD * DH + (long long)iBase * DH;
    for (int idx = tid; idx < 64 * 64; idx += 256) {
        int r = idx >> 6, d = idx & 63;
        float s = 0.f;
        #pragma unroll
        for (int t = 0; t < CONVK; t++) s += sw[t] * sv[r + t][d];
        out[r * 64 + d] = s;
    }
}

__global__ void final_kernel(const float* __restrict__ h, const float* __restrict__ gam,
                             const float* __restrict__ bet, const float* __restrict__ w2,
                             const float* __restrict__ b2, float* __restrict__ out) {
    __shared__ float sh[8];
    int b = blockIdx.x;
    const float* x = h + ((long long)b * NPAD + PADN) * DM;
    float s = 0.f, s2 = 0.f;
    for (int i = threadIdx.x; i < DM; i += 256) { float v = x[i]; s += v; s2 += v * v; }
    s = blockReduceSum(s, sh);
    s2 = blockReduceSum(s2, sh);
    float mean = s / DM;
    float var = s2 / DM - mean * mean;
    float inv = rsqrtf(var + 1e-5f);
    float p0 = 0.f, p1 = 0.f;
    for (int i = threadIdx.x; i < DM; i += 256) {
        float hn = (x[i] - mean) * inv * gam[i] + bet[i];
        p0 += hn * w2[2 * i];
        p1 += hn * w2[2 * i + 1];
    }
    p0 = blockReduceSum(p0, sh);
    p1 = blockReduceSum(p1, sh);
    if (threadIdx.x == 0) {
        float l0 = p0 + b2[0], l1 = p1 + b2[1];
        float mx = fmaxf(l0, l1);
        float e0 = expf(l0 - mx), e1 = expf(l1 - mx);
        float si = 1.f / (e0 + e1);
        out[b * 2 + 0] = l0;
        out[b * 2 + 1] = l1;
        out[4 + b * 2 + 0] = e0 * si;
        out[4 + b * 2 + 1] = e1 * si;
        out[8 + b] = (l1 > l0) ? 1.f : 0.f;
    }
}

// ---------------- host side ----------------
static void launch_gemm(cudaStream_t st, int bn, const bf16* A, const bf16* B,
                        long long aPlane, long long bPlane,
                        float* C, bf16* D, long long dPlane, bf16* D2, long long d2Plane,
                        int M, int N, int K, int lda, int ldb, int ldc,
                        long long aO, long long aI, int aC,
                        long long bO, long long bI, int bC,
                        long long cS, int batches, float alpha,
                        const float* bias, int relu, int accum, int transB,
                        int splitK = 1, long long partStride = 0,
                        float diagVal = 0.f, float diag2 = 0.f) {
    dim3 grid(N / bn, (M + BM - 1) / BM, batches * splitK);
    if (bn == 128)
        gemm_tc<128, 2, 4><<<grid, 256, 0, st>>>(A, B, aPlane, bPlane, C, D, dPlane, D2, d2Plane,
                                                 M, K, lda, ldb, ldc, aO, aI, aC, bO, bI, bC,
                                                 cS, alpha, bias, relu, accum, transB,
                                                 splitK, partStride, diagVal, diag2);
    else
        gemm_tc<64, 4, 2><<<grid, 256, 0, st>>>(A, B, aPlane, bPlane, C, D, dPlane, D2, d2Plane,
                                                M, K, lda, ldb, ldc, aO, aI, aC, bO, bI, bC,
                                                cS, alpha, bias, relu, accum, transB,
                                                splitK, partStride, diagVal, diag2);
}

// streams/events created once at static-init time (outside harness mem checkpoints;
// no device-memory allocation APIs involved)
struct SideStream {
    cudaStream_t sB;
    cudaEvent_t eL[2], eB[2];
    SideStream() {
        cudaStreamCreateWithFlags(&sB, cudaStreamNonBlocking);
        for (int i = 0; i < 2; i++) {
            cudaEventCreateWithFlags(&eL[i], cudaEventDisableTiming);
            cudaEventCreateWithFlags(&eB[i], cudaEventDisableTiming);
        }
    }
};
static SideStream g_ss;

#define SYMF(p, s) do { void* _t; cudaGetSymbolAddress(&_t, s); p = (float*)_t; } while (0)
#define SYMB(p, s) do { void* _t; cudaGetSymbolAddress(&_t, s); p = (bf16*)_t; } while (0)

extern "C" void kernel_launch(void* const* d_in, const int* in_sizes, int n_in,
                              void* d_out, int out_size) {
    const float* feats = (const float*)d_in[0];
    const float* fc1_w = (const float*)d_in[1];
    const float* fc1_b = (const float*)d_in[2];
    const float* cls   = (const float*)d_in[3];
    const float* lng[2]   = {(const float*)d_in[4],  (const float*)d_in[10]};
    const float* lnb[2]   = {(const float*)d_in[5],  (const float*)d_in[11]};
    const float* qkvw[2]  = {(const float*)d_in[6],  (const float*)d_in[12]};
    const float* outw[2]  = {(const float*)d_in[7],  (const float*)d_in[13]};
    const float* outb[2]  = {(const float*)d_in[8],  (const float*)d_in[14]};
    const float* convw[2] = {(const float*)d_in[9],  (const float*)d_in[15]};
    const float* nfg  = (const float*)d_in[16];
    const float* nfb  = (const float*)d_in[17];
    const float* fc2w = (const float*)d_in[18];
    const float* fc2b = (const float*)d_in[19];

    float *h, *a2, *outh, *po, *pm, *ps;
    SYMF(h, g_h); SYMF(a2, g_a2); SYMF(outh, g_outh);
    SYMF(po, g_po); SYMF(pm, g_pm); SYMF(ps, g_ps);
    bf16 *featsd, *w1d, *qkvwd, *outwd, *xlnd, *qkvd, *qld, *kld, *a2d;
    bf16 *zpd, *p2d, *t1d, *t2d, *t3d, *a3vd, *u1d, *u2d, *wd, *catd;
    SYMB(featsd, g_featsd); SYMB(w1d, g_w1d); SYMB(qkvwd, g_qkvwd); SYMB(outwd, g_outwd);
    SYMB(xlnd, g_xlnd); SYMB(qkvd, g_qkvd); SYMB(qld, g_qld); SYMB(kld, g_kld);
    SYMB(a2d, g_a2d);
    SYMB(zpd, g_zpd); SYMB(p2d, g_p2d); SYMB(t1d, g_t1d); SYMB(t2d, g_t2d); SYMB(t3d, g_t3d);
    SYMB(a3vd, g_a3vd); SYMB(u1d, g_u1d); SYMB(u2d, g_u2d); SYMB(wd, g_wd); SYMB(catd, g_catd);

    const long long featsPlane = (long long)BATCH * NTOK * DIN;
    const long long qkvPlane   = (long long)BATCH * NPAD * TD;
    const long long qlPlane    = (long long)BHN * NLM * DH;
    const long long a2Plane    = (long long)BHN * MM;
    const long long zpPlane    = 32LL * MM;
    const long long p16Plane   = 16LL * MM;
    const long long t3Plane    = 6LL * 16 * MM;
    const long long avPlane    = (long long)BHN * NLM * DH;
    const long long MMl = MM;
    (void)MMl;

    cudaFuncSetAttribute(flash_kernel<0>, cudaFuncAttributeMaxDynamicSharedMemorySize, FA_SMEM_BYTES);
    cudaFuncSetAttribute(flash_kernel<1>, cudaFuncAttributeMaxDynamicSharedMemorySize, FA_SMEM_BYTES);

    cudaStream_t sB = g_ss.sB;

    tobf16hi_kernel<<<(unsigned)((featsPlane + 255) / 256), 256>>>(feats, featsd, featsPlane);
    tobf16_kernel<<<(DIN * DM + 255) / 256, 256>>>(fc1_w, w1d, DIN * DM, DIN * DM);
    for (int l = 0; l < 2; l++) {
        tobf16_kernel<<<(DM * TD + 255) / 256, 256>>>(qkvw[l], qkvwd + (long long)l * 2 * DM * TD,
                                                      DM * TD, DM * TD);
        tobf16_kernel<<<(DM * DM + 255) / 256, 256>>>(outw[l], outwd + (long long)l * 2 * DM * DM,
                                                      DM * DM, DM * DM);
    }

    init_h_kernel<<<dim3(PADN + 1, BATCH), 256>>>(cls, h);

    // fc1 + relu
    launch_gemm(0, 128, featsd, w1d, 0, DIN * DM,
                h + (long long)(PADN + 1) * DM, nullptr, 0, nullptr, 0,
                NTOK, DM, DIN, DIN, DM, DM,
                (long long)NTOK * DIN, 0, 1, 0, 0, 1,
                (long long)NPAD * DM, BATCH, 1.f, fc1_b, 1, 0, 0);

    for (int l = 0; l < 2; l++) {
        layernorm_kernel<<<BATCH * NPAD, 256>>>(h, xlnd, lng[l], lnb[l]);

        // qkv = xln @ qkvw  (dual output only)
        launch_gemm(0, 128, xlnd, qkvwd + (long long)l * 2 * DM * TD, 0, DM * TD,
                    nullptr, qkvd, qkvPlane, nullptr, 0,
                    NPAD, TD, DM, DM, TD, TD,
                    (long long)NPAD * DM, 0, 1, 0, 0, 1,
                    (long long)NPAD * TD, BATCH, 1.f, nullptr, 0, 0, 0);

        landmark_kernel<<<dim3(NLM, BHN), 64>>>(qkvd, qkvPlane, qld, kld, qlPlane);
        cudaEventRecord(g_ss.eL[l], 0);

        // ===== side stream: a2 + pinv p-chain =====
        cudaStreamWaitEvent(sB, g_ss.eL[l], 0);
        launch_gemm(sB, 128, qld, kld, 0, qlPlane,
                    a2, nullptr, 0, nullptr, 0,
                    NLM, NLM, DH, DH, DH, NLM,
                    (long long)NLM * DH, 0, 1, (long long)NLM * DH, 0, 1,
                    MM, BHN, 0.125f, nullptr, 0, 0, 1);
        softmax256<<<(BHN * NLM) / 8, 256, 0, sB>>>(a2, a2, a2d, a2Plane, (long long)BHN * NLM);
        reset_kernel<<<1, 32, 0, sB>>>();
        a2stats_kernel<<<BHN, 256, 0, sB>>>(a2);
        z0_kernel<<<dim3(8, 8, BHN), dim3(32, 8), 0, sB>>>(a2, zpd, zpPlane);
        bf16* pA = zpd + 16 * MM;  long long pAplane = zpPlane;
        bf16* pB = p2d;            long long pBplane = p16Plane;
        launch_gemm(sB, 64, a2d, zpd, a2Plane, zpPlane,
                    nullptr, pA, pAplane, t1d, p16Plane,
                    NLM, NLM, NLM, NLM, NLM, NLM,
                    MM, 0, 1, MM, 0, 1, MM, BHN, 1.f, nullptr, 0, 0, 0,
                    1, 0, 0.f, 7.f);
        for (int it = 0; it < 6; it++) {
            launch_gemm(sB, 64, pA, t1d, pAplane, p16Plane,
                        nullptr, nullptr, 0, t2d, p16Plane,
                        NLM, NLM, NLM, NLM, NLM, NLM,
                        MM, 0, 1, MM, 0, 1, MM, BHN, 1.f, nullptr, 0, 0, 0,
                        1, 0, 0.f, 15.f);
            launch_gemm(sB, 64, pA, t2d, pAplane, p16Plane,
                        nullptr, nullptr, 0, t3d + (long long)it * 16 * MM, t3Plane,
                        NLM, NLM, NLM, NLM, NLM, NLM,
                        MM, 0, 1, MM, 0, 1, MM, BHN, 1.f, nullptr, 0, 0, 0,
                        1, 0, 0.f, 13.f);
            if (it < 5) {
                launch_gemm(sB, 64, pA, t3d + (long long)it * 16 * MM, pAplane, t3Plane,
                            nullptr, pB, pBplane, t1d, p16Plane,
                            NLM, NLM, NLM, NLM, NLM, NLM,
                            MM, 0, 1, MM, 0, 1, MM, BHN, 0.25f, nullptr, 0, 0, 0,
                            1, 0, 0.f, 7.f);
                bf16* tp = pA; pA = pB; pB = tp;
                long long tpl = pAplane; pAplane = pBplane; pBplane = tpl;
            }
        }
        cudaEventRecord(g_ss.eB[l], sB);

        // ===== main stream: conv + F1 + combine (overlaps with side stream) =====
        conv_kernel<<<dim3(NPAD / 64, BHN), 256>>>(qkvd, qkvPlane, convw[l], outh);

        flash_kernel<0><<<dim3(NLM / 128, NSPLIT, BHN), 256, FA_SMEM_BYTES>>>(
            qld, 0, DH, 0, (long long)NLM * DH, BHN,
            qkvd + DM, qkvPlane, TD, (long long)NPAD * TD, 64, NH,
            qkvd + 2 * DM, qkvPlane, TD, (long long)NPAD * TD, 64, NH,
            NPAD / NSPLIT, po, pm, ps, nullptr, nullptr, 0);
        fa_combine<<<(unsigned)((long long)BHN * NLM * DH / 256), 256>>>(po, pm, ps, a3vd, avPlane);

        // join pinv chain
        cudaStreamWaitEvent(0, g_ss.eB[l], 0);

        // u chain: u = t3_0 @ (t3_1 @ ... (t3_5 @ a3v))
        bf16* uc = a3vd;  long long ucPlane = avPlane;
        bf16* un = u1d;
        for (int it = 5; it >= 0; it--) {
            launch_gemm(0, 64, t3d + (long long)it * 16 * MM, uc, t3Plane, ucPlane,
                        nullptr, un, avPlane, nullptr, 0,
                        NLM, DH, NLM, NLM, DH, DH,
                        MM, 0, 1, (long long)NLM * DH, 0, 1,
                        (long long)NLM * DH, BHN, 1.f, nullptr, 0, 0, 0);
            bf16* prev = uc;
            uc = un; ucPlane = avPlane;
            un = (prev == a3vd) ? u2d : prev;
        }
        // w = 0.25^6 * z0 @ u
        launch_gemm(0, 64, zpd, uc, zpPlane, avPlane,
                    nullptr, wd, avPlane, nullptr, 0,
                    NLM, DH, NLM, NLM, DH, DH,
                    MM, 0, 1, (long long)NLM * DH, 0, 1,
                    (long long)NLM * DH, BHN, 1.f / 4096.f, nullptr, 0, 0, 0);

        // F2: catd = merge( softmax(0.125 Q k_l^T) @ w + conv )   (hi-only store)
        flash_kernel<1><<<dim3(NPAD / 128, 1, BHN), 256, FA_SMEM_BYTES>>>(
            qkvd, qkvPlane, TD, (long long)NPAD * TD, 64, NH,
            kld, qlPlane, DH, 0, (long long)NLM * DH, BHN,
            wd, avPlane, DH, 0, (long long)NLM * DH, BHN,
            NLM, nullptr, nullptr, nullptr, outh, catd, 0);

        // output projection, accumulate into residual stream (fp32)
        launch_gemm(0, 128, catd + (long long)PADN * DM, outwd + (long long)l * 2 * DM * DM,
                    0, DM * DM,
                    h + (long long)PADN * DM, nullptr, 0, nullptr, 0,
                    NP1, DM, DM, DM, DM, DM,
                    (long long)NPAD * DM, 0, 1, 0, 0, 1,
                    (long long)NPAD * DM, BATCH, 1.f, outb[l], 0, 1, 0);
    }

    final_kernel<<<BATCH, 256>>>(h, nfg, nfb, fc2w, fc2b, (float*)d_out);
}

// round 16
// speedup vs baseline: 1.4488x; 1.0279x over previous
#include <cuda_runtime.h>
#include <cuda_bf16.h>
#include <cstdint>
#include <math.h>

#define BATCH 2
#define NTOK  8000
#define NP1   8001
#define PADN  191
#define NPAD  8192
#define DM    512
#define DIN   1024
#define NH    8
#define DH    64
#define NLM   256
#define LPER  32
#define BHN   16
#define CONVK 33
#define TD    1536
#define BM    128
#define BK    32
#define NSPLIT 8
#define MM    ((long long)NLM * NLM)

typedef __nv_bfloat16 bf16;

// ---------------- fp32 scratch ----------------
__device__ float g_h   [(long long)BATCH*NPAD*DM];
__device__ float g_a2  [(long long)BHN*NLM*NLM];
__device__ float g_outh[(long long)BHN*NPAD*DH];
__device__ float g_po  [(long long)NSPLIT*BHN*NLM*DH];
__device__ float g_pm  [(long long)NSPLIT*BHN*NLM];
__device__ float g_ps  [(long long)NSPLIT*BHN*NLM];
__device__ int   g_maxrow;
__device__ int   g_maxcol;

// ---------------- dual-bf16 scratch (hi plane + lo plane) ----------------
__device__ __align__(16) bf16 g_featsd[1LL*BATCH*NTOK*DIN];        // hi only
__device__ __align__(16) bf16 g_w1d   [2LL*DIN*DM];
__device__ __align__(16) bf16 g_qkvwd [2LL*2*DM*TD];
__device__ __align__(16) bf16 g_outwd [2LL*2*DM*DM];
__device__ __align__(16) bf16 g_xlnd  [1LL*BATCH*NPAD*DM];         // hi only
__device__ __align__(16) bf16 g_qkvd  [2LL*BATCH*NPAD*TD];
__device__ __align__(16) bf16 g_qld   [1LL*BHN*NLM*DH];            // hi only
__device__ __align__(16) bf16 g_kld   [2LL*BHN*NLM*DH];
__device__ __align__(16) bf16 g_a2d   [2LL*BHN*NLM*NLM];
__device__ __align__(16) bf16 g_zpd   [2LL*32*NLM*NLM];   // z in 0-15, p in 16-31
__device__ __align__(16) bf16 g_zp2d  [2LL*32*NLM*NLM];
__device__ __align__(16) bf16 g_t1d   [2LL*32*NLM*NLM];   // t1 valid in p-half
__device__ __align__(16) bf16 g_t2d   [2LL*16*NLM*NLM];
__device__ __align__(16) bf16 g_t3d   [2LL*16*NLM*NLM];
__device__ __align__(16) bf16 g_a3vd  [2LL*BHN*NLM*DH];
__device__ __align__(16) bf16 g_wd    [2LL*BHN*NLM*DH];
__device__ __align__(16) bf16 g_catd  [1LL*BATCH*NPAD*DM];         // hi only

// ---------------- helpers ----------------
__device__ __forceinline__ void storeDual2(bf16* d, long long plane, long long idx,
                                           float x, float y) {
    __nv_bfloat162 h = __floats2bfloat162_rn(x, y);
    *reinterpret_cast<__nv_bfloat162*>(d + idx) = h;
    __nv_bfloat162 l = __floats2bfloat162_rn(x - __bfloat162float(h.x),
                                             y - __bfloat162float(h.y));
    *reinterpret_cast<__nv_bfloat162*>(d + plane + idx) = l;
}
__device__ __forceinline__ void storeHi2(bf16* d, long long idx, float x, float y) {
    __nv_bfloat162 h = __floats2bfloat162_rn(x, y);
    *reinterpret_cast<__nv_bfloat162*>(d + idx) = h;
}
__device__ __forceinline__ void storeDual1(bf16* d, long long plane, long long idx, float x) {
    bf16 h = __float2bfloat16(x);
    d[idx] = h;
    d[plane + idx] = __float2bfloat16(x - __bfloat162float(h));
}
__device__ __forceinline__ float loadDual(const bf16* d, long long plane, long long idx) {
    return __bfloat162float(d[idx]) + __bfloat162float(d[plane + idx]);
}
__device__ __forceinline__ void cpa16(uint32_t dst, const void* src, bool pred) {
    int sz = pred ? 16 : 0;
    asm volatile("cp.async.cg.shared.global [%0], [%1], 16, %2;\n"
                 :: "r"(dst), "l"(src), "r"(sz));
}
__device__ __forceinline__ void cpa_commit() {
    asm volatile("cp.async.commit_group;\n");
}

__device__ __forceinline__ float blockReduceSum(float v, float* sh) {
    #pragma unroll
    for (int o = 16; o; o >>= 1) v += __shfl_xor_sync(0xffffffffu, v, o);
    int w = threadIdx.x >> 5;
    if ((threadIdx.x & 31) == 0) sh[w] = v;
    __syncthreads();
    if (threadIdx.x < 8) {
        v = sh[threadIdx.x];
        #pragma unroll
        for (int o = 4; o; o >>= 1) v += __shfl_xor_sync(0xffu, v, o);
        if (threadIdx.x == 0) sh[0] = v;
    }
    __syncthreads();
    float r = sh[0];
    __syncthreads();
    return r;
}
__device__ __forceinline__ float blockReduceMax(float v, float* sh) {
    #pragma unroll
    for (int o = 16; o; o >>= 1) v = fmaxf(v, __shfl_xor_sync(0xffffffffu, v, o));
    int w = threadIdx.x >> 5;
    if ((threadIdx.x & 31) == 0) sh[w] = v;
    __syncthreads();
    if (threadIdx.x < 8) {
        v = sh[threadIdx.x];
        #pragma unroll
        for (int o = 4; o; o >>= 1) v = fmaxf(v, __shfl_xor_sync(0xffu, v, o));
        if (threadIdx.x == 0) sh[0] = v;
    }
    __syncthreads();
    float r = sh[0];
    __syncthreads();
    return r;
}

__device__ __forceinline__ void mma16816(float* c, const unsigned* a, const unsigned* b) {
    asm volatile(
        "mma.sync.aligned.m16n8k16.row.col.f32.bf16.bf16.f32 "
        "{%0,%1,%2,%3},{%4,%5,%6,%7},{%8,%9},{%0,%1,%2,%3};\n"
        : "+f"(c[0]), "+f"(c[1]), "+f"(c[2]), "+f"(c[3])
        : "r"(a[0]), "r"(a[1]), "r"(a[2]), "r"(a[3]), "r"(b[0]), "r"(b[1]));
}
__device__ __forceinline__ void ldsm4(unsigned& r0, unsigned& r1, unsigned& r2, unsigned& r3,
                                      uint32_t addr) {
    asm volatile("ldmatrix.sync.aligned.m8n8.x4.shared.b16 {%0,%1,%2,%3}, [%4];\n"
                 : "=r"(r0), "=r"(r1), "=r"(r2), "=r"(r3) : "r"(addr));
}
__device__ __forceinline__ void ldsm4t(unsigned& r0, unsigned& r1, unsigned& r2, unsigned& r3,
                                       uint32_t addr) {
    asm volatile("ldmatrix.sync.aligned.m8n8.x4.trans.shared.b16 {%0,%1,%2,%3}, [%4];\n"
                 : "=r"(r0), "=r"(r1), "=r"(r2), "=r"(r3) : "r"(addr));
}

// ---------------- A-hi x B-dual tensor-core GEMM (2 MMAs/tile, cp.async pipelined) ----------------
template<int BN, int WROWS, int WCOLS>
__global__ void __launch_bounds__(256) gemm_tc(
    const bf16* __restrict__ A, const bf16* __restrict__ B,
    long long aPlane, long long bPlane,
    float* __restrict__ C, bf16* __restrict__ D, long long dPlane,
    bf16* __restrict__ D2, long long d2Plane,
    int Mn, int Kn, int lda, int ldb, int ldc,
    long long aOuter, long long aInner, int aCnt,
    long long bOuter, long long bInner, int bCnt,
    long long cStride, float alpha, const float* __restrict__ bias,
    int relu, int accum, int transB, int splitK, long long partStride,
    float diagVal, float diag2)
{
    constexpr int WM = BM / WROWS;
    constexpr int WN = BN / WCOLS;
    constexpr int MT = WM / 16;
    constexpr int NT = WN / 8;
    constexpr int NTP = WN / 16;
    constexpr int KST = BN + 8;
    constexpr int ASTG = BM * 40;
    constexpr int BSTG = 2 * BN * 40;

    int bz = blockIdx.z;
    int batch = bz / splitK;
    int split = bz - batch * splitK;
    const bf16* Ab = A + (long long)(batch / aCnt) * aOuter + (long long)(batch % aCnt) * aInner;
    const bf16* Bb = B + (long long)(batch / bCnt) * bOuter + (long long)(batch % bCnt) * bInner;
    long long cOff = (long long)batch * cStride + (long long)split * partStride;
    int kPer = Kn / splitK;
    int kStart = split * kPer;

    __shared__ __align__(16) bf16 sA[2 * ASTG];
    __shared__ __align__(16) bf16 sB[2 * BSTG];
    uint32_t saBase = (uint32_t)__cvta_generic_to_shared(sA);
    uint32_t sbBase = (uint32_t)__cvta_generic_to_shared(sB);

    int tid = threadIdx.x;
    int lane = tid & 31;
    int wid = tid >> 5;
    int lt = lane & 7;
    int lg = lane >> 3;
    int warpM = (wid / WCOLS) * WM;
    int warpN = (wid % WCOLS) * WN;
    int rowBase = blockIdx.y * BM;
    int colBase = blockIdx.x * BN;

    float acc[MT][NT][4];
    #pragma unroll
    for (int i = 0; i < MT; i++)
        #pragma unroll
        for (int j = 0; j < NT; j++)
            #pragma unroll
            for (int e = 0; e < 4; e++) acc[i][j][e] = 0.f;

    auto issue = [&](int k0, int stg) {
        uint32_t sa = saBase + stg * ASTG * 2;
        uint32_t sb = sbBase + stg * BSTG * 2;
        #pragma unroll
        for (int j = 0; j < 2; j++) {
            int id = tid + j * 256;
            int row = id >> 2, seg = id & 3;
            int gr = rowBase + row;
            bool ok = gr < Mn;
            const bf16* src = Ab + (long long)(ok ? gr : 0) * lda + kStart + k0 + seg * 8;
            cpa16(sa + ((row * 40 + seg * 8) << 1), src, ok);
        }
        if (transB) {
            #pragma unroll
            for (int p = 0; p < 2; p++)
                #pragma unroll
                for (int j = 0; j < BN / 64; j++) {
                    int id = tid + j * 256;
                    int row = id >> 2, seg = id & 3;
                    const bf16* src = Bb + p * bPlane +
                                      (long long)(colBase + row) * ldb + kStart + k0 + seg * 8;
                    cpa16(sb + (((p * BN + row) * 40 + seg * 8) << 1), src, true);
                }
        } else {
            #pragma unroll
            for (int p = 0; p < 2; p++)
                #pragma unroll
                for (int j = 0; j < BN / 64; j++) {
                    int id = tid + j * 256;
                    int k = id / (BN / 8), seg = id % (BN / 8);
                    const bf16* src = Bb + p * bPlane +
                                      (long long)(kStart + k0 + k) * ldb + colBase + seg * 8;
                    cpa16(sb + (((p * 32 + k) * KST + seg * 8) << 1), src, true);
                }
        }
        cpa_commit();
    };

    int nIter = kPer / BK;
    issue(0, 0);

    for (int it = 0; it < nIter; it++) {
        int cur = it & 1;
        asm volatile("cp.async.wait_group 0;\n");
        __syncthreads();
        if (it + 1 < nIter) issue((it + 1) * BK, cur ^ 1);

        uint32_t saS = saBase + cur * ASTG * 2;
        uint32_t sbS = sbBase + cur * BSTG * 2;

        #pragma unroll
        for (int ks = 0; ks < 2; ks++) {
            int k8 = ks * 16;
            unsigned bh[NTP][4], bl[NTP][4];
            #pragma unroll
            for (int ntp = 0; ntp < NTP; ntp++) {
                if (transB) {
                    int n = warpN + ntp * 16 + lt + ((lg >> 1) << 3);
                    int kk = k8 + ((lg & 1) << 3);
                    ldsm4(bh[ntp][0], bh[ntp][1], bh[ntp][2], bh[ntp][3],
                          sbS + (((0 * BN + n) * 40 + kk) << 1));
                    ldsm4(bl[ntp][0], bl[ntp][1], bl[ntp][2], bl[ntp][3],
                          sbS + (((1 * BN + n) * 40 + kk) << 1));
                } else {
                    int k = k8 + lt + ((lg & 1) << 3);
                    int n = warpN + ntp * 16 + ((lg >> 1) << 3);
                    ldsm4t(bh[ntp][0], bh[ntp][1], bh[ntp][2], bh[ntp][3],
                           sbS + (((0 * 32 + k) * KST + n) << 1));
                    ldsm4t(bl[ntp][0], bl[ntp][1], bl[ntp][2], bl[ntp][3],
                           sbS + (((1 * 32 + k) * KST + n) << 1));
                }
            }
            #pragma unroll
            for (int mt = 0; mt < MT; mt++) {
                unsigned ah[4];
                int m = warpM + mt * 16 + lt + ((lg & 1) << 3);
                int kk = k8 + ((lg >> 1) << 3);
                ldsm4(ah[0], ah[1], ah[2], ah[3],
                      saS + ((m * 40 + kk) << 1));
                #pragma unroll
                for (int nt = 0; nt < NT; nt++) {
                    const unsigned* ph = &bh[nt >> 1][(nt & 1) * 2];
                    const unsigned* pl = &bl[nt >> 1][(nt & 1) * 2];
                    mma16816(acc[mt][nt], ah, ph);
                    mma16816(acc[mt][nt], ah, pl);
                }
            }
        }
        __syncthreads();
    }

    int q = lane & 3, g = lane >> 2;
    float* Cb = C ? C + cOff : nullptr;
    bf16* Db = D ? D + cOff : nullptr;
    bf16* D2b = D2 ? D2 + cOff : nullptr;
    #pragma unroll
    for (int mt = 0; mt < MT; mt++) {
        #pragma unroll
        for (int nt = 0; nt < NT; nt++) {
            int r0 = rowBase + warpM + mt * 16 + g;
            int c0 = colBase + warpN + nt * 8 + q * 2;
            #pragma unroll
            for (int half = 0; half < 2; half++) {
                int gr = r0 + half * 8;
                if (gr >= Mn) continue;
                float v0 = alpha * acc[mt][nt][half * 2 + 0];
                float v1 = alpha * acc[mt][nt][half * 2 + 1];
                if (gr == c0)     v0 += diagVal;
                if (gr == c0 + 1) v1 += diagVal;
                long long off = (long long)gr * ldc + c0;
                if (Cb) {
                    float w0 = v0, w1 = v1;
                    if (bias) { w0 += bias[c0]; w1 += bias[c0 + 1]; }
                    if (relu) { w0 = fmaxf(w0, 0.f); w1 = fmaxf(w1, 0.f); }
                    if (accum) { w0 += Cb[off]; w1 += Cb[off + 1]; }
                    *reinterpret_cast<float2*>(Cb + off) = make_float2(w0, w1);
                }
                if (Db) storeDual2(Db, dPlane, off, v0, v1);
                if (D2b) {
                    float u0 = ((gr == c0)     ? diag2 : 0.f) - v0;
                    float u1 = ((gr == c0 + 1) ? diag2 : 0.f) - v1;
                    storeDual2(D2b, d2Plane, off, u0, u1);
                }
            }
        }
    }
}

// ---------------- fused flash attention (Q-hi, K/V-dual, 2 MMAs/tile) ----------------
#define FA_K    9216
#define FA_V    27648
#define FA_SMEM_BYTES (46080 * 2)

template<int MODE>
__global__ void __launch_bounds__(256) flash_kernel(
    const bf16* __restrict__ Qa, long long qPlane, int qStride,
    long long qOuter, long long qInner, int qCnt,
    const bf16* __restrict__ Ka, long long kPlane, int kStride,
    long long kOuter, long long kInner, int kCnt,
    const bf16* __restrict__ Va, long long vPlane, int vStride,
    long long vOuter, long long vInner, int vCnt,
    int keysPerSplit,
    float* __restrict__ PO, float* __restrict__ PM, float* __restrict__ PS,
    const float* __restrict__ CONV, bf16* __restrict__ CATD, long long catPlane)
{
    extern __shared__ __align__(16) bf16 fsm[];
    uint32_t smBase = (uint32_t)__cvta_generic_to_shared(fsm);
    int tid = threadIdx.x, lane = tid & 31, wid = tid >> 5;
    int lt = lane & 7, lg = lane >> 3, g = lane >> 2, q = lane & 3;
    int bh = blockIdx.z, split = blockIdx.y;
    int rowBase = blockIdx.x * 128;
    const bf16* Q = Qa + (long long)(bh / qCnt) * qOuter + (long long)(bh % qCnt) * qInner;
    const bf16* K = Ka + (long long)(bh / kCnt) * kOuter + (long long)(bh % kCnt) * kInner
                       + (long long)split * keysPerSplit * kStride;
    const bf16* V = Va + (long long)(bh / vCnt) * vOuter + (long long)(bh % vCnt) * vInner
                       + (long long)split * keysPerSplit * vStride;

    #pragma unroll
    for (int j = 0; j < 4; j++) {
        int c = tid + j * 256;
        int row = c >> 3, seg = c & 7;
        cpa16(smBase + ((row * 72 + seg * 8) << 1),
              Q + (long long)(rowBase + row) * qStride + seg * 8, true);
    }
    auto issueKV = [&](int t, int stg) {
        int key0 = t * 64;
        #pragma unroll
        for (int j = 0; j < 2; j++) {
            int c = tid + j * 256;
            int p = c >> 8, rem = c & 255;
            int row = rem >> 2, seg = rem & 3;
            cpa16(smBase + ((FA_K + stg * 9216 + (p * 64 + row) * 72 + seg * 16) << 1),
                  K + (long long)p * kPlane + (long long)(key0 + row) * kStride + seg * 16, true);
            cpa16(smBase + ((FA_K + stg * 9216 + (p * 64 + row) * 72 + seg * 16 + 8) << 1),
                  K + (long long)p * kPlane + (long long)(key0 + row) * kStride + seg * 16 + 8, true);
            cpa16(smBase + ((FA_V + stg * 9216 + (p * 64 + row) * 72 + seg * 16) << 1),
                  V + (long long)p * vPlane + (long long)(key0 + row) * vStride + seg * 16, true);
            cpa16(smBase + ((FA_V + stg * 9216 + (p * 64 + row) * 72 + seg * 16 + 8) << 1),
                  V + (long long)p * vPlane + (long long)(key0 + row) * vStride + seg * 16 + 8, true);
        }
        cpa_commit();
    };
    issueKV(0, 0);

    int warpRow = wid * 16;
    unsigned qh[4][4];
    float o[8][4];
    #pragma unroll
    for (int i = 0; i < 8; i++)
        #pragma unroll
        for (int e = 0; e < 4; e++) o[i][e] = 0.f;
    float m0 = -1e30f, m1 = -1e30f, l0 = 0.f, l1 = 0.f;

    int nTiles = keysPerSplit / 64;
    for (int t = 0; t < nTiles; t++) {
        int stg = t & 1;
        bool more = (t + 1 < nTiles);
        if (more) {
            issueKV(t + 1, stg ^ 1);
            asm volatile("cp.async.wait_group 1;\n");
        } else {
            asm volatile("cp.async.wait_group 0;\n");
        }
        __syncthreads();
        if (t == 0) {
            #pragma unroll
            for (int kc = 0; kc < 4; kc++) {
                int row = warpRow + lt + ((lg & 1) << 3);
                int kk = kc * 16 + ((lg >> 1) << 3);
                ldsm4(qh[kc][0], qh[kc][1], qh[kc][2], qh[kc][3],
                      smBase + ((row * 72 + kk) << 1));
            }
        }
        uint32_t skS = smBase + ((FA_K + stg * 9216) << 1);
        uint32_t svS = smBase + ((FA_V + stg * 9216) << 1);

        float sc[8][4];
        #pragma unroll
        for (int i = 0; i < 8; i++)
            #pragma unroll
            for (int e = 0; e < 4; e++) sc[i][e] = 0.f;
        #pragma unroll
        for (int kc = 0; kc < 4; kc++) {
            unsigned kh[4][4], kl[4][4];
            #pragma unroll
            for (int ntp = 0; ntp < 4; ntp++) {
                int n = ntp * 16 + lt + ((lg >> 1) << 3);
                int kk = kc * 16 + ((lg & 1) << 3);
                ldsm4(kh[ntp][0], kh[ntp][1], kh[ntp][2], kh[ntp][3],
                      skS + (((0 * 64 + n) * 72 + kk) << 1));
                ldsm4(kl[ntp][0], kl[ntp][1], kl[ntp][2], kl[ntp][3],
                      skS + (((64 + n) * 72 + kk) << 1));
            }
            #pragma unroll
            for (int nt = 0; nt < 8; nt++) {
                const unsigned* bhf = &kh[nt >> 1][(nt & 1) * 2];
                const unsigned* blf = &kl[nt >> 1][(nt & 1) * 2];
                mma16816(sc[nt], qh[kc], bhf);
                mma16816(sc[nt], qh[kc], blf);
            }
        }
        float mt0 = -1e30f, mt1 = -1e30f;
        #pragma unroll
        for (int nt = 0; nt < 8; nt++) {
            #pragma unroll
            for (int e = 0; e < 4; e++) sc[nt][e] *= 0.125f;
            mt0 = fmaxf(mt0, fmaxf(sc[nt][0], sc[nt][1]));
            mt1 = fmaxf(mt1, fmaxf(sc[nt][2], sc[nt][3]));
        }
        mt0 = fmaxf(mt0, __shfl_xor_sync(0xffffffffu, mt0, 1));
        mt0 = fmaxf(mt0, __shfl_xor_sync(0xffffffffu, mt0, 2));
        mt1 = fmaxf(mt1, __shfl_xor_sync(0xffffffffu, mt1, 1));
        mt1 = fmaxf(mt1, __shfl_xor_sync(0xffffffffu, mt1, 2));
        float mn0 = fmaxf(m0, mt0), mn1 = fmaxf(m1, mt1);
        float f0 = __expf(m0 - mn0), f1 = __expf(m1 - mn1);
        m0 = mn0; m1 = mn1;
        float rs0 = 0.f, rs1 = 0.f;
        #pragma unroll
        for (int nt = 0; nt < 8; nt++) {
            sc[nt][0] = __expf(sc[nt][0] - mn0);
            sc[nt][1] = __expf(sc[nt][1] - mn0);
            sc[nt][2] = __expf(sc[nt][2] - mn1);
            sc[nt][3] = __expf(sc[nt][3] - mn1);
            rs0 += sc[nt][0] + sc[nt][1];
            rs1 += sc[nt][2] + sc[nt][3];
        }
        rs0 += __shfl_xor_sync(0xffffffffu, rs0, 1);
        rs0 += __shfl_xor_sync(0xffffffffu, rs0, 2);
        rs1 += __shfl_xor_sync(0xffffffffu, rs1, 1);
        rs1 += __shfl_xor_sync(0xffffffffu, rs1, 2);
        l0 = l0 * f0 + rs0;
        l1 = l1 * f1 + rs1;
        #pragma unroll
        for (int nt = 0; nt < 8; nt++) {
            o[nt][0] *= f0; o[nt][1] *= f0;
            o[nt][2] *= f1; o[nt][3] *= f1;
        }
        #pragma unroll
        for (int kc = 0; kc < 4; kc++) {
            unsigned ph[4];
            __nv_bfloat162 t0 = __floats2bfloat162_rn(sc[2 * kc][0], sc[2 * kc][1]);
            __nv_bfloat162 t1 = __floats2bfloat162_rn(sc[2 * kc][2], sc[2 * kc][3]);
            __nv_bfloat162 t2 = __floats2bfloat162_rn(sc[2 * kc + 1][0], sc[2 * kc + 1][1]);
            __nv_bfloat162 t3 = __floats2bfloat162_rn(sc[2 * kc + 1][2], sc[2 * kc + 1][3]);
            ph[0] = *reinterpret_cast<unsigned*>(&t0);
            ph[1] = *reinterpret_cast<unsigned*>(&t1);
            ph[2] = *reinterpret_cast<unsigned*>(&t2);
            ph[3] = *reinterpret_cast<unsigned*>(&t3);
            unsigned vh[4][4], vl[4][4];
            #pragma unroll
            for (int ntp = 0; ntp < 4; ntp++) {
                int k = kc * 16 + lt + ((lg & 1) << 3);
                int n = ntp * 16 + ((lg >> 1) << 3);
                ldsm4t(vh[ntp][0], vh[ntp][1], vh[ntp][2], vh[ntp][3],
                       svS + (((0 * 64 + k) * 72 + n) << 1));
                ldsm4t(vl[ntp][0], vl[ntp][1], vl[ntp][2], vl[ntp][3],
                       svS + (((64 + k) * 72 + n) << 1));
            }
            #pragma unroll
            for (int nt = 0; nt < 8; nt++) {
                const unsigned* bhf = &vh[nt >> 1][(nt & 1) * 2];
                const unsigned* blf = &vl[nt >> 1][(nt & 1) * 2];
                mma16816(o[nt], ph, bhf);
                mma16816(o[nt], ph, blf);
            }
        }
        __syncthreads();
    }

    int row0 = rowBase + warpRow + g;
    int row1 = row0 + 8;
    if (MODE == 1) {
        float i0 = 1.f / l0, i1 = 1.f / l1;
        int b = bh >> 3, hh = bh & 7;
        const float* Cv = CONV + (long long)bh * NPAD * 64;
        #pragma unroll
        for (int nt = 0; nt < 8; nt++) {
            int col = nt * 8 + q * 2;
            float2 c0 = *(const float2*)&Cv[(long long)row0 * 64 + col];
            float2 c1 = *(const float2*)&Cv[(long long)row1 * 64 + col];
            long long i0d = ((long long)b * NPAD + row0) * DM + hh * 64 + col;
            long long i1d = ((long long)b * NPAD + row1) * DM + hh * 64 + col;
            storeHi2(CATD, i0d, o[nt][0] * i0 + c0.x, o[nt][1] * i0 + c0.y);
            storeHi2(CATD, i1d, o[nt][2] * i1 + c1.x, o[nt][3] * i1 + c1.y);
        }
    } else {
        long long pb = ((long long)split * BHN + bh) * NLM;
        #pragma unroll
        for (int nt = 0; nt < 8; nt++) {
            int col = nt * 8 + q * 2;
            *(float2*)&PO[(pb + row0) * 64 + col] = make_float2(o[nt][0], o[nt][1]);
            *(float2*)&PO[(pb + row1) * 64 + col] = make_float2(o[nt][2], o[nt][3]);
        }
        if (q == 0) {
            PM[pb + row0] = m0; PM[pb + row1] = m1;
            PS[pb + row0] = l0; PS[pb + row1] = l1;
        }
    }
}

__global__ void fa_combine(const float* __restrict__ po, const float* __restrict__ pm,
                           const float* __restrict__ ps, bf16* __restrict__ outd,
                           long long plane) {
    long long idx = (long long)blockIdx.x * 256 + threadIdx.x;
    int d = (int)(idx & 63);
    long long rid = idx >> 6;
    const long long RS = (long long)BHN * NLM;
    float M = -1e30f;
    #pragma unroll
    for (int s = 0; s < NSPLIT; s++) M = fmaxf(M, pm[s * RS + rid]);
    float S = 0.f, val = 0.f;
    #pragma unroll
    for (int s = 0; s < NSPLIT; s++) {
        float e = __expf(pm[s * RS + rid] - M);
        S += ps[s * RS + rid] * e;
        val += po[(s * RS + rid) * 64 + d] * e;
    }
    storeDual1(outd, plane, rid * 64 + d, val / S);
}

// ---------------- misc kernels ----------------
__global__ void tobf16_kernel(const float* __restrict__ x, bf16* __restrict__ d,
                              long long n, long long plane) {
    long long i = (long long)blockIdx.x * 256 + threadIdx.x;
    if (i >= n) return;
    storeDual1(d, plane, i, x[i]);
}
__global__ void tobf16hi_kernel(const float* __restrict__ x, bf16* __restrict__ d,
                                long long n) {
    long long i = (long long)blockIdx.x * 256 + threadIdx.x;
    if (i >= n) return;
    d[i] = __float2bfloat16(x[i]);
}

__global__ void init_h_kernel(const float* __restrict__ cls, float* __restrict__ h) {
    int r = blockIdx.x, b = blockIdx.y;
    float* o = h + ((long long)b * NPAD + r) * DM;
    for (int i = threadIdx.x; i < DM; i += 256) o[i] = (r == PADN) ? cls[i] : 0.f;
}

__global__ void layernorm_kernel(const float* __restrict__ in, bf16* __restrict__ xd,
                                 const float* __restrict__ gam, const float* __restrict__ bet) {
    __shared__ float sh[8];
    long long row = blockIdx.x;
    int r = (int)(row % NPAD);
    int tid = threadIdx.x;
    long long idx = row * DM + tid * 2;
    if (r < PADN) {
        storeHi2(xd, idx, 0.f, 0.f);
        return;
    }
    const float2* x = (const float2*)(in + row * DM);
    float2 v = x[tid];
    float s = v.x + v.y;
    float s2 = v.x * v.x + v.y * v.y;
    s = blockReduceSum(s, sh);
    s2 = blockReduceSum(s2, sh);
    float mean = s / DM;
    float var = s2 / DM - mean * mean;
    float inv = rsqrtf(var + 1e-5f);
    float2 gv = ((const float2*)gam)[tid];
    float2 bv = ((const float2*)bet)[tid];
    storeHi2(xd, idx,
             (v.x - mean) * inv * gv.x + bv.x,
             (v.y - mean) * inv * gv.y + bv.y);
}

__global__ void landmark_kernel(const bf16* __restrict__ qkvd, long long qkvPlane,
                                bf16* __restrict__ qld, bf16* __restrict__ kld,
                                long long kplane) {
    int m = blockIdx.x, bh = blockIdx.y;
    int b = bh >> 3, h = bh & 7;
    int d = threadIdx.x;
    long long base = (long long)b * NPAD * TD + (long long)m * LPER * TD + h * 64 + d;
    float sq = 0.f, sk = 0.f;
    #pragma unroll 4
    for (int r = 0; r < LPER; r++) {
        long long i = base + (long long)r * TD;
        sq += loadDual(qkvd, qkvPlane, i);
        sk += loadDual(qkvd, qkvPlane, i + 512);
    }
    long long idx = ((long long)bh * NLM + m) * DH + d;
    qld[idx] = __float2bfloat16(sq * (1.f / LPER));
    storeDual1(kld, kplane, idx, sk * (1.f / LPER));
}

__global__ void softmax256(const float* __restrict__ in, float* __restrict__ out32,
                           bf16* __restrict__ dual, long long plane, long long nrows) {
    long long row = (long long)blockIdx.x * 8 + (threadIdx.x >> 5);
    if (row >= nrows) return;
    int lane = threadIdx.x & 31;
    const float4* pi = (const float4*)(in + row * 256);
    float4 v0 = pi[lane];
    float4 v1 = pi[lane + 32];
    float m = fmaxf(fmaxf(fmaxf(v0.x, v0.y), fmaxf(v0.z, v0.w)),
                    fmaxf(fmaxf(v1.x, v1.y), fmaxf(v1.z, v1.w)));
    #pragma unroll
    for (int o = 16; o; o >>= 1) m = fmaxf(m, __shfl_xor_sync(0xffffffffu, m, o));
    v0.x = __expf(v0.x - m); v0.y = __expf(v0.y - m);
    v0.z = __expf(v0.z - m); v0.w = __expf(v0.w - m);
    v1.x = __expf(v1.x - m); v1.y = __expf(v1.y - m);
    v1.z = __expf(v1.z - m); v1.w = __expf(v1.w - m);
    float s = v0.x + v0.y + v0.z + v0.w + v1.x + v1.y + v1.z + v1.w;
    #pragma unroll
    for (int o = 16; o; o >>= 1) s += __shfl_xor_sync(0xffffffffu, s, o);
    float inv = 1.f / s;
    v0.x *= inv; v0.y *= inv; v0.z *= inv; v0.w *= inv;
    v1.x *= inv; v1.y *= inv; v1.z *= inv; v1.w *= inv;
    if (out32) {
        ((float4*)(out32 + row * 256))[lane] = v0;
        ((float4*)(out32 + row * 256))[lane + 32] = v1;
    }
    long long b0 = row * 256 + lane * 4;
    storeDual2(dual, plane, b0, v0.x, v0.y);
    storeDual2(dual, plane, b0 + 2, v0.z, v0.w);
    storeDual2(dual, plane, b0 + 128, v1.x, v1.y);
    storeDual2(dual, plane, b0 + 130, v1.z, v1.w);
}

__global__ void reset_kernel() {
    if (threadIdx.x == 0) { g_maxrow = 0; g_maxcol = 0; }
}

__global__ void a2stats_kernel(const float* __restrict__ a2) {
    __shared__ float sh[8];
    int bh = blockIdx.x;
    const float* a = a2 + (long long)bh * MM;
    int j = threadIdx.x;
    float cs = 0.f, rs = 0.f;
    for (int i = 0; i < NLM; i++) cs += a[(long long)i * NLM + j];
    const float* row = a + (long long)j * NLM;
    for (int i = 0; i < NLM; i++) rs += row[i];
    float cmax = blockReduceMax(cs, sh);
    float rmax = blockReduceMax(rs, sh);
    if (threadIdx.x == 0) {
        atomicMax(&g_maxcol, __float_as_int(cmax));
        atomicMax(&g_maxrow, __float_as_int(rmax));
    }
}

__global__ void z0_kernel(const float* __restrict__ a2, bf16* __restrict__ zp, long long plane) {
    __shared__ float tile[32][33];
    int bh = blockIdx.z;
    const float* a = a2 + (long long)bh * MM;
    long long zbase = (long long)bh * MM;
    float inv = 1.f / (__int_as_float(g_maxrow) * __int_as_float(g_maxcol));
    int i0 = blockIdx.y * 32, j0 = blockIdx.x * 32;
    for (int r = threadIdx.y; r < 32; r += 8)
        tile[r][threadIdx.x] = a[(long long)(i0 + r) * NLM + j0 + threadIdx.x];
    __syncthreads();
    for (int r = threadIdx.y; r < 32; r += 8)
        storeDual1(zp, plane, zbase + (long long)(j0 + r) * NLM + i0 + threadIdx.x,
                   tile[threadIdx.x][r] * inv);
}

__global__ void conv_kernel(const bf16* __restrict__ qkvd, long long qkvPlane,
                            const float* __restrict__ w, float* __restrict__ outh) {
    int bh = blockIdx.y;
    int b = bh >> 3, h = bh & 7;
    int iBase = blockIdx.x * 64;
    __shared__ float sv[96][64];
    __shared__ float sw[CONVK];
    long long vbase = (long long)b * NPAD * TD + 1024 + h * 64;
    int tid = threadIdx.x;
    for (int idx = tid; idx < 96 * 64; idx += 256) {
        int r = idx >> 6, d = idx & 63;
        int gi = iBase - 16 + r;
        sv[r][d] = (gi >= 0 && gi < NPAD)
                   ? loadDual(qkvd, qkvPlane, vbase + (long long)gi * TD + d) : 0.f;
    }
    if (tid < CONVK) sw[tid] = w[h * CONVK + tid];
    __syncthreads();
    float* out = outh + (long long)bh * NPAD * DH + (long long)iBase * DH;
    for (int idx = tid; idx < 64 * 64; idx += 256) {
        int r = idx >> 6, d = idx & 63;
        float s = 0.f;
        #pragma unroll
        for (int t = 0; t < CONVK; t++) s += sw[t] * sv[r + t][d];
        out[r * 64 + d] = s;
    }
}

__global__ void final_kernel(const float* __restrict__ h, const float* __restrict__ gam,
                             const float* __restrict__ bet, const float* __restrict__ w2,
                             const float* __restrict__ b2, float* __restrict__ out) {
    __shared__ float sh[8];
    int b = blockIdx.x;
    const float* x = h + ((long long)b * NPAD + PADN) * DM;
    float s = 0.f, s2 = 0.f;
    for (int i = threadIdx.x; i < DM; i += 256) { float v = x[i]; s += v; s2 += v * v; }
    s = blockReduceSum(s, sh);
    s2 = blockReduceSum(s2, sh);
    float mean = s / DM;
    float var = s2 / DM - mean * mean;
    float inv = rsqrtf(var + 1e-5f);
    float p0 = 0.f, p1 = 0.f;
    for (int i = threadIdx.x; i < DM; i += 256) {
        float hn = (x[i] - mean) * inv * gam[i] + bet[i];
        p0 += hn * w2[2 * i];
        p1 += hn * w2[2 * i + 1];
    }
    p0 = blockReduceSum(p0, sh);
    p1 = blockReduceSum(p1, sh);
    if (threadIdx.x == 0) {
        float l0 = p0 + b2[0], l1 = p1 + b2[1];
        float mx = fmaxf(l0, l1);
        float e0 = expf(l0 - mx), e1 = expf(l1 - mx);
        float si = 1.f / (e0 + e1);
        out[b * 2 + 0] = l0;
        out[b * 2 + 1] = l1;
        out[4 + b * 2 + 0] = e0 * si;
        out[4 + b * 2 + 1] = e1 * si;
        out[8 + b] = (l1 > l0) ? 1.f : 0.f;
    }
}

// ---------------- host side ----------------
static void launch_gemm(cudaStream_t st, int bn, const bf16* A, const bf16* B,
                        long long aPlane, long long bPlane,
                        float* C, bf16* D, long long dPlane, bf16* D2, long long d2Plane,
                        int M, int N, int K, int lda, int ldb, int ldc,
                        long long aO, long long aI, int aC,
                        long long bO, long long bI, int bC,
                        long long cS, int batches, float alpha,
                        const float* bias, int relu, int accum, int transB,
                        int splitK = 1, long long partStride = 0,
                        float diagVal = 0.f, float diag2 = 0.f) {
    dim3 grid(N / bn, (M + BM - 1) / BM, batches * splitK);
    if (bn == 128)
        gemm_tc<128, 2, 4><<<grid, 256, 0, st>>>(A, B, aPlane, bPlane, C, D, dPlane, D2, d2Plane,
                                                 M, K, lda, ldb, ldc, aO, aI, aC, bO, bI, bC,
                                                 cS, alpha, bias, relu, accum, transB,
                                                 splitK, partStride, diagVal, diag2);
    else
        gemm_tc<64, 4, 2><<<grid, 256, 0, st>>>(A, B, aPlane, bPlane, C, D, dPlane, D2, d2Plane,
                                                M, K, lda, ldb, ldc, aO, aI, aC, bO, bI, bC,
                                                cS, alpha, bias, relu, accum, transB,
                                                splitK, partStride, diagVal, diag2);
}

// streams/events created once at static-init time
struct SideStream {
    cudaStream_t sB;
    cudaEvent_t eF, eL[2], eB[2], eW;
    SideStream() {
        cudaStreamCreateWithFlags(&sB, cudaStreamNonBlocking);
        cudaEventCreateWithFlags(&eF, cudaEventDisableTiming);
        for (int i = 0; i < 2; i++) {
            cudaEventCreateWithFlags(&eL[i], cudaEventDisableTiming);
            cudaEventCreateWithFlags(&eB[i], cudaEventDisableTiming);
        }
        cudaEventCreateWithFlags(&eW, cudaEventDisableTiming);
    }
};
static SideStream g_ss;

#define SYMF(p, s) do { void* _t; cudaGetSymbolAddress(&_t, s); p = (float*)_t; } while (0)
#define SYMB(p, s) do { void* _t; cudaGetSymbolAddress(&_t, s); p = (bf16*)_t; } while (0)

extern "C" void kernel_launch(void* const* d_in, const int* in_sizes, int n_in,
                              void* d_out, int out_size) {
    const float* feats = (const float*)d_in[0];
    const float* fc1_w = (const float*)d_in[1];
    const float* fc1_b = (const float*)d_in[2];
    const float* cls   = (const float*)d_in[3];
    const float* lng[2]   = {(const float*)d_in[4],  (const float*)d_in[10]};
    const float* lnb[2]   = {(const float*)d_in[5],  (const float*)d_in[11]};
    const float* qkvw[2]  = {(const float*)d_in[6],  (const float*)d_in[12]};
    const float* outw[2]  = {(const float*)d_in[7],  (const float*)d_in[13]};
    const float* outb[2]  = {(const float*)d_in[8],  (const float*)d_in[14]};
    const float* convw[2] = {(const float*)d_in[9],  (const float*)d_in[15]};
    const float* nfg  = (const float*)d_in[16];
    const float* nfb  = (const float*)d_in[17];
    const float* fc2w = (const float*)d_in[18];
    const float* fc2b = (const float*)d_in[19];

    float *h, *a2, *outh, *po, *pm, *ps;
    SYMF(h, g_h); SYMF(a2, g_a2); SYMF(outh, g_outh);
    SYMF(po, g_po); SYMF(pm, g_pm); SYMF(ps, g_ps);
    bf16 *featsd, *w1d, *qkvwd, *outwd, *xlnd, *qkvd, *qld, *kld, *a2d;
    bf16 *zpd, *zp2d, *t1d, *t2d, *t3d, *a3vd, *wd, *catd;
    SYMB(featsd, g_featsd); SYMB(w1d, g_w1d); SYMB(qkvwd, g_qkvwd); SYMB(outwd, g_outwd);
    SYMB(xlnd, g_xlnd); SYMB(qkvd, g_qkvd); SYMB(qld, g_qld); SYMB(kld, g_kld);
    SYMB(a2d, g_a2d);
    SYMB(zpd, g_zpd); SYMB(zp2d, g_zp2d); SYMB(t1d, g_t1d); SYMB(t2d, g_t2d); SYMB(t3d, g_t3d);
    SYMB(a3vd, g_a3vd); SYMB(wd, g_wd); SYMB(catd, g_catd);

    const long long featsPlane = (long long)BATCH * NTOK * DIN;
    const long long qkvPlane   = (long long)BATCH * NPAD * TD;
    const long long qlPlane    = (long long)BHN * NLM * DH;
    const long long a2Plane    = (long long)BHN * MM;
    const long long zpPlane    = 32LL * MM;
    const long long t16Plane   = 16LL * MM;
    const long long avPlane    = (long long)BHN * NLM * DH;

    cudaFuncSetAttribute(flash_kernel<0>, cudaFuncAttributeMaxDynamicSharedMemorySize, FA_SMEM_BYTES);
    cudaFuncSetAttribute(flash_kernel<1>, cudaFuncAttributeMaxDynamicSharedMemorySize, FA_SMEM_BYTES);

    cudaStream_t sB = g_ss.sB;

    // fork side stream from capture origin FIRST (legal capture fork)
    cudaEventRecord(g_ss.eF, 0);
    cudaStreamWaitEvent(sB, g_ss.eF, 0);

    // input conversions: feats+fc1w on main (fc1 deps), layer weights on side (overlap fc1)
    tobf16hi_kernel<<<(unsigned)((featsPlane + 255) / 256), 256>>>(feats, featsd, featsPlane);
    tobf16_kernel<<<(DIN * DM + 255) / 256, 256>>>(fc1_w, w1d, DIN * DM, DIN * DM);
    for (int l = 0; l < 2; l++) {
        tobf16_kernel<<<(DM * TD + 255) / 256, 256, 0, sB>>>(
            qkvw[l], qkvwd + (long long)l * 2 * DM * TD, DM * TD, DM * TD);
        tobf16_kernel<<<(DM * DM + 255) / 256, 256, 0, sB>>>(
            outw[l], outwd + (long long)l * 2 * DM * DM, DM * DM, DM * DM);
    }
    cudaEventRecord(g_ss.eW, sB);

    init_h_kernel<<<dim3(PADN + 1, BATCH), 256>>>(cls, h);

    // fc1 + relu (overlaps side-stream weight conversions)
    launch_gemm(0, 128, featsd, w1d, 0, DIN * DM,
                h + (long long)(PADN + 1) * DM, nullptr, 0, nullptr, 0,
                NTOK, DM, DIN, DIN, DM, DM,
                (long long)NTOK * DIN, 0, 1, 0, 0, 1,
                (long long)NPAD * DM, BATCH, 1.f, fc1_b, 1, 0, 0);

    cudaStreamWaitEvent(0, g_ss.eW, 0);

    for (int l = 0; l < 2; l++) {
        layernorm_kernel<<<BATCH * NPAD, 256>>>(h, xlnd, lng[l], lnb[l]);

        // qkv = xln @ qkvw  (dual output only)
        launch_gemm(0, 128, xlnd, qkvwd + (long long)l * 2 * DM * TD, 0, DM * TD,
                    nullptr, qkvd, qkvPlane, nullptr, 0,
                    NPAD, TD, DM, DM, TD, TD,
                    (long long)NPAD * DM, 0, 1, 0, 0, 1,
                    (long long)NPAD * TD, BATCH, 1.f, nullptr, 0, 0, 0);

        landmark_kernel<<<dim3(NLM, BHN), 64>>>(qkvd, qkvPlane, qld, kld, qlPlane);
        cudaEventRecord(g_ss.eL[l], 0);

        // ===== side stream: a2 + fused [z;p] Newton chain (z propagated) =====
        cudaStreamWaitEvent(sB, g_ss.eL[l], 0);
        launch_gemm(sB, 128, qld, kld, 0, qlPlane,
                    a2, nullptr, 0, nullptr, 0,
                    NLM, NLM, DH, DH, DH, NLM,
                    (long long)NLM * DH, 0, 1, (long long)NLM * DH, 0, 1,
                    MM, BHN, 0.125f, nullptr, 0, 0, 1);
        softmax256<<<(BHN * NLM) / 8, 256, 0, sB>>>(a2, a2, a2d, a2Plane, (long long)BHN * NLM);
        reset_kernel<<<1, 32, 0, sB>>>();
        a2stats_kernel<<<BHN, 256, 0, sB>>>(a2);
        z0_kernel<<<dim3(8, 8, BHN), dim3(32, 8), 0, sB>>>(a2, zpd, zpPlane);
        // p0 = a2 @ z0 -> zpd p-half ; t1 = 7I - p0 -> t1d p-half
        launch_gemm(sB, 64, a2d, zpd, a2Plane, zpPlane,
                    nullptr, zpd + 16 * MM, zpPlane, t1d + 16 * MM, zpPlane,
                    NLM, NLM, NLM, NLM, NLM, NLM,
                    MM, 0, 1, MM, 0, 1, MM, BHN, 1.f, nullptr, 0, 0, 0,
                    1, 0, 0.f, 7.f);
        bf16* zpCur = zpd;
        bf16* zpNxt = zp2d;
        for (int it = 0; it < 6; it++) {
            // t2 = 15I - p@t1
            launch_gemm(sB, 64, zpCur + 16 * MM, t1d + 16 * MM, zpPlane, zpPlane,
                        nullptr, nullptr, 0, t2d, t16Plane,
                        NLM, NLM, NLM, NLM, NLM, NLM,
                        MM, 0, 1, MM, 0, 1, MM, BHN, 1.f, nullptr, 0, 0, 0,
                        1, 0, 0.f, 15.f);
            // t3 = 13I - p@t2
            launch_gemm(sB, 64, zpCur + 16 * MM, t2d, zpPlane, t16Plane,
                        nullptr, nullptr, 0, t3d, t16Plane,
                        NLM, NLM, NLM, NLM, NLM, NLM,
                        MM, 0, 1, MM, 0, 1, MM, BHN, 1.f, nullptr, 0, 0, 0,
                        1, 0, 0.f, 13.f);
            // [z';p'] = 0.25 [z;p]@t3 -> zpNxt ; t1' = 7I - [..;p'] (z-half junk)
            launch_gemm(sB, 64, zpCur, t3d, zpPlane, t16Plane,
                        nullptr, zpNxt, zpPlane, t1d, zpPlane,
                        NLM, NLM, NLM, NLM, NLM, NLM,
                        0, MM, 32, 0, MM, 16, MM, 32, 0.25f, nullptr, 0, 0, 0,
                        1, 0, 0.f, 7.f);
            bf16* tp = zpCur; zpCur = zpNxt; zpNxt = tp;
        }
        cudaEventRecord(g_ss.eB[l], sB);

        // ===== main stream: conv + F1 + combine (overlaps with side stream) =====
        conv_kernel<<<dim3(NPAD / 64, BHN), 256>>>(qkvd, qkvPlane, convw[l], outh);

        flash_kernel<0><<<dim3(NLM / 128, NSPLIT, BHN), 256, FA_SMEM_BYTES>>>(
            qld, 0, DH, 0, (long long)NLM * DH, BHN,
            qkvd + DM, qkvPlane, TD, (long long)NPAD * TD, 64, NH,
            qkvd + 2 * DM, qkvPlane, TD, (long long)NPAD * TD, 64, NH,
            NPAD / NSPLIT, po, pm, ps, nullptr, nullptr, 0);
        fa_combine<<<(unsigned)((long long)BHN * NLM * DH / 256), 256>>>(po, pm, ps, a3vd, avPlane);

        // join pinv chain
        cudaStreamWaitEvent(0, g_ss.eB[l], 0);

        // w = z @ a3v   (z in zpCur z-half)
        launch_gemm(0, 64, zpCur, a3vd, zpPlane, avPlane,
                    nullptr, wd, avPlane, nullptr, 0,
                    NLM, DH, NLM, NLM, DH, DH,
                    MM, 0, 1, (long long)NLM * DH, 0, 1,
                    (long long)NLM * DH, BHN, 1.f, nullptr, 0, 0, 0);

        // F2: catd = merge( softmax(0.125 Q k_l^T) @ w + conv )   (hi-only store)
        flash_kernel<1><<<dim3(NPAD / 128, 1, BHN), 256, FA_SMEM_BYTES>>>(
            qkvd, qkvPlane, TD, (long long)NPAD * TD, 64, NH,
            kld, qlPlane, DH, 0, (long long)NLM * DH, BHN,
            wd, avPlane, DH, 0, (long long)NLM * DH, BHN,
            NLM, nullptr, nullptr, nullptr, outh, catd, 0);

        // output projection, accumulate into residual stream (fp32)
        launch_gemm(0, 128, catd + (long long)PADN * DM, outwd + (long long)l * 2 * DM * DM,
                    0, DM * DM,
                    h + (long long)PADN * DM, nullptr, 0, nullptr, 0,
                    NP1, DM, DM, DM, DM, DM,
                    (long long)NPAD * DM, 0, 1, 0, 0, 1,
                    (long long)NPAD * DM, BATCH, 1.f, outb[l], 0, 1, 0);
    }

    final_kernel<<<BATCH, 256>>>(h, nfg, nfb, fc2w, fc2b, (float*)d_out);
}

// round 17
// speedup vs baseline: 2.0351x; 1.4047x over previous
#include <cuda_runtime.h>
#include <cuda_bf16.h>
#include <cstdint>
#include <math.h>

#define BATCH 2
#define NTOK  8000
#define NP1   8001
#define PADN  191
#define NPAD  8192
#define DM    512
#define DIN   1024
#define NH    8
#define DH    64
#define NLM   256
#define LPER  32
#define BHN   16
#define CONVK 33
#define TD    1536
#define BM    128
#define BK    32
#define NSPLIT 8
#define MM    ((long long)NLM * NLM)

typedef __nv_bfloat16 bf16;

// ---------------- fp32 scratch ----------------
__device__ float g_h   [(long long)BATCH*NPAD*DM];
__device__ float g_a2  [(long long)BHN*NLM*NLM];
__device__ float g_outh[(long long)BHN*NPAD*DH];
__device__ float g_po  [(long long)NSPLIT*BHN*NLM*DH];
__device__ float g_pm  [(long long)NSPLIT*BHN*NLM];
__device__ float g_ps  [(long long)NSPLIT*BHN*NLM];
__device__ int   g_maxrow;
__device__ int   g_maxcol;

// ---------------- bf16 scratch (single plane everywhere) ----------------
__device__ __align__(16) bf16 g_featsd[1LL*BATCH*NTOK*DIN];
__device__ __align__(16) bf16 g_w1d   [1LL*DIN*DM];
__device__ __align__(16) bf16 g_qkvwd [1LL*2*DM*TD];
__device__ __align__(16) bf16 g_outwd [1LL*2*DM*DM];
__device__ __align__(16) bf16 g_xlnd  [1LL*BATCH*NPAD*DM];
__device__ __align__(16) bf16 g_qkvd  [1LL*BATCH*NPAD*TD];
__device__ __align__(16) bf16 g_qld   [1LL*BHN*NLM*DH];
__device__ __align__(16) bf16 g_kld   [1LL*BHN*NLM*DH];
__device__ __align__(16) bf16 g_a2d   [1LL*BHN*NLM*NLM];
__device__ __align__(16) bf16 g_zpd   [1LL*32*NLM*NLM];   // z in 0-15, p in 16-31
__device__ __align__(16) bf16 g_zp2d  [1LL*32*NLM*NLM];
__device__ __align__(16) bf16 g_t1d   [1LL*32*NLM*NLM];   // t1 valid in p-half
__device__ __align__(16) bf16 g_t2d   [1LL*16*NLM*NLM];
__device__ __align__(16) bf16 g_t3d   [1LL*16*NLM*NLM];
__device__ __align__(16) bf16 g_a3vd  [1LL*BHN*NLM*DH];
__device__ __align__(16) bf16 g_wd    [1LL*BHN*NLM*DH];
__device__ __align__(16) bf16 g_catd  [1LL*BATCH*NPAD*DM];

// ---------------- helpers ----------------
__device__ __forceinline__ void storeHi2(bf16* d, long long idx, float x, float y) {
    __nv_bfloat162 h = __floats2bfloat162_rn(x, y);
    *reinterpret_cast<__nv_bfloat162*>(d + idx) = h;
}
__device__ __forceinline__ void cpa16(uint32_t dst, const void* src, bool pred) {
    int sz = pred ? 16 : 0;
    asm volatile("cp.async.cg.shared.global [%0], [%1], 16, %2;\n"
                 :: "r"(dst), "l"(src), "r"(sz));
}
__device__ __forceinline__ void cpa_commit() {
    asm volatile("cp.async.commit_group;\n");
}

__device__ __forceinline__ float blockReduceSum(float v, float* sh) {
    #pragma unroll
    for (int o = 16; o; o >>= 1) v += __shfl_xor_sync(0xffffffffu, v, o);
    int w = threadIdx.x >> 5;
    if ((threadIdx.x & 31) == 0) sh[w] = v;
    __syncthreads();
    if (threadIdx.x < 8) {
        v = sh[threadIdx.x];
        #pragma unroll
        for (int o = 4; o; o >>= 1) v += __shfl_xor_sync(0xffu, v, o);
        if (threadIdx.x == 0) sh[0] = v;
    }
    __syncthreads();
    float r = sh[0];
    __syncthreads();
    return r;
}
__device__ __forceinline__ float blockReduceMax(float v, float* sh) {
    #pragma unroll
    for (int o = 16; o; o >>= 1) v = fmaxf(v, __shfl_xor_sync(0xffffffffu, v, o));
    int w = threadIdx.x >> 5;
    if ((threadIdx.x & 31) == 0) sh[w] = v;
    __syncthreads();
    if (threadIdx.x < 8) {
        v = sh[threadIdx.x];
        #pragma unroll
        for (int o = 4; o; o >>= 1) v = fmaxf(v, __shfl_xor_sync(0xffu, v, o));
        if (threadIdx.x == 0) sh[0] = v;
    }
    __syncthreads();
    float r = sh[0];
    __syncthreads();
    return r;
}

__device__ __forceinline__ void mma16816(float* c, const unsigned* a, const unsigned* b) {
    asm volatile(
        "mma.sync.aligned.m16n8k16.row.col.f32.bf16.bf16.f32 "
        "{%0,%1,%2,%3},{%4,%5,%6,%7},{%8,%9},{%0,%1,%2,%3};\n"
        : "+f"(c[0]), "+f"(c[1]), "+f"(c[2]), "+f"(c[3])
        : "r"(a[0]), "r"(a[1]), "r"(a[2]), "r"(a[3]), "r"(b[0]), "r"(b[1]));
}
__device__ __forceinline__ void ldsm4(unsigned& r0, unsigned& r1, unsigned& r2, unsigned& r3,
                                      uint32_t addr) {
    asm volatile("ldmatrix.sync.aligned.m8n8.x4.shared.b16 {%0,%1,%2,%3}, [%4];\n"
                 : "=r"(r0), "=r"(r1), "=r"(r2), "=r"(r3) : "r"(addr));
}
__device__ __forceinline__ void ldsm4t(unsigned& r0, unsigned& r1, unsigned& r2, unsigned& r3,
                                       uint32_t addr) {
    asm volatile("ldmatrix.sync.aligned.m8n8.x4.trans.shared.b16 {%0,%1,%2,%3}, [%4];\n"
                 : "=r"(r0), "=r"(r1), "=r"(r2), "=r"(r3) : "r"(addr));
}

// ---------------- pure-bf16 tensor-core GEMM (1 MMA/tile, cp.async pipelined) ----------------
template<int BN, int WROWS, int WCOLS>
__global__ void __launch_bounds__(256) gemm_tc(
    const bf16* __restrict__ A, const bf16* __restrict__ B,
    float* __restrict__ C, bf16* __restrict__ D,
    bf16* __restrict__ D2,
    int Mn, int Kn, int lda, int ldb, int ldc,
    long long aOuter, long long aInner, int aCnt,
    long long bOuter, long long bInner, int bCnt,
    long long cStride, float alpha, const float* __restrict__ bias,
    int relu, int accum, int transB, int splitK, long long partStride,
    float diagVal, float diag2)
{
    constexpr int WM = BM / WROWS;
    constexpr int WN = BN / WCOLS;
    constexpr int MT = WM / 16;
    constexpr int NT = WN / 8;
    constexpr int NTP = WN / 16;
    constexpr int KST = BN + 8;
    constexpr int ASTG = BM * 40;
    constexpr int BSTG = BN * 40;

    int bz = blockIdx.z;
    int batch = bz / splitK;
    int split = bz - batch * splitK;
    const bf16* Ab = A + (long long)(batch / aCnt) * aOuter + (long long)(batch % aCnt) * aInner;
    const bf16* Bb = B + (long long)(batch / bCnt) * bOuter + (long long)(batch % bCnt) * bInner;
    long long cOff = (long long)batch * cStride + (long long)split * partStride;
    int kPer = Kn / splitK;
    int kStart = split * kPer;

    __shared__ __align__(16) bf16 sA[2 * ASTG];
    __shared__ __align__(16) bf16 sB[2 * BSTG];
    uint32_t saBase = (uint32_t)__cvta_generic_to_shared(sA);
    uint32_t sbBase = (uint32_t)__cvta_generic_to_shared(sB);

    int tid = threadIdx.x;
    int lane = tid & 31;
    int wid = tid >> 5;
    int lt = lane & 7;
    int lg = lane >> 3;
    int warpM = (wid / WCOLS) * WM;
    int warpN = (wid % WCOLS) * WN;
    int rowBase = blockIdx.y * BM;
    int colBase = blockIdx.x * BN;

    float acc[MT][NT][4];
    #pragma unroll
    for (int i = 0; i < MT; i++)
        #pragma unroll
        for (int j = 0; j < NT; j++)
            #pragma unroll
            for (int e = 0; e < 4; e++) acc[i][j][e] = 0.f;

    auto issue = [&](int k0, int stg) {
        uint32_t sa = saBase + stg * ASTG * 2;
        uint32_t sb = sbBase + stg * BSTG * 2;
        #pragma unroll
        for (int j = 0; j < 2; j++) {
            int id = tid + j * 256;
            int row = id >> 2, seg = id & 3;
            int gr = rowBase + row;
            bool ok = gr < Mn;
            const bf16* src = Ab + (long long)(ok ? gr : 0) * lda + kStart + k0 + seg * 8;
            cpa16(sa + ((row * 40 + seg * 8) << 1), src, ok);
        }
        if (transB) {
            #pragma unroll
            for (int j = 0; j < BN / 64; j++) {
                int id = tid + j * 256;
                int row = id >> 2, seg = id & 3;
                const bf16* src = Bb + (long long)(colBase + row) * ldb + kStart + k0 + seg * 8;
                cpa16(sb + ((row * 40 + seg * 8) << 1), src, true);
            }
        } else {
            #pragma unroll
            for (int j = 0; j < BN / 64; j++) {
                int id = tid + j * 256;
                int k = id / (BN / 8), seg = id % (BN / 8);
                const bf16* src = Bb + (long long)(kStart + k0 + k) * ldb + colBase + seg * 8;
                cpa16(sb + ((k * KST + seg * 8) << 1), src, true);
            }
        }
        cpa_commit();
    };

    int nIter = kPer / BK;
    issue(0, 0);

    for (int it = 0; it < nIter; it++) {
        int cur = it & 1;
        asm volatile("cp.async.wait_group 0;\n");
        __syncthreads();
        if (it + 1 < nIter) issue((it + 1) * BK, cur ^ 1);

        uint32_t saS = saBase + cur * ASTG * 2;
        uint32_t sbS = sbBase + cur * BSTG * 2;

        #pragma unroll
        for (int ks = 0; ks < 2; ks++) {
            int k8 = ks * 16;
            unsigned bh[NTP][4];
            #pragma unroll
            for (int ntp = 0; ntp < NTP; ntp++) {
                if (transB) {
                    int n = warpN + ntp * 16 + lt + ((lg >> 1) << 3);
                    int kk = k8 + ((lg & 1) << 3);
                    ldsm4(bh[ntp][0], bh[ntp][1], bh[ntp][2], bh[ntp][3],
                          sbS + ((n * 40 + kk) << 1));
                } else {
                    int k = k8 + lt + ((lg & 1) << 3);
                    int n = warpN + ntp * 16 + ((lg >> 1) << 3);
                    ldsm4t(bh[ntp][0], bh[ntp][1], bh[ntp][2], bh[ntp][3],
                           sbS + ((k * KST + n) << 1));
                }
            }
            #pragma unroll
            for (int mt = 0; mt < MT; mt++) {
                unsigned ah[4];
                int m = warpM + mt * 16 + lt + ((lg & 1) << 3);
                int kk = k8 + ((lg >> 1) << 3);
                ldsm4(ah[0], ah[1], ah[2], ah[3],
                      saS + ((m * 40 + kk) << 1));
                #pragma unroll
                for (int nt = 0; nt < NT; nt++) {
                    const unsigned* ph = &bh[nt >> 1][(nt & 1) * 2];
                    mma16816(acc[mt][nt], ah, ph);
                }
            }
        }
        __syncthreads();
    }

    int q = lane & 3, g = lane >> 2;
    float* Cb = C ? C + cOff : nullptr;
    bf16* Db = D ? D + cOff : nullptr;
    bf16* D2b = D2 ? D2 + cOff : nullptr;
    #pragma unroll
    for (int mt = 0; mt < MT; mt++) {
        #pragma unroll
        for (int nt = 0; nt < NT; nt++) {
            int r0 = rowBase + warpM + mt * 16 + g;
            int c0 = colBase + warpN + nt * 8 + q * 2;
            #pragma unroll
            for (int half = 0; half < 2; half++) {
                int gr = r0 + half * 8;
                if (gr >= Mn) continue;
                float v0 = alpha * acc[mt][nt][half * 2 + 0];
                float v1 = alpha * acc[mt][nt][half * 2 + 1];
                if (gr == c0)     v0 += diagVal;
                if (gr == c0 + 1) v1 += diagVal;
                long long off = (long long)gr * ldc + c0;
                if (Cb) {
                    float w0 = v0, w1 = v1;
                    if (bias) { w0 += bias[c0]; w1 += bias[c0 + 1]; }
                    if (relu) { w0 = fmaxf(w0, 0.f); w1 = fmaxf(w1, 0.f); }
                    if (accum) { w0 += Cb[off]; w1 += Cb[off + 1]; }
                    *reinterpret_cast<float2*>(Cb + off) = make_float2(w0, w1);
                }
                if (Db) storeHi2(Db, off, v0, v1);
                if (D2b) {
                    float u0 = ((gr == c0)     ? diag2 : 0.f) - v0;
                    float u1 = ((gr == c0 + 1) ? diag2 : 0.f) - v1;
                    storeHi2(D2b, off, u0, u1);
                }
            }
        }
    }
}

// ---------------- fused flash attention (pure bf16, 1 MMA/tile) ----------------
// smem elems: Q 128*72 | K 2stg x 64*72 | V 2stg x 64*72
#define FA_K    9216
#define FA_V    18432
#define FA_SMEM_BYTES (27648 * 2)

template<int MODE>
__global__ void __launch_bounds__(256) flash_kernel(
    const bf16* __restrict__ Qa, int qStride,
    long long qOuter, long long qInner, int qCnt,
    const bf16* __restrict__ Ka, int kStride,
    long long kOuter, long long kInner, int kCnt,
    const bf16* __restrict__ Va, int vStride,
    long long vOuter, long long vInner, int vCnt,
    int keysPerSplit,
    float* __restrict__ PO, float* __restrict__ PM, float* __restrict__ PS,
    const float* __restrict__ CONV, bf16* __restrict__ CATD)
{
    extern __shared__ __align__(16) bf16 fsm[];
    uint32_t smBase = (uint32_t)__cvta_generic_to_shared(fsm);
    int tid = threadIdx.x, lane = tid & 31, wid = tid >> 5;
    int lt = lane & 7, lg = lane >> 3, g = lane >> 2, q = lane & 3;
    int bh = blockIdx.z, split = blockIdx.y;
    int rowBase = blockIdx.x * 128;
    const bf16* Q = Qa + (long long)(bh / qCnt) * qOuter + (long long)(bh % qCnt) * qInner;
    const bf16* K = Ka + (long long)(bh / kCnt) * kOuter + (long long)(bh % kCnt) * kInner
                       + (long long)split * keysPerSplit * kStride;
    const bf16* V = Va + (long long)(bh / vCnt) * vOuter + (long long)(bh % vCnt) * vInner
                       + (long long)split * keysPerSplit * vStride;

    // stage Q: 128 rows x 64 cols
    #pragma unroll
    for (int j = 0; j < 4; j++) {
        int c = tid + j * 256;
        int row = c >> 3, seg = c & 7;
        cpa16(smBase + ((row * 72 + seg * 8) << 1),
              Q + (long long)(rowBase + row) * qStride + seg * 8, true);
    }
    auto issueKV = [&](int t, int stg) {
        int key0 = t * 64;
        int row = tid >> 2, seg = tid & 3;
        cpa16(smBase + ((FA_K + stg * 4608 + row * 72 + seg * 16) << 1),
              K + (long long)(key0 + row) * kStride + seg * 16, true);
        cpa16(smBase + ((FA_K + stg * 4608 + row * 72 + seg * 16 + 8) << 1),
              K + (long long)(key0 + row) * kStride + seg * 16 + 8, true);
        cpa16(smBase + ((FA_V + stg * 4608 + row * 72 + seg * 16) << 1),
              V + (long long)(key0 + row) * vStride + seg * 16, true);
        cpa16(smBase + ((FA_V + stg * 4608 + row * 72 + seg * 16 + 8) << 1),
              V + (long long)(key0 + row) * vStride + seg * 16 + 8, true);
        cpa_commit();
    };
    issueKV(0, 0);

    int warpRow = wid * 16;
    unsigned qh[4][4];
    float o[8][4];
    #pragma unroll
    for (int i = 0; i < 8; i++)
        #pragma unroll
        for (int e = 0; e < 4; e++) o[i][e] = 0.f;
    float m0 = -1e30f, m1 = -1e30f, l0 = 0.f, l1 = 0.f;

    int nTiles = keysPerSplit / 64;
    for (int t = 0; t < nTiles; t++) {
        int stg = t & 1;
        bool more = (t + 1 < nTiles);
        if (more) {
            issueKV(t + 1, stg ^ 1);
            asm volatile("cp.async.wait_group 1;\n");
        } else {
            asm volatile("cp.async.wait_group 0;\n");
        }
        __syncthreads();
        if (t == 0) {
            #pragma unroll
            for (int kc = 0; kc < 4; kc++) {
                int row = warpRow + lt + ((lg & 1) << 3);
                int kk = kc * 16 + ((lg >> 1) << 3);
                ldsm4(qh[kc][0], qh[kc][1], qh[kc][2], qh[kc][3],
                      smBase + ((row * 72 + kk) << 1));
            }
        }
        uint32_t skS = smBase + ((FA_K + stg * 4608) << 1);
        uint32_t svS = smBase + ((FA_V + stg * 4608) << 1);

        float sc[8][4];
        #pragma unroll
        for (int i = 0; i < 8; i++)
            #pragma unroll
            for (int e = 0; e < 4; e++) sc[i][e] = 0.f;
        #pragma unroll
        for (int kc = 0; kc < 4; kc++) {
            unsigned kh[4][4];
            #pragma unroll
            for (int ntp = 0; ntp < 4; ntp++) {
                int n = ntp * 16 + lt + ((lg >> 1) << 3);
                int kk = kc * 16 + ((lg & 1) << 3);
                ldsm4(kh[ntp][0], kh[ntp][1], kh[ntp][2], kh[ntp][3],
                      skS + ((n * 72 + kk) << 1));
            }
            #pragma unroll
            for (int nt = 0; nt < 8; nt++) {
                const unsigned* bhf = &kh[nt >> 1][(nt & 1) * 2];
                mma16816(sc[nt], qh[kc], bhf);
            }
        }
        float mt0 = -1e30f, mt1 = -1e30f;
        #pragma unroll
        for (int nt = 0; nt < 8; nt++) {
            #pragma unroll
            for (int e = 0; e < 4; e++) sc[nt][e] *= 0.125f;
            mt0 = fmaxf(mt0, fmaxf(sc[nt][0], sc[nt][1]));
            mt1 = fmaxf(mt1, fmaxf(sc[nt][2], sc[nt][3]));
        }
        mt0 = fmaxf(mt0, __shfl_xor_sync(0xffffffffu, mt0, 1));
        mt0 = fmaxf(mt0, __shfl_xor_sync(0xffffffffu, mt0, 2));
        mt1 = fmaxf(mt1, __shfl_xor_sync(0xffffffffu, mt1, 1));
        mt1 = fmaxf(mt1, __shfl_xor_sync(0xffffffffu, mt1, 2));
        float mn0 = fmaxf(m0, mt0), mn1 = fmaxf(m1, mt1);
        float f0 = __expf(m0 - mn0), f1 = __expf(m1 - mn1);
        m0 = mn0; m1 = mn1;
        float rs0 = 0.f, rs1 = 0.f;
        #pragma unroll
        for (int nt = 0; nt < 8; nt++) {
            sc[nt][0] = __expf(sc[nt][0] - mn0);
            sc[nt][1] = __expf(sc[nt][1] - mn0);
            sc[nt][2] = __expf(sc[nt][2] - mn1);
            sc[nt][3] = __expf(sc[nt][3] - mn1);
            rs0 += sc[nt][0] + sc[nt][1];
            rs1 += sc[nt][2] + sc[nt][3];
        }
        rs0 += __shfl_xor_sync(0xffffffffu, rs0, 1);
        rs0 += __shfl_xor_sync(0xffffffffu, rs0, 2);
        rs1 += __shfl_xor_sync(0xffffffffu, rs1, 1);
        rs1 += __shfl_xor_sync(0xffffffffu, rs1, 2);
        l0 = l0 * f0 + rs0;
        l1 = l1 * f1 + rs1;
        #pragma unroll
        for (int nt = 0; nt < 8; nt++) {
            o[nt][0] *= f0; o[nt][1] *= f0;
            o[nt][2] *= f1; o[nt][3] *= f1;
        }
        #pragma unroll
        for (int kc = 0; kc < 4; kc++) {
            unsigned ph[4];
            __nv_bfloat162 t0 = __floats2bfloat162_rn(sc[2 * kc][0], sc[2 * kc][1]);
            __nv_bfloat162 t1 = __floats2bfloat162_rn(sc[2 * kc][2], sc[2 * kc][3]);
            __nv_bfloat162 t2 = __floats2bfloat162_rn(sc[2 * kc + 1][0], sc[2 * kc + 1][1]);
            __nv_bfloat162 t3 = __floats2bfloat162_rn(sc[2 * kc + 1][2], sc[2 * kc + 1][3]);
            ph[0] = *reinterpret_cast<unsigned*>(&t0);
            ph[1] = *reinterpret_cast<unsigned*>(&t1);
            ph[2] = *reinterpret_cast<unsigned*>(&t2);
            ph[3] = *reinterpret_cast<unsigned*>(&t3);
            unsigned vh[4][4];
            #pragma unroll
            for (int ntp = 0; ntp < 4; ntp++) {
                int k = kc * 16 + lt + ((lg & 1) << 3);
                int n = ntp * 16 + ((lg >> 1) << 3);
                ldsm4t(vh[ntp][0], vh[ntp][1], vh[ntp][2], vh[ntp][3],
                       svS + ((k * 72 + n) << 1));
            }
            #pragma unroll
            for (int nt = 0; nt < 8; nt++) {
                const unsigned* bhf = &vh[nt >> 1][(nt & 1) * 2];
                mma16816(o[nt], ph, bhf);
            }
        }
        __syncthreads();
    }

    int row0 = rowBase + warpRow + g;
    int row1 = row0 + 8;
    if (MODE == 1) {
        float i0 = 1.f / l0, i1 = 1.f / l1;
        int b = bh >> 3, hh = bh & 7;
        const float* Cv = CONV + (long long)bh * NPAD * 64;
        #pragma unroll
        for (int nt = 0; nt < 8; nt++) {
            int col = nt * 8 + q * 2;
            float2 c0 = *(const float2*)&Cv[(long long)row0 * 64 + col];
            float2 c1 = *(const float2*)&Cv[(long long)row1 * 64 + col];
            long long i0d = ((long long)b * NPAD + row0) * DM + hh * 64 + col;
            long long i1d = ((long long)b * NPAD + row1) * DM + hh * 64 + col;
            storeHi2(CATD, i0d, o[nt][0] * i0 + c0.x, o[nt][1] * i0 + c0.y);
            storeHi2(CATD, i1d, o[nt][2] * i1 + c1.x, o[nt][3] * i1 + c1.y);
        }
    } else {
        long long pb = ((long long)split * BHN + bh) * NLM;
        #pragma unroll
        for (int nt = 0; nt < 8; nt++) {
            int col = nt * 8 + q * 2;
            *(float2*)&PO[(pb + row0) * 64 + col] = make_float2(o[nt][0], o[nt][1]);
            *(float2*)&PO[(pb + row1) * 64 + col] = make_float2(o[nt][2], o[nt][3]);
        }
        if (q == 0) {
            PM[pb + row0] = m0; PM[pb + row1] = m1;
            PS[pb + row0] = l0; PS[pb + row1] = l1;
        }
    }
}

__global__ void fa_combine(const float* __restrict__ po, const float* __restrict__ pm,
                           const float* __restrict__ ps, bf16* __restrict__ outd) {
    long long idx = (long long)blockIdx.x * 256 + threadIdx.x;
    int d = (int)(idx & 63);
    long long rid = idx >> 6;
    const long long RS = (long long)BHN * NLM;
    float M = -1e30f;
    #pragma unroll
    for (int s = 0; s < NSPLIT; s++) M = fmaxf(M, pm[s * RS + rid]);
    float S = 0.f, val = 0.f;
    #pragma unroll
    for (int s = 0; s < NSPLIT; s++) {
        float e = __expf(pm[s * RS + rid] - M);
        S += ps[s * RS + rid] * e;
        val += po[(s * RS + rid) * 64 + d] * e;
    }
    outd[rid * 64 + d] = __float2bfloat16(val / S);
}

// ---------------- misc kernels ----------------
__global__ void tobf16hi_kernel(const float* __restrict__ x, bf16* __restrict__ d,
                                long long n) {
    long long i = (long long)blockIdx.x * 256 + threadIdx.x;
    if (i >= n) return;
    d[i] = __float2bfloat16(x[i]);
}

__global__ void init_h_kernel(const float* __restrict__ cls, float* __restrict__ h) {
    int r = blockIdx.x, b = blockIdx.y;
    float* o = h + ((long long)b * NPAD + r) * DM;
    for (int i = threadIdx.x; i < DM; i += 256) o[i] = (r == PADN) ? cls[i] : 0.f;
}

__global__ void layernorm_kernel(const float* __restrict__ in, bf16* __restrict__ xd,
                                 const float* __restrict__ gam, const float* __restrict__ bet) {
    __shared__ float sh[8];
    long long row = blockIdx.x;
    int r = (int)(row % NPAD);
    int tid = threadIdx.x;
    long long idx = row * DM + tid * 2;
    if (r < PADN) {
        storeHi2(xd, idx, 0.f, 0.f);
        return;
    }
    const float2* x = (const float2*)(in + row * DM);
    float2 v = x[tid];
    float s = v.x + v.y;
    float s2 = v.x * v.x + v.y * v.y;
    s = blockReduceSum(s, sh);
    s2 = blockReduceSum(s2, sh);
    float mean = s / DM;
    float var = s2 / DM - mean * mean;
    float inv = rsqrtf(var + 1e-5f);
    float2 gv = ((const float2*)gam)[tid];
    float2 bv = ((const float2*)bet)[tid];
    storeHi2(xd, idx,
             (v.x - mean) * inv * gv.x + bv.x,
             (v.y - mean) * inv * gv.y + bv.y);
}

__global__ void landmark_kernel(const bf16* __restrict__ qkvd,
                                bf16* __restrict__ qld, bf16* __restrict__ kld) {
    int m = blockIdx.x, bh = blockIdx.y;
    int b = bh >> 3, h = bh & 7;
    int d = threadIdx.x;
    long long base = (long long)b * NPAD * TD + (long long)m * LPER * TD + h * 64 + d;
    float sq = 0.f, sk = 0.f;
    #pragma unroll 4
    for (int r = 0; r < LPER; r++) {
        long long i = base + (long long)r * TD;
        sq += __bfloat162float(qkvd[i]);
        sk += __bfloat162float(qkvd[i + 512]);
    }
    long long idx = ((long long)bh * NLM + m) * DH + d;
    qld[idx] = __float2bfloat16(sq * (1.f / LPER));
    kld[idx] = __float2bfloat16(sk * (1.f / LPER));
}

__global__ void softmax256(const float* __restrict__ in, float* __restrict__ out32,
                           bf16* __restrict__ outd, long long nrows) {
    long long row = (long long)blockIdx.x * 8 + (threadIdx.x >> 5);
    if (row >= nrows) return;
    int lane = threadIdx.x & 31;
    const float4* pi = (const float4*)(in + row * 256);
    float4 v0 = pi[lane];
    float4 v1 = pi[lane + 32];
    float m = fmaxf(fmaxf(fmaxf(v0.x, v0.y), fmaxf(v0.z, v0.w)),
                    fmaxf(fmaxf(v1.x, v1.y), fmaxf(v1.z, v1.w)));
    #pragma unroll
    for (int o = 16; o; o >>= 1) m = fmaxf(m, __shfl_xor_sync(0xffffffffu, m, o));
    v0.x = __expf(v0.x - m); v0.y = __expf(v0.y - m);
    v0.z = __expf(v0.z - m); v0.w = __expf(v0.w - m);
    v1.x = __expf(v1.x - m); v1.y = __expf(v1.y - m);
    v1.z = __expf(v1.z - m); v1.w = __expf(v1.w - m);
    float s = v0.x + v0.y + v0.z + v0.w + v1.x + v1.y + v1.z + v1.w;
    #pragma unroll
    for (int o = 16; o; o >>= 1) s += __shfl_xor_sync(0xffffffffu, s, o);
    float inv = 1.f / s;
    v0.x *= inv; v0.y *= inv; v0.z *= inv; v0.w *= inv;
    v1.x *= inv; v1.y *= inv; v1.z *= inv; v1.w *= inv;
    if (out32) {
        ((float4*)(out32 + row * 256))[lane] = v0;
        ((float4*)(out32 + row * 256))[lane + 32] = v1;
    }
    long long b0 = row * 256 + lane * 4;
    storeHi2(outd, b0, v0.x, v0.y);
    storeHi2(outd, b0 + 2, v0.z, v0.w);
    storeHi2(outd, b0 + 128, v1.x, v1.y);
    storeHi2(outd, b0 + 130, v1.z, v1.w);
}

__global__ void reset_kernel() {
    if (threadIdx.x == 0) { g_maxrow = 0; g_maxcol = 0; }
}

__global__ void a2stats_kernel(const float* __restrict__ a2) {
    __shared__ float sh[8];
    int bh = blockIdx.x;
    const float* a = a2 + (long long)bh * MM;
    int j = threadIdx.x;
    float cs = 0.f, rs = 0.f;
    for (int i = 0; i < NLM; i++) cs += a[(long long)i * NLM + j];
    const float* row = a + (long long)j * NLM;
    for (int i = 0; i < NLM; i++) rs += row[i];
    float cmax = blockReduceMax(cs, sh);
    float rmax = blockReduceMax(rs, sh);
    if (threadIdx.x == 0) {
        atomicMax(&g_maxcol, __float_as_int(cmax));
        atomicMax(&g_maxrow, __float_as_int(rmax));
    }
}

__global__ void z0_kernel(const float* __restrict__ a2, bf16* __restrict__ zp) {
    __shared__ float tile[32][33];
    int bh = blockIdx.z;
    const float* a = a2 + (long long)bh * MM;
    long long zbase = (long long)bh * MM;
    float inv = 1.f / (__int_as_float(g_maxrow) * __int_as_float(g_maxcol));
    int i0 = blockIdx.y * 32, j0 = blockIdx.x * 32;
    for (int r = threadIdx.y; r < 32; r += 8)
        tile[r][threadIdx.x] = a[(long long)(i0 + r) * NLM + j0 + threadIdx.x];
    __syncthreads();
    for (int r = threadIdx.y; r < 32; r += 8)
        zp[zbase + (long long)(j0 + r) * NLM + i0 + threadIdx.x] =
            __float2bfloat16(tile[threadIdx.x][r] * inv);
}

__global__ void conv_kernel(const bf16* __restrict__ qkvd,
                            const float* __restrict__ w, float* __restrict__ outh) {
    int bh = blockIdx.y;
    int b = bh >> 3, h = bh & 7;
    int iBase = blockIdx.x * 64;
    __shared__ float sv[96][64];
    __shared__ float sw[CONVK];
    long long vbase = (long long)b * NPAD * TD + 1024 + h * 64;
    int tid = threadIdx.x;
    for (int idx = tid; idx < 96 * 64; idx += 256) {
        int r = idx >> 6, d = idx & 63;
        int gi = iBase - 16 + r;
        sv[r][d] = (gi >= 0 && gi < NPAD)
                   ? __bfloat162float(qkvd[vbase + (long long)gi * TD + d]) : 0.f;
    }
    if (tid < CONVK) sw[tid] = w[h * CONVK + tid];
    __syncthreads();
    float* out = outh + (long long)bh * NPAD * DH + (long long)iBase * DH;
    for (int idx = tid; idx < 64 * 64; idx += 256) {
        int r = idx >> 6, d = idx & 63;
        float s = 0.f;
        #pragma unroll
        for (int t = 0; t < CONVK; t++) s += sw[t] * sv[r + t][d];
        out[r * 64 + d] = s;
    }
}

__global__ void final_kernel(const float* __restrict__ h, const float* __restrict__ gam,
                             const float* __restrict__ bet, const float* __restrict__ w2,
                             const float* __restrict__ b2, float* __restrict__ out) {
    __shared__ float sh[8];
    int b = blockIdx.x;
    const float* x = h + ((long long)b * NPAD + PADN) * DM;
    float s = 0.f, s2 = 0.f;
    for (int i = threadIdx.x; i < DM; i += 256) { float v = x[i]; s += v; s2 += v * v; }
    s = blockReduceSum(s, sh);
    s2 = blockReduceSum(s2, sh);
    float mean = s / DM;
    float var = s2 / DM - mean * mean;
    float inv = rsqrtf(var + 1e-5f);
    float p0 = 0.f, p1 = 0.f;
    for (int i = threadIdx.x; i < DM; i += 256) {
        float hn = (x[i] - mean) * inv * gam[i] + bet[i];
        p0 += hn * w2[2 * i];
        p1 += hn * w2[2 * i + 1];
    }
    p0 = blockReduceSum(p0, sh);
    p1 = blockReduceSum(p1, sh);
    if (threadIdx.x == 0) {
        float l0 = p0 + b2[0], l1 = p1 + b2[1];
        float mx = fmaxf(l0, l1);
        float e0 = expf(l0 - mx), e1 = expf(l1 - mx);
        float si = 1.f / (e0 + e1);
        out[b * 2 + 0] = l0;
        out[b * 2 + 1] = l1;
        out[4 + b * 2 + 0] = e0 * si;
        out[4 + b * 2 + 1] = e1 * si;
        out[8 + b] = (l1 > l0) ? 1.f : 0.f;
    }
}

// ---------------- host side ----------------
static void launch_gemm(cudaStream_t st, int bn, const bf16* A, const bf16* B,
                        float* C, bf16* D, bf16* D2,
                        int M, int N, int K, int lda, int ldb, int ldc,
                        long long aO, long long aI, int aC,
                        long long bO, long long bI, int bC,
                        long long cS, int batches, float alpha,
                        const float* bias, int relu, int accum, int transB,
                        int splitK = 1, long long partStride = 0,
                        float diagVal = 0.f, float diag2 = 0.f) {
    dim3 grid(N / bn, (M + BM - 1) / BM, batches * splitK);
    if (bn == 128)
        gemm_tc<128, 2, 4><<<grid, 256, 0, st>>>(A, B, C, D, D2,
                                                 M, K, lda, ldb, ldc, aO, aI, aC, bO, bI, bC,
                                                 cS, alpha, bias, relu, accum, transB,
                                                 splitK, partStride, diagVal, diag2);
    else
        gemm_tc<64, 4, 2><<<grid, 256, 0, st>>>(A, B, C, D, D2,
                                                M, K, lda, ldb, ldc, aO, aI, aC, bO, bI, bC,
                                                cS, alpha, bias, relu, accum, transB,
                                                splitK, partStride, diagVal, diag2);
}

// streams/events created once at static-init time
struct SideStream {
    cudaStream_t sB;
    cudaEvent_t eF, eL[2], eB[2], eW;
    SideStream() {
        cudaStreamCreateWithFlags(&sB, cudaStreamNonBlocking);
        cudaEventCreateWithFlags(&eF, cudaEventDisableTiming);
        for (int i = 0; i < 2; i++) {
            cudaEventCreateWithFlags(&eL[i], cudaEventDisableTiming);
            cudaEventCreateWithFlags(&eB[i], cudaEventDisableTiming);
        }
        cudaEventCreateWithFlags(&eW, cudaEventDisableTiming);
    }
};
static SideStream g_ss;

#define SYMF(p, s) do { void* _t; cudaGetSymbolAddress(&_t, s); p = (float*)_t; } while (0)
#define SYMB(p, s) do { void* _t; cudaGetSymbolAddress(&_t, s); p = (bf16*)_t; } while (0)

extern "C" void kernel_launch(void* const* d_in, const int* in_sizes, int n_in,
                              void* d_out, int out_size) {
    const float* feats = (const float*)d_in[0];
    const float* fc1_w = (const float*)d_in[1];
    const float* fc1_b = (const float*)d_in[2];
    const float* cls   = (const float*)d_in[3];
    const float* lng[2]   = {(const float*)d_in[4],  (const float*)d_in[10]};
    const float* lnb[2]   = {(const float*)d_in[5],  (const float*)d_in[11]};
    const float* qkvw[2]  = {(const float*)d_in[6],  (const float*)d_in[12]};
    const float* outw[2]  = {(const float*)d_in[7],  (const float*)d_in[13]};
    const float* outb[2]  = {(const float*)d_in[8],  (const float*)d_in[14]};
    const float* convw[2] = {(const float*)d_in[9],  (const float*)d_in[15]};
    const float* nfg  = (const float*)d_in[16];
    const float* nfb  = (const float*)d_in[17];
    const float* fc2w = (const float*)d_in[18];
    const float* fc2b = (const float*)d_in[19];

    float *h, *a2, *outh, *po, *pm, *ps;
    SYMF(h, g_h); SYMF(a2, g_a2); SYMF(outh, g_outh);
    SYMF(po, g_po); SYMF(pm, g_pm); SYMF(ps, g_ps);
    bf16 *featsd, *w1d, *qkvwd, *outwd, *xlnd, *qkvd, *qld, *kld, *a2d;
    bf16 *zpd, *zp2d, *t1d, *t2d, *t3d, *a3vd, *wd, *catd;
    SYMB(featsd, g_featsd); SYMB(w1d, g_w1d); SYMB(qkvwd, g_qkvwd); SYMB(outwd, g_outwd);
    SYMB(xlnd, g_xlnd); SYMB(qkvd, g_qkvd); SYMB(qld, g_qld); SYMB(kld, g_kld);
    SYMB(a2d, g_a2d);
    SYMB(zpd, g_zpd); SYMB(zp2d, g_zp2d); SYMB(t1d, g_t1d); SYMB(t2d, g_t2d); SYMB(t3d, g_t3d);
    SYMB(a3vd, g_a3vd); SYMB(wd, g_wd); SYMB(catd, g_catd);

    const long long featsPlane = (long long)BATCH * NTOK * DIN;

    cudaFuncSetAttribute(flash_kernel<0>, cudaFuncAttributeMaxDynamicSharedMemorySize, FA_SMEM_BYTES);
    cudaFuncSetAttribute(flash_kernel<1>, cudaFuncAttributeMaxDynamicSharedMemorySize, FA_SMEM_BYTES);

    cudaStream_t sB = g_ss.sB;

    // fork side stream from capture origin FIRST (legal capture fork)
    cudaEventRecord(g_ss.eF, 0);
    cudaStreamWaitEvent(sB, g_ss.eF, 0);

    // input conversions (all hi-only): feats+fc1w on main, layer weights on side
    tobf16hi_kernel<<<(unsigned)((featsPlane + 255) / 256), 256>>>(feats, featsd, featsPlane);
    tobf16hi_kernel<<<(DIN * DM + 255) / 256, 256>>>(fc1_w, w1d, DIN * DM);
    for (int l = 0; l < 2; l++) {
        tobf16hi_kernel<<<(DM * TD + 255) / 256, 256, 0, sB>>>(
            qkvw[l], qkvwd + (long long)l * DM * TD, DM * TD);
        tobf16hi_kernel<<<(DM * DM + 255) / 256, 256, 0, sB>>>(
            outw[l], outwd + (long long)l * DM * DM, DM * DM);
    }
    cudaEventRecord(g_ss.eW, sB);

    init_h_kernel<<<dim3(PADN + 1, BATCH), 256>>>(cls, h);

    // fc1 + relu
    launch_gemm(0, 128, featsd, w1d,
                h + (long long)(PADN + 1) * DM, nullptr, nullptr,
                NTOK, DM, DIN, DIN, DM, DM,
                (long long)NTOK * DIN, 0, 1, 0, 0, 1,
                (long long)NPAD * DM, BATCH, 1.f, fc1_b, 1, 0, 0);

    cudaStreamWaitEvent(0, g_ss.eW, 0);

    for (int l = 0; l < 2; l++) {
        layernorm_kernel<<<BATCH * NPAD, 256>>>(h, xlnd, lng[l], lnb[l]);

        // qkv = xln @ qkvw  (bf16 output)
        launch_gemm(0, 128, xlnd, qkvwd + (long long)l * DM * TD,
                    nullptr, qkvd, nullptr,
                    NPAD, TD, DM, DM, TD, TD,
                    (long long)NPAD * DM, 0, 1, 0, 0, 1,
                    (long long)NPAD * TD, BATCH, 1.f, nullptr, 0, 0, 0);

        landmark_kernel<<<dim3(NLM, BHN), 64>>>(qkvd, qld, kld);
        cudaEventRecord(g_ss.eL[l], 0);

        // ===== side stream: a2 + fused [z;p] Newton chain =====
        cudaStreamWaitEvent(sB, g_ss.eL[l], 0);
        launch_gemm(sB, 128, qld, kld,
                    a2, nullptr, nullptr,
                    NLM, NLM, DH, DH, DH, NLM,
                    (long long)NLM * DH, 0, 1, (long long)NLM * DH, 0, 1,
                    MM, BHN, 0.125f, nullptr, 0, 0, 1);
        softmax256<<<(BHN * NLM) / 8, 256, 0, sB>>>(a2, a2, a2d, (long long)BHN * NLM);
        reset_kernel<<<1, 32, 0, sB>>>();
        a2stats_kernel<<<BHN, 256, 0, sB>>>(a2);
        z0_kernel<<<dim3(8, 8, BHN), dim3(32, 8), 0, sB>>>(a2, zpd);
        // p0 = a2 @ z0 -> zpd p-half ; t1 = 7I - p0 -> t1d p-half
        launch_gemm(sB, 64, a2d, zpd,
                    nullptr, zpd + 16 * MM, t1d + 16 * MM,
                    NLM, NLM, NLM, NLM, NLM, NLM,
                    MM, 0, 1, MM, 0, 1, MM, BHN, 1.f, nullptr, 0, 0, 0,
                    1, 0, 0.f, 7.f);
        bf16* zpCur = zpd;
        bf16* zpNxt = zp2d;
        for (int it = 0; it < 6; it++) {
            // t2 = 15I - p@t1
            launch_gemm(sB, 64, zpCur + 16 * MM, t1d + 16 * MM,
                        nullptr, nullptr, t2d,
                        NLM, NLM, NLM, NLM, NLM, NLM,
                        MM, 0, 1, MM, 0, 1, MM, BHN, 1.f, nullptr, 0, 0, 0,
                        1, 0, 0.f, 15.f);
            // t3 = 13I - p@t2
            launch_gemm(sB, 64, zpCur + 16 * MM, t2d,
                        nullptr, nullptr, t3d,
                        NLM, NLM, NLM, NLM, NLM, NLM,
                        MM, 0, 1, MM, 0, 1, MM, BHN, 1.f, nullptr, 0, 0, 0,
                        1, 0, 0.f, 13.f);
            // [z';p'] = 0.25 [z;p]@t3 -> zpNxt ; t1' = 7I - [..;p']
            launch_gemm(sB, 64, zpCur, t3d,
                        nullptr, zpNxt, t1d,
                        NLM, NLM, NLM, NLM, NLM, NLM,
                        0, MM, 32, 0, MM, 16, MM, 32, 0.25f, nullptr, 0, 0, 0,
                        1, 0, 0.f, 7.f);
            bf16* tp = zpCur; zpCur = zpNxt; zpNxt = tp;
        }
        cudaEventRecord(g_ss.eB[l], sB);

        // ===== main stream: conv + F1 + combine (overlaps side) =====
        conv_kernel<<<dim3(NPAD / 64, BHN), 256>>>(qkvd, convw[l], outh);

        flash_kernel<0><<<dim3(NLM / 128, NSPLIT, BHN), 256, FA_SMEM_BYTES>>>(
            qld, DH, 0, (long long)NLM * DH, BHN,
            qkvd + DM, TD, (long long)NPAD * TD, 64, NH,
            qkvd + 2 * DM, TD, (long long)NPAD * TD, 64, NH,
            NPAD / NSPLIT, po, pm, ps, nullptr, nullptr);
        fa_combine<<<(unsigned)((long long)BHN * NLM * DH / 256), 256>>>(po, pm, ps, a3vd);

        // join pinv chain
        cudaStreamWaitEvent(0, g_ss.eB[l], 0);

        // w = z @ a3v   (z in zpCur z-half)
        launch_gemm(0, 64, zpCur, a3vd,
                    nullptr, wd, nullptr,
                    NLM, DH, NLM, NLM, DH, DH,
                    MM, 0, 1, (long long)NLM * DH, 0, 1,
                    (long long)NLM * DH, BHN, 1.f, nullptr, 0, 0, 0);

        // F2: catd = merge( softmax(0.125 Q k_l^T) @ w + conv )
        flash_kernel<1><<<dim3(NPAD / 128, 1, BHN), 256, FA_SMEM_BYTES>>>(
            qkvd, TD, (long long)NPAD * TD, 64, NH,
            kld, DH, 0, (long long)NLM * DH, BHN,
            wd, DH, 0, (long long)NLM * DH, BHN,
            NLM, nullptr, nullptr, nullptr, outh, catd);

        // output projection, accumulate into residual stream (fp32)
        launch_gemm(0, 128, catd + (long long)PADN * DM, outwd + (long long)l * DM * DM,
                    h + (long long)PADN * DM, nullptr, nullptr,
                    NP1, DM, DM, DM, DM, DM,
                    (long long)NPAD * DM, 0, 1, 0, 0, 1,
                    (long long)NPAD * DM, BATCH, 1.f, outb[l], 0, 1, 0);
    }

    final_kernel<<<BATCH, 256>>>(h, nfg, nfb, fc2w, fc2b, (float*)d_out);
}